// round 9
// baseline (speedup 1.0000x reference)
#include <cuda_runtime.h>
#include <cuda_fp16.h>
#include <math.h>
#include <stdint.h>

#define B_   256
#define S1_  512
#define S2_  64
#define H_   768
#define OPC_ 64
#define OT_  128
#define NEGV (-1e12f)

// ---------------- scratch (device globals) ----------------------------------
__device__ float g_gAB [B_ * 2 * H_];     // [B][1536]: gA | gB
__device__ float g_gCD [B_ * 2 * H_];     // [B][1536]: gC | gD
__device__ float g_node[B_ * H_];
__device__ float g_P1  [B_ * H_];
__device__ float g_eng [B_ * S1_];
__device__ float g_ctx [B_ * H_];
__device__ float g_Q1  [B_ * H_];
__device__ float g_Q2c [OPC_ * H_];
// fp16 activations
__device__ __half g_encH [(size_t)B_ * S1_ * H_];
__device__ __half g_varH [(size_t)B_ * S2_ * H_];
__device__ __half g_opcH [OPC_ * H_];
__device__ __half g_lcH  [B_ * 2 * H_];   // [left | current]
__device__ __half g_nodeH[B_ * H_];
__device__ __half g_leafH[B_ * 2 * H_];
// fp16 transposed weights: Wt[n][k] = W[k][n]
__device__ __half g_WtLLG [2 * H_ * H_];
__device__ __half g_WtRRG [2 * H_ * 2 * H_];
__device__ __half g_WtA1  [H_ * H_];
__device__ __half g_WtA2  [H_ * H_];
__device__ __half g_WtS3  [H_ * H_];
__device__ __half g_WtS12 [H_ * 2 * H_];

// ---------------- helpers ------------------------------------------------------
__device__ __forceinline__ float tanh_fast(float x) {
    float y; asm("tanh.approx.f32 %0, %1;" : "=f"(y) : "f"(x)); return y;
}
__device__ __forceinline__ float ftanh(float x) {
    float ax = fabsf(x);
    float e  = __expf(2.0f * ax);
    float r  = 1.0f - __fdividef(2.0f, e + 1.0f);
    return copysignf(r, x);
}
__device__ __forceinline__ float fsig(float x) {
    return __fdividef(1.0f, 1.0f + __expf(-x));
}
__device__ __forceinline__ uint32_t smem_u32(const void* p) {
    uint32_t a;
    asm("{ .reg .u64 t; cvta.to.shared.u64 t, %1; cvt.u32.u64 %0, t; }" : "=r"(a) : "l"(p));
    return a;
}
__device__ __forceinline__ void cp16(uint32_t saddr, const __half* g, uint32_t sz) {
    asm volatile("cp.async.cg.shared.global [%0], [%1], 16, %2;"
                 :: "r"(saddr), "l"(g), "r"(sz) : "memory");
}
__device__ __forceinline__ void cp_commit() {
    asm volatile("cp.async.commit_group;" ::: "memory");
}
__device__ __forceinline__ void cp_wait2() {
    asm volatile("cp.async.wait_group 2;" ::: "memory");
}
__device__ __forceinline__ void cp_wait0() {
    asm volatile("cp.async.wait_group 0;" ::: "memory");
}
__device__ __forceinline__ void ldm4(uint32_t r[4], uint32_t addr) {
    asm volatile("ldmatrix.sync.aligned.m8n8.x4.shared.b16 {%0,%1,%2,%3}, [%4];"
                 : "=r"(r[0]), "=r"(r[1]), "=r"(r[2]), "=r"(r[3]) : "r"(addr));
}
__device__ __forceinline__ void mma_f16(float c[4], const uint32_t a[4],
                                        uint32_t b0, uint32_t b1) {
    asm volatile(
        "mma.sync.aligned.m16n8k16.row.col.f32.f16.f16.f32 "
        "{%0,%1,%2,%3}, {%4,%5,%6,%7}, {%8,%9}, {%0,%1,%2,%3};"
        : "+f"(c[0]), "+f"(c[1]), "+f"(c[2]), "+f"(c[3])
        : "r"(a[0]), "r"(a[1]), "r"(a[2]), "r"(a[3]), "r"(b0), "r"(b1));
}

// ---------------- pipelined fp16 MMA kernel (cp.async 4-stage, BK=32) ----------
// C-tile 128m x 256n, 512 thr = 16 warps (4 m-bands x 4 n-groups), warp 32x64.
// A row-major [M, lda] fp16; Wt row-major [N][K] fp16.
// MODE 0: split-K over blockIdx.z, ngroups=1, atomicAdd into C[M,ldc] (bias preloaded).
// MODE 1: ngroups=3 n-loop (N=768); out[r] = sum_n v[n]*tanh(aux1[bm>>9, n] + acc);
//         continuous pipeline across n-groups; plain store (no atomics).
// MODE 2: like MODE 1 with out[(r>>6)*128+64+(r&63)].
#define KPAD 40
#define A_STAGE (128 * KPAD * 2)            // 10240 B
#define B_STAGE (256 * KPAD * 2)            // 20480 B
#define SMEM_MMA (4 * (A_STAGE + B_STAGE))  // 122880 B

template <int MODE>
__global__ __launch_bounds__(512, 1) void mma_k(
    const __half* __restrict__ A, const __half* __restrict__ Wt,
    float* __restrict__ outv,
    const float* __restrict__ aux1, const float* __restrict__ aux2,
    int M, int K, int lda, int niter, int ngroups, int ldc)
{
    extern __shared__ __align__(16) __half smh[];
    const uint32_t sA = smem_u32(smh);
    const uint32_t sB = sA + 4 * A_STAGE;

    const int tid  = threadIdx.x;
    const int lane = tid & 31;
    const int wid  = tid >> 5;
    const int wm   = wid & 3;
    const int wn   = wid >> 2;
    const int bm   = blockIdx.y * 128;
    const int bn0  = (MODE == 0) ? blockIdx.x * 256 : 0;
    const int kst  = blockIdx.z * niter * 32;

    float acc[2][8][4];
#pragma unroll
    for (int i = 0; i < 2; i++)
#pragma unroll
        for (int j = 0; j < 8; j++)
#pragma unroll
            for (int q = 0; q < 4; q++) acc[i][j][q] = 0.f;

    float part_acc[2][2] = {{0.f, 0.f}, {0.f, 0.f}};

    // loaders: A 128 rows x 64B (1 cp16/thread); B 256 rows x 64B (2 cp16/thread)
    const int l_row = tid >> 2;
    const int lq    = tid & 3;
    const uint32_t a_sz = ((bm + l_row) < M) ? 16u : 0u;
    const __half* Ap  = A  + (size_t)(bm + l_row) * lda + kst + lq * 8;
    const __half* Bp0 = Wt + (size_t)(bn0 + l_row) * K + kst + lq * 8;
    const __half* Bp1 = Wt + (size_t)(bn0 + 128 + l_row) * K + kst + lq * 8;
    const uint32_t dA  = sA + (uint32_t)(l_row * KPAD + lq * 8) * 2u;
    const uint32_t dB0 = sB + (uint32_t)(l_row * KPAD + lq * 8) * 2u;
    const uint32_t dB1 = sB + (uint32_t)((128 + l_row) * KPAD + lq * 8) * 2u;

    const int total_iters = niter * ngroups;

    auto issue = [&](int stage, int c) {
        int g  = c / niter;
        int kc = c - g * niter;
        size_t bgo = (size_t)g * 256 * K;
        cp16(dA  + (uint32_t)stage * A_STAGE, Ap  + (size_t)kc * 32, a_sz);
        cp16(dB0 + (uint32_t)stage * B_STAGE, Bp0 + bgo + (size_t)kc * 32, 16u);
        cp16(dB1 + (uint32_t)stage * B_STAGE, Bp1 + bgo + (size_t)kc * 32, 16u);
    };

#pragma unroll
    for (int s = 0; s < 3; s++) {
        if (s < total_iters) issue(s, s);
        cp_commit();
    }

    const int lk = lane & 3;
    const int lg = lane >> 2;
    const int l15 = lane & 15;
    const int lhi = lane >> 4;
    const int l8k = (lane >> 3) & 1;
    const int l7  = lane & 7;

    const uint32_t aoff = (uint32_t)((wm * 32 + l15) * KPAD) * 2u + (uint32_t)lhi * 16u;
    const uint32_t boff = (uint32_t)((wn * 64 + l7 + lhi * 8) * KPAD) * 2u + (uint32_t)l8k * 16u;

    for (int c = 0; c < total_iters; c++) {
        cp_wait2();
        __syncthreads();
        const uint32_t soa = (uint32_t)(c & 3) * A_STAGE;
        const uint32_t sob = (uint32_t)(c & 3) * B_STAGE;

#pragma unroll
        for (int ks = 0; ks < 2; ks++) {
            const uint32_t kso = (uint32_t)ks * 32u;
            uint32_t a0[4], a1[4];
            ldm4(a0, sA + soa + aoff + kso);
            ldm4(a1, sA + soa + aoff + kso + 16u * KPAD * 2u);
#pragma unroll
            for (int p = 0; p < 4; p++) {
                uint32_t bb[4];
                ldm4(bb, sB + sob + boff + kso + (uint32_t)(p * 16 * KPAD) * 2u);
                mma_f16(acc[0][2 * p],     a0, bb[0], bb[1]);
                mma_f16(acc[0][2 * p + 1], a0, bb[2], bb[3]);
                mma_f16(acc[1][2 * p],     a1, bb[0], bb[1]);
                mma_f16(acc[1][2 * p + 1], a1, bb[2], bb[3]);
            }
        }

        if (c + 3 < total_iters) issue((c + 3) & 3, c + 3);
        cp_commit();

        // ---- per-group partial epilogue (MODE 1/2): fold acc into part_acc ----
        if (MODE != 0) {
            int cn = c + 1;
            if (cn % niter == 0) {
                const int g = c / niter;
                const int bn_g = g * 256;
#pragma unroll
                for (int ti = 0; ti < 2; ti++)
#pragma unroll
                    for (int half = 0; half < 2; half++) {
                        const int r = bm + wm * 32 + ti * 16 + lg + half * 8;
                        const int brow = (MODE == 1) ? (bm >> 9) : (r >> 6);
                        const float* p1 = aux1 + (size_t)brow * H_;
                        float part = 0.f;
#pragma unroll
                        for (int nj = 0; nj < 8; nj++) {
                            int n = bn_g + wn * 64 + nj * 8 + 2 * lk;
                            part += __ldg(&aux2[n])     * tanh_fast(acc[ti][nj][half * 2]     + __ldg(&p1[n]));
                            part += __ldg(&aux2[n + 1]) * tanh_fast(acc[ti][nj][half * 2 + 1] + __ldg(&p1[n + 1]));
                        }
                        part_acc[ti][half] += part;
                    }
#pragma unroll
                for (int i = 0; i < 2; i++)
#pragma unroll
                    for (int j = 0; j < 8; j++)
#pragma unroll
                        for (int q = 0; q < 4; q++) acc[i][j][q] = 0.f;
            }
        }
    }

    // ---------------- final epilogues ----------------
    if (MODE == 0) {
#pragma unroll
        for (int ti = 0; ti < 2; ti++)
#pragma unroll
            for (int nj = 0; nj < 8; nj++) {
                int r0 = bm + wm * 32 + ti * 16 + lg;
                int cc = bn0 + wn * 64 + nj * 8 + 2 * lk;
                if (r0 < M) {
                    atomicAdd(&outv[(size_t)r0 * ldc + cc],     acc[ti][nj][0]);
                    atomicAdd(&outv[(size_t)r0 * ldc + cc + 1], acc[ti][nj][1]);
                }
                if (r0 + 8 < M) {
                    atomicAdd(&outv[(size_t)(r0 + 8) * ldc + cc],     acc[ti][nj][2]);
                    atomicAdd(&outv[(size_t)(r0 + 8) * ldc + cc + 1], acc[ti][nj][3]);
                }
            }
        return;
    }

    // cross-warp (wn) reduce via SMEM, then plain store
    cp_wait0();
    __syncthreads();
    float* red = (float*)smh;      // 128 rows x 4 wn
#pragma unroll
    for (int ti = 0; ti < 2; ti++)
#pragma unroll
        for (int half = 0; half < 2; half++) {
            float p = part_acc[ti][half];
            p += __shfl_xor_sync(0xFFFFFFFFu, p, 1);
            p += __shfl_xor_sync(0xFFFFFFFFu, p, 2);
            if (lk == 0)
                red[(wm * 32 + ti * 16 + lg + half * 8) * 4 + wn] = p;
        }
    __syncthreads();
    if (tid < 128) {
        float s = red[tid * 4] + red[tid * 4 + 1] + red[tid * 4 + 2] + red[tid * 4 + 3];
        if (MODE == 1) {
            outv[bm + tid] = s;
        } else {
            int r = bm + tid;
            outv[(size_t)(r >> 6) * OT_ + OPC_ + (r & 63)] = s;
        }
    }
}

// ---------------- fused prep / epilogue helpers --------------------------------
__global__ void fill_mega_k(
    float* gAB, const float* bA, const float* bB,
    float* gCD, const float* bC, const float* bD,
    float* P1, const float* bE, float* Q1, const float* bF,
    float* z1, int n1)
{
    const int BH = B_ * H_;
    const int BH2 = B_ * 2 * H_;
    int i = blockIdx.x * blockDim.x + threadIdx.x;
    if (i < BH2) { int h = i % (2 * H_); gAB[i] = (h < H_) ? bA[h] : bB[h - H_]; return; }
    i -= BH2;
    if (i < BH2) { int h = i % (2 * H_); gCD[i] = (h < H_) ? bC[h] : bD[h - H_]; return; }
    i -= BH2;
    if (i < BH) { P1[i] = bE[i % H_]; return; }
    i -= BH;
    if (i < BH) { Q1[i] = bF[i % H_]; return; }
    i -= BH;
    if (i < n1) z1[i] = 0.f;
}

__global__ void cvt_h_k(const float* __restrict__ src, __half* __restrict__ dst, int n4)
{
    int i = blockIdx.x * blockDim.x + threadIdx.x;
    if (i >= n4) return;
    float4 v = ((const float4*)src)[i];
    ((__half2*)dst)[2 * i]     = __floats2half2_rn(v.x, v.y);
    ((__half2*)dst)[2 * i + 1] = __floats2half2_rn(v.z, v.w);
}

// left/current -> lcH
__global__ void prep_cur_k(const float* __restrict__ current, const float* __restrict__ left,
                           __half* __restrict__ lcH)
{
    int i = blockIdx.x * blockDim.x + threadIdx.x;
    if (i >= B_ * H_) return;
    int b = i / H_, h = i % H_;
    lcH[(size_t)b * 2 * H_ + h]      = __float2half_rn(left[i]);
    lcH[(size_t)b * 2 * H_ + H_ + h] = __float2half_rn(current[i]);
}

// opc/var -> out_emb (fp32) + opcH/varH (fp16), single pass
__global__ void prep_emb_k(const float* __restrict__ opc, const float* __restrict__ var,
                           float* __restrict__ out_emb,
                           __half* __restrict__ opcH, __half* __restrict__ varH)
{
    size_t i = (size_t)blockIdx.x * blockDim.x + threadIdx.x;   // float4 units
    const size_t total = (size_t)B_ * OT_ * (H_ / 4);
    if (i >= total) return;
    int h4 = (int)(i % (H_ / 4));
    size_t bo = i / (H_ / 4);
    int o = (int)(bo & 127);
    int b = (int)(bo >> 7);
    float4 v;
    if (o < OPC_) {
        size_t si = (size_t)o * (H_ / 4) + h4;
        v = ((const float4*)opc)[si];
        if (b == 0) {
            ((__half2*)opcH)[2 * si]     = __floats2half2_rn(v.x, v.y);
            ((__half2*)opcH)[2 * si + 1] = __floats2half2_rn(v.z, v.w);
        }
    } else {
        size_t si = ((size_t)b * S2_ + (o - OPC_)) * (H_ / 4) + h4;
        v = ((const float4*)var)[si];
        ((__half2*)varH)[2 * si]     = __floats2half2_rn(v.x, v.y);
        ((__half2*)varH)[2 * si + 1] = __floats2half2_rn(v.z, v.w);
    }
    ((float4*)out_emb)[i] = v;
}

// batched 768x768 transposes -> fp16
__global__ void transpose5h_k(const float* s0, __half* d0, const float* s1, __half* d1,
                              const float* s2, __half* d2, const float* s3, __half* d3,
                              const float* s4, __half* d4)
{
    __shared__ float t[32][33];
    const float* src; __half* dst;
    switch (blockIdx.z) {
        case 0: src = s0; dst = d0; break;
        case 1: src = s1; dst = d1; break;
        case 2: src = s2; dst = d2; break;
        case 3: src = s3; dst = d3; break;
        default: src = s4; dst = d4; break;
    }
    int bx = blockIdx.x * 32, by = blockIdx.y * 32;
    int x = threadIdx.x, y = threadIdx.y;
#pragma unroll
    for (int i = 0; i < 32; i += 8)
        t[y + i][x] = src[(size_t)(by + y + i) * H_ + bx + x];
    __syncthreads();
#pragma unroll
    for (int i = 0; i < 32; i += 8)
        dst[(size_t)(bx + y + i) * H_ + by + x] = __float2half_rn(t[x][y + i]);
}

// batched [1536][768] transposes -> fp16 [768 n][1536 k]
__global__ void transpose3h_k(const float* s0, __half* d0, const float* s1, __half* d1,
                              const float* s2, __half* d2)
{
    __shared__ float t[32][33];
    const float* src; __half* dst;
    switch (blockIdx.z) {
        case 0: src = s0; dst = d0; break;
        case 1: src = s1; dst = d1; break;
        default: src = s2; dst = d2; break;
    }
    int bx = blockIdx.x * 32, by = blockIdx.y * 32;   // grid (24, 48)
    int x = threadIdx.x, y = threadIdx.y;
#pragma unroll
    for (int i = 0; i < 32; i += 8)
        t[y + i][x] = src[(size_t)(by + y + i) * H_ + bx + x];
    __syncthreads();
#pragma unroll
    for (int i = 0; i < 32; i += 8)
        dst[(size_t)(bx + y + i) * (2 * H_) + by + x] = __float2half_rn(t[x][y + i]);
}

// gates -> node (fp32 + fp16 + output copy + lower half of leafH)
__global__ void combine_node_k(const int* __restrict__ has_left,
                               float* __restrict__ out_node)
{
    int i = blockIdx.x * blockDim.x + threadIdx.x;
    if (i >= B_ * H_) return;
    int b = i / H_, h = i % H_;
    size_t base = (size_t)b * 2 * H_ + h;
    float v = has_left[b] ? ftanh(g_gCD[base]) * fsig(g_gCD[base + H_])
                          : ftanh(g_gAB[base]) * fsig(g_gAB[base + H_]);
    g_node[i] = v;
    __half hv = __float2half_rn(v);
    g_nodeH[i] = hv;
    g_leafH[base] = hv;
    out_node[i] = v;
}

// fused softmax (over S1) + context (attn @ encH); writes ctx copies and
// the upper half of leafH. block = 768 threads, grid = B_.
__global__ __launch_bounds__(768) void softmax_context_k(
    const int* __restrict__ smask, const __half* __restrict__ encH,
    float* __restrict__ out_ctx)
{
    __shared__ float attn[S1_];
    __shared__ float wred[16];
    const int b = blockIdx.x, t = threadIdx.x;
    const int lane = t & 31, w = t >> 5;

    float x = 0.f;
    if (t < S1_)
        x = smask[(size_t)b * S1_ + t] ? NEGV : g_eng[(size_t)b * S1_ + t];

    if (t < S1_) {
        float m = x;
#pragma unroll
        for (int o = 16; o; o >>= 1) m = fmaxf(m, __shfl_xor_sync(0xFFFFFFFFu, m, o));
        if (lane == 0) wred[w] = m;
    }
    __syncthreads();
    if (t == 0) {
        float m = wred[0];
#pragma unroll
        for (int k = 1; k < 16; k++) m = fmaxf(m, wred[k]);
        wred[0] = m;
    }
    __syncthreads();
    const float mx = wred[0];
    __syncthreads();

    float e = 0.f;
    if (t < S1_) {
        e = __expf(x - mx);
        float s = e;
#pragma unroll
        for (int o = 16; o; o >>= 1) s += __shfl_xor_sync(0xFFFFFFFFu, s, o);
        if (lane == 0) wred[w] = s;
    }
    __syncthreads();
    if (t == 0) {
        float s = wred[0];
#pragma unroll
        for (int k = 1; k < 16; k++) s += wred[k];
        wred[0] = s;
    }
    __syncthreads();
    if (t < S1_) attn[t] = e * __fdividef(1.f, wred[0]);
    __syncthreads();

    const __half* ep = encH + (size_t)b * S1_ * H_ + t;
    float acc = 0.f;
#pragma unroll 8
    for (int s = 0; s < S1_; s++)
        acc = fmaf(attn[s], __half2float(ep[(size_t)s * H_]), acc);
    size_t oi = (size_t)b * H_ + t;
    g_ctx[oi] = acc;
    out_ctx[oi] = acc;
    g_leafH[(size_t)b * 2 * H_ + H_ + t] = __float2half_rn(acc);
}

__global__ void finalize_score_k(const float* __restrict__ vsc,
                                 const int* __restrict__ cmask,
                                 float* __restrict__ score)
{
    int idx = (blockIdx.x * blockDim.x + threadIdx.x) >> 5;
    if (idx >= B_ * OT_) return;
    int lane = threadIdx.x & 31;
    int b = idx >> 7, o = idx & 127;
    if (cmask[idx]) {
        if (lane == 0) score[idx] = NEGV;
        return;
    }
    if (o >= OPC_) return;
    const float* q1 = g_Q1 + (size_t)b * H_;
    const float* q2 = g_Q2c + (size_t)o * H_;
    float acc = 0.f;
    for (int h = lane; h < H_; h += 32)
        acc += vsc[h] * ftanh(q1[h] + q2[h]);
#pragma unroll
    for (int off = 16; off; off >>= 1) acc += __shfl_xor_sync(0xFFFFFFFFu, acc, off);
    if (lane == 0) score[idx] = acc;
}

// ---------------- launch -------------------------------------------------------
extern "C" void kernel_launch(void* const* d_in, const int* in_sizes, int n_in,
                              void* d_out, int out_size)
{
    (void)in_sizes; (void)n_in; (void)out_size;
    const float* current = (const float*)d_in[0];
    const float* left    = (const float*)d_in[1];
    const float* enc     = (const float*)d_in[2];
    const float* var     = (const float*)d_in[3];
    const float* opc     = (const float*)d_in[4];
    const float* W_l     = (const float*)d_in[5];
    const float* b_l     = (const float*)d_in[6];
    const float* W_lg    = (const float*)d_in[7];
    const float* b_lg    = (const float*)d_in[8];
    const float* W_r     = (const float*)d_in[9];
    const float* b_r     = (const float*)d_in[10];
    const float* W_rg    = (const float*)d_in[11];
    const float* b_rg    = (const float*)d_in[12];
    const float* W_attn  = (const float*)d_in[13];
    const float* b_attn  = (const float*)d_in[14];
    const float* v_attn  = (const float*)d_in[15];
    const float* W_score = (const float*)d_in[16];
    const float* b_score = (const float*)d_in[17];
    const float* v_score = (const float*)d_in[18];
    const int*   has_left = (const int*)d_in[19];
    const int*   smask    = (const int*)d_in[20];
    const int*   cmask    = (const int*)d_in[21];

    float *gAB, *gCD, *node, *P1, *eng, *ctx, *Q1, *Q2c;
    __half *encH, *varH, *opcH, *lcH, *nodeH, *leafH;
    __half *WtLLG, *WtRRG, *WtA1, *WtA2, *WtS3, *WtS12;
    cudaGetSymbolAddress((void**)&gAB,  g_gAB);
    cudaGetSymbolAddress((void**)&gCD,  g_gCD);
    cudaGetSymbolAddress((void**)&node, g_node);
    cudaGetSymbolAddress((void**)&P1,   g_P1);
    cudaGetSymbolAddress((void**)&eng,  g_eng);
    cudaGetSymbolAddress((void**)&ctx,  g_ctx);
    cudaGetSymbolAddress((void**)&Q1,   g_Q1);
    cudaGetSymbolAddress((void**)&Q2c,  g_Q2c);
    cudaGetSymbolAddress((void**)&encH, g_encH);
    cudaGetSymbolAddress((void**)&varH, g_varH);
    cudaGetSymbolAddress((void**)&opcH, g_opcH);
    cudaGetSymbolAddress((void**)&lcH,  g_lcH);
    cudaGetSymbolAddress((void**)&nodeH, g_nodeH);
    cudaGetSymbolAddress((void**)&leafH, g_leafH);
    cudaGetSymbolAddress((void**)&WtLLG, g_WtLLG);
    cudaGetSymbolAddress((void**)&WtRRG, g_WtRRG);
    cudaGetSymbolAddress((void**)&WtA1, g_WtA1);
    cudaGetSymbolAddress((void**)&WtA2, g_WtA2);
    cudaGetSymbolAddress((void**)&WtS3, g_WtS3);
    cudaGetSymbolAddress((void**)&WtS12, g_WtS12);

    float* out       = (float*)d_out;
    float* out_score = out;
    float* out_node  = out_score + B_ * OT_;
    float* out_ctx   = out_node + B_ * H_;
    float* out_emb   = out_ctx + B_ * H_;

    const int BH = B_ * H_;
    const int TPB = 256;

    cudaFuncSetAttribute(mma_k<0>, cudaFuncAttributeMaxDynamicSharedMemorySize, SMEM_MMA);
    cudaFuncSetAttribute(mma_k<1>, cudaFuncAttributeMaxDynamicSharedMemorySize, SMEM_MMA);
    cudaFuncSetAttribute(mma_k<2>, cudaFuncAttributeMaxDynamicSharedMemorySize, SMEM_MMA);

    // --- fills + conversions + transposes (independent) ---
    {
        int total = 2 * (B_ * 2 * H_) + 2 * BH + OPC_ * H_;
        fill_mega_k<<<(total + TPB - 1) / TPB, TPB>>>(
            gAB, b_l, b_lg, gCD, b_r, b_rg, P1, b_attn, Q1, b_score,
            Q2c, OPC_ * H_);
    }
    prep_cur_k<<<(BH + TPB - 1) / TPB, TPB>>>(current, left, lcH);
    {
        size_t total4 = (size_t)B_ * OT_ * (H_ / 4);
        prep_emb_k<<<(unsigned)((total4 + TPB - 1) / TPB), TPB>>>(opc, var, out_emb, opcH, varH);
    }
    {
        int n4 = B_ * S1_ * (H_ / 4);
        cvt_h_k<<<(n4 + TPB - 1) / TPB, TPB>>>(enc, encH, n4);
    }
    transpose5h_k<<<dim3(24, 24, 5), dim3(32, 8)>>>(
        W_l, WtLLG, W_lg, WtLLG + (size_t)H_ * H_,
        W_attn, WtA1, W_attn + (size_t)H_ * H_, WtA2,
        W_score + (size_t)2 * H_ * H_, WtS3);
    transpose3h_k<<<dim3(24, 48, 3), dim3(32, 8)>>>(
        W_r, WtRRG, W_rg, WtRRG + (size_t)H_ * 2 * H_, W_score, WtS12);

    // --- node: two merged gate GEMMs (A = current half / full lc of lcH) ---
    mma_k<0><<<dim3(6, 2, 6),  512, SMEM_MMA>>>(lcH + H_, WtLLG, gAB, nullptr, nullptr,
                                                B_, H_, 2 * H_, 4, 1, 2 * H_);
    mma_k<0><<<dim3(6, 2, 12), 512, SMEM_MMA>>>(lcH, WtRRG, gCD, nullptr, nullptr,
                                                B_, 2 * H_, 2 * H_, 4, 1, 2 * H_);
    combine_node_k<<<(BH + TPB - 1) / TPB, TPB>>>(has_left, out_node);

    // --- attention ---
    mma_k<0><<<dim3(3, 2, 6), 512, SMEM_MMA>>>(nodeH, WtA1, P1, nullptr, nullptr,
                                               B_, H_, H_, 4, 1, H_);
    mma_k<1><<<dim3(1, (B_ * S1_) / 128, 1), 512, SMEM_MMA>>>(encH, WtA2, eng, P1, v_attn,
                                                              B_ * S1_, H_, H_, 24, 3, 0);
    softmax_context_k<<<B_, 768>>>(smask, encH, out_ctx);

    // --- leaf score ---
    mma_k<0><<<dim3(3, 2, 12), 512, SMEM_MMA>>>(leafH, WtS12, Q1, nullptr, nullptr,
                                                B_, 2 * H_, 2 * H_, 4, 1, H_);
    mma_k<0><<<dim3(3, 1, 6),  512, SMEM_MMA>>>(opcH, WtS3, Q2c, nullptr, nullptr,
                                                OPC_, H_, H_, 4, 1, H_);
    mma_k<2><<<dim3(1, (B_ * S2_) / 128, 1), 512, SMEM_MMA>>>(varH, WtS3, out_score, Q1, v_score,
                                                              B_ * S2_, H_, H_, 24, 3, 0);
    finalize_score_k<<<(B_ * OT_ * 32 + TPB - 1) / TPB, TPB>>>(v_score, cmask, out_score);
}

// round 10
// speedup vs baseline: 1.1342x; 1.1342x over previous
#include <cuda_runtime.h>
#include <cuda_fp16.h>
#include <math.h>
#include <stdint.h>

#define B_   256
#define S1_  512
#define S2_  64
#define H_   768
#define OPC_ 64
#define OT_  128
#define NEGV (-1e12f)

// ---------------- scratch (device globals) ----------------------------------
__device__ float g_gAB [B_ * 2 * H_];     // [B][1536]: gA | gB
__device__ float g_gCD [B_ * 2 * H_];     // [B][1536]: gC | gD
__device__ float g_node[B_ * H_];
__device__ float g_P1  [B_ * H_];
__device__ float g_eng [B_ * S1_];
__device__ float g_ctx [B_ * H_];
__device__ float g_Q1  [B_ * H_];
__device__ float g_Q2c [OPC_ * H_];
// fp16 activations
__device__ __half g_varH [(size_t)B_ * S2_ * H_];
__device__ __half g_opcH [OPC_ * H_];
__device__ __half g_lcH  [B_ * 2 * H_];   // [left | current]
__device__ __half g_nodeH[B_ * H_];
__device__ __half g_leafH[B_ * 2 * H_];
// fp16 transposed weights: Wt[n][k] = W[k][n]
__device__ __half g_WtLLG [2 * H_ * H_];
__device__ __half g_WtRRG [2 * H_ * 2 * H_];
__device__ __half g_WtA1  [H_ * H_];
__device__ __half g_WtA2  [H_ * H_];
__device__ __half g_WtS3  [H_ * H_];
__device__ __half g_WtS12 [H_ * 2 * H_];

// ---------------- helpers ------------------------------------------------------
__device__ __forceinline__ float tanh_fast(float x) {
    float y; asm("tanh.approx.f32 %0, %1;" : "=f"(y) : "f"(x)); return y;
}
__device__ __forceinline__ float ftanh(float x) {
    float ax = fabsf(x);
    float e  = __expf(2.0f * ax);
    float r  = 1.0f - __fdividef(2.0f, e + 1.0f);
    return copysignf(r, x);
}
__device__ __forceinline__ float fsig(float x) {
    return __fdividef(1.0f, 1.0f + __expf(-x));
}
__device__ __forceinline__ uint32_t smem_u32(const void* p) {
    uint32_t a;
    asm("{ .reg .u64 t; cvta.to.shared.u64 t, %1; cvt.u32.u64 %0, t; }" : "=r"(a) : "l"(p));
    return a;
}
__device__ __forceinline__ void cp16(uint32_t saddr, const void* g, uint32_t sz) {
    asm volatile("cp.async.cg.shared.global [%0], [%1], 16, %2;"
                 :: "r"(saddr), "l"(g), "r"(sz) : "memory");
}
__device__ __forceinline__ void cp_commit() {
    asm volatile("cp.async.commit_group;" ::: "memory");
}
__device__ __forceinline__ void cp_wait2() {
    asm volatile("cp.async.wait_group 2;" ::: "memory");
}
__device__ __forceinline__ void ldm4(uint32_t r[4], uint32_t addr) {
    asm volatile("ldmatrix.sync.aligned.m8n8.x4.shared.b16 {%0,%1,%2,%3}, [%4];"
                 : "=r"(r[0]), "=r"(r[1]), "=r"(r[2]), "=r"(r[3]) : "r"(addr));
}
__device__ __forceinline__ uint32_t pack_h2(float2 v) {
    __half2 h = __floats2half2_rn(v.x, v.y);
    return *(uint32_t*)&h;
}
__device__ __forceinline__ void mma_f16(float c[4], const uint32_t a[4],
                                        uint32_t b0, uint32_t b1) {
    asm volatile(
        "mma.sync.aligned.m16n8k16.row.col.f32.f16.f16.f32 "
        "{%0,%1,%2,%3}, {%4,%5,%6,%7}, {%8,%9}, {%0,%1,%2,%3};"
        : "+f"(c[0]), "+f"(c[1]), "+f"(c[2]), "+f"(c[3])
        : "r"(a[0]), "r"(a[1]), "r"(a[2]), "r"(a[3]), "r"(b0), "r"(b1));
}

// ---------------- pipelined fp16 MMA kernel (cp.async 4-stage, BK=32) ----------
// C-tile 128m x 256n, 512 thr = 16 warps (4 m-bands x 4 n-groups), warp 32x64.
// AF=0: A fp16 [M,lda]; AF=1: A fp32 [M,lda], converted to fp16 in-register
// (identical __float2half_rn rounding as a pre-pass). Wt row-major [N][K] fp16.
// MODE 0: split-K over blockIdx.z, atomicAdd into C[M,ldc] (bias preloaded).
// MODE 1: energy out[r] += sum_n v[n]*tanh(aux1[bm>>9, n] + acc)   (atomicAdd)
// MODE 2: score  out[(r>>6)*128+64+(r&63)] += ... (atomicAdd)
#define KPAD 40            // fp16 A/B row pad (halfs)
#define KPADF 40           // fp32 A row pad (floats): stride 40 words = 8 mod 32
#define B_STAGE (256 * KPAD * 2)            // 20480 B

template <int MODE, int AF>
__global__ __launch_bounds__(512, 1) void mma_k(
    const void* __restrict__ Araw, const __half* __restrict__ Wt,
    float* __restrict__ outv,
    const float* __restrict__ aux1, const float* __restrict__ aux2,
    int M, int K, int lda, int niter, int ldc)
{
    constexpr int ASZ = AF ? (128 * KPADF * 4) : (128 * KPAD * 2);
    extern __shared__ __align__(16) char smh[];
    const uint32_t sA = smem_u32(smh);
    const uint32_t sB = sA + 4 * ASZ;

    const int tid  = threadIdx.x;
    const int lane = tid & 31;
    const int wid  = tid >> 5;
    const int wm   = wid & 3;
    const int wn   = wid >> 2;
    const int bm   = blockIdx.y * 128;
    const int bn   = blockIdx.x * 256;
    const int kst  = blockIdx.z * niter * 32;

    float acc[2][8][4];
#pragma unroll
    for (int i = 0; i < 2; i++)
#pragma unroll
        for (int j = 0; j < 8; j++)
#pragma unroll
            for (int q = 0; q < 4; q++) acc[i][j][q] = 0.f;

    // loaders: 4 threads per row; A row = 32 elements; B row = 32 halfs
    const int l_row = tid >> 2;
    const int lq    = tid & 3;
    const uint32_t a_sz = ((bm + l_row) < M) ? 16u : 0u;
    const __half* Bp0 = Wt + (size_t)(bn + l_row) * K + kst + lq * 8;
    const __half* Bp1 = Wt + (size_t)(bn + 128 + l_row) * K + kst + lq * 8;
    const uint32_t dB0 = sB + (uint32_t)(l_row * KPAD + lq * 8) * 2u;
    const uint32_t dB1 = sB + (uint32_t)((128 + l_row) * KPAD + lq * 8) * 2u;

    const __half* ApH = AF ? nullptr
        : (const __half*)Araw + (size_t)(bm + l_row) * lda + kst + lq * 8;
    const float*  ApF = AF
        ? (const float*)Araw + (size_t)(bm + l_row) * lda + kst + lq * 8
        : nullptr;
    const uint32_t dA = AF
        ? sA + (uint32_t)(l_row * KPADF + lq * 8) * 4u
        : sA + (uint32_t)(l_row * KPAD  + lq * 8) * 2u;

    auto issue = [&](int stage, int kt) {
        if (AF) {
            const float* a = ApF + (size_t)kt * 32;
            cp16(dA + (uint32_t)stage * ASZ,      a,     a_sz);
            cp16(dA + (uint32_t)stage * ASZ + 16, a + 4, a_sz);
        } else {
            cp16(dA + (uint32_t)stage * ASZ, ApH + (size_t)kt * 32, a_sz);
        }
        cp16(dB0 + (uint32_t)stage * B_STAGE, Bp0 + (size_t)kt * 32, 16u);
        cp16(dB1 + (uint32_t)stage * B_STAGE, Bp1 + (size_t)kt * 32, 16u);
    };

#pragma unroll
    for (int s = 0; s < 3; s++) {
        if (s < niter) issue(s, s);
        cp_commit();
    }

    const int lk = lane & 3;
    const int lg = lane >> 2;
    const int l15 = lane & 15;
    const int lhi = lane >> 4;
    const int l8k = (lane >> 3) & 1;
    const int l7  = lane & 7;

    const uint32_t aoff = (uint32_t)((wm * 32 + l15) * KPAD) * 2u + (uint32_t)lhi * 16u;
    const uint32_t boff = (uint32_t)((wn * 64 + l7 + lhi * 8) * KPAD) * 2u + (uint32_t)l8k * 16u;

    for (int c = 0; c < niter; c++) {
        cp_wait2();
        __syncthreads();
        const uint32_t soa = (uint32_t)(c & 3) * ASZ;
        const uint32_t sob = (uint32_t)(c & 3) * B_STAGE;
        const float* Afp = AF ? (const float*)(smh + (size_t)(c & 3) * ASZ) : nullptr;

#pragma unroll
        for (int ks = 0; ks < 2; ks++) {
            const uint32_t kso = (uint32_t)ks * 32u;
            uint32_t a0[4], a1[4];
            if (AF) {
                // manual A-frag assembly from fp32 SMEM (same layout as ldmatrix.x4)
#pragma unroll
                for (int ti = 0; ti < 2; ti++) {
                    const float* base = Afp + (wm * 32 + ti * 16 + lg) * KPADF
                                        + ks * 16 + 2 * lk;
                    uint32_t* aa = ti ? a1 : a0;
                    aa[0] = pack_h2(*(const float2*)(base));
                    aa[1] = pack_h2(*(const float2*)(base + 8 * KPADF));
                    aa[2] = pack_h2(*(const float2*)(base + 8));
                    aa[3] = pack_h2(*(const float2*)(base + 8 * KPADF + 8));
                }
            } else {
                ldm4(a0, sA + soa + aoff + kso);
                ldm4(a1, sA + soa + aoff + kso + 16u * KPAD * 2u);
            }
#pragma unroll
            for (int p = 0; p < 4; p++) {
                uint32_t bb[4];
                ldm4(bb, sB + sob + boff + kso + (uint32_t)(p * 16 * KPAD) * 2u);
                mma_f16(acc[0][2 * p],     a0, bb[0], bb[1]);
                mma_f16(acc[0][2 * p + 1], a0, bb[2], bb[3]);
                mma_f16(acc[1][2 * p],     a1, bb[0], bb[1]);
                mma_f16(acc[1][2 * p + 1], a1, bb[2], bb[3]);
            }
        }

        if (c + 3 < niter) issue((c + 3) & 3, c + 3);
        cp_commit();
    }

    // ---------------- epilogues ----------------
    if (MODE == 0) {
#pragma unroll
        for (int ti = 0; ti < 2; ti++)
#pragma unroll
            for (int nj = 0; nj < 8; nj++) {
                int r0 = bm + wm * 32 + ti * 16 + lg;
                int cc = bn + wn * 64 + nj * 8 + 2 * lk;
                if (r0 < M) {
                    atomicAdd(&outv[(size_t)r0 * ldc + cc],     acc[ti][nj][0]);
                    atomicAdd(&outv[(size_t)r0 * ldc + cc + 1], acc[ti][nj][1]);
                }
                if (r0 + 8 < M) {
                    atomicAdd(&outv[(size_t)(r0 + 8) * ldc + cc],     acc[ti][nj][2]);
                    atomicAdd(&outv[(size_t)(r0 + 8) * ldc + cc + 1], acc[ti][nj][3]);
                }
            }
        return;
    }

    float vv[16];
#pragma unroll
    for (int nj = 0; nj < 8; nj++)
#pragma unroll
        for (int u = 0; u < 2; u++)
            vv[nj * 2 + u] = __ldg(&aux2[bn + wn * 64 + nj * 8 + 2 * lk + u]);

    if (MODE == 1) {
        const int b = bm >> 9;
        float p1v[16];
#pragma unroll
        for (int nj = 0; nj < 8; nj++)
#pragma unroll
            for (int u = 0; u < 2; u++)
                p1v[nj * 2 + u] = __ldg(&aux1[(size_t)b * H_ + bn + wn * 64 + nj * 8 + 2 * lk + u]);
#pragma unroll
        for (int ti = 0; ti < 2; ti++)
#pragma unroll
            for (int half = 0; half < 2; half++) {
                int r = bm + wm * 32 + ti * 16 + lg + half * 8;
                float part = 0.f;
#pragma unroll
                for (int nj = 0; nj < 8; nj++) {
                    part += vv[nj * 2]     * tanh_fast(acc[ti][nj][half * 2]     + p1v[nj * 2]);
                    part += vv[nj * 2 + 1] * tanh_fast(acc[ti][nj][half * 2 + 1] + p1v[nj * 2 + 1]);
                }
                part += __shfl_xor_sync(0xFFFFFFFFu, part, 1);
                part += __shfl_xor_sync(0xFFFFFFFFu, part, 2);
                if (lk == 0) atomicAdd(&outv[r], part);
            }
    } else {
#pragma unroll
        for (int ti = 0; ti < 2; ti++)
#pragma unroll
            for (int half = 0; half < 2; half++) {
                int r = bm + wm * 32 + ti * 16 + lg + half * 8;
                int b = r >> 6;
                const float* q1 = aux1 + (size_t)b * H_;
                float part = 0.f;
#pragma unroll
                for (int nj = 0; nj < 8; nj++) {
                    int n = bn + wn * 64 + nj * 8 + 2 * lk;
                    part += vv[nj * 2]     * tanh_fast(acc[ti][nj][half * 2]     + __ldg(&q1[n]));
                    part += vv[nj * 2 + 1] * tanh_fast(acc[ti][nj][half * 2 + 1] + __ldg(&q1[n + 1]));
                }
                part += __shfl_xor_sync(0xFFFFFFFFu, part, 1);
                part += __shfl_xor_sync(0xFFFFFFFFu, part, 2);
                if (lk == 0) atomicAdd(&outv[(size_t)b * OT_ + OPC_ + (r & 63)], part);
            }
    }
}

#define SMEM_MMA_H (4 * (128 * KPAD * 2) + 4 * B_STAGE)    // 122880
#define SMEM_MMA_F (4 * (128 * KPADF * 4) + 4 * B_STAGE)   // 163840

// ---------------- fused prep / epilogue helpers --------------------------------
__global__ void fill_mega_k(
    float* gAB, const float* bA, const float* bB,
    float* gCD, const float* bC, const float* bD,
    float* P1, const float* bE, float* Q1, const float* bF,
    float* z1, int n1, float* z2, int n2, float* z3, int n3)
{
    const int BH = B_ * H_;
    const int BH2 = B_ * 2 * H_;
    int i = blockIdx.x * blockDim.x + threadIdx.x;
    if (i < BH2) { int h = i % (2 * H_); gAB[i] = (h < H_) ? bA[h] : bB[h - H_]; return; }
    i -= BH2;
    if (i < BH2) { int h = i % (2 * H_); gCD[i] = (h < H_) ? bC[h] : bD[h - H_]; return; }
    i -= BH2;
    if (i < BH) { P1[i] = bE[i % H_]; return; }
    i -= BH;
    if (i < BH) { Q1[i] = bF[i % H_]; return; }
    i -= BH;
    if (i < n1) { z1[i] = 0.f; return; }
    i -= n1;
    if (i < n2) { z2[i] = 0.f; return; }
    i -= n2;
    if (i < n3) z3[i] = 0.f;
}

// left/current -> lcH
__global__ void prep_cur_k(const float* __restrict__ current, const float* __restrict__ left,
                           __half* __restrict__ lcH)
{
    int i = blockIdx.x * blockDim.x + threadIdx.x;
    if (i >= B_ * H_) return;
    int b = i / H_, h = i % H_;
    lcH[(size_t)b * 2 * H_ + h]      = __float2half_rn(left[i]);
    lcH[(size_t)b * 2 * H_ + H_ + h] = __float2half_rn(current[i]);
}

// opc/var -> out_emb (fp32) + opcH/varH (fp16), single pass
__global__ void prep_emb_k(const float* __restrict__ opc, const float* __restrict__ var,
                           float* __restrict__ out_emb,
                           __half* __restrict__ opcH, __half* __restrict__ varH)
{
    size_t i = (size_t)blockIdx.x * blockDim.x + threadIdx.x;   // float4 units
    const size_t total = (size_t)B_ * OT_ * (H_ / 4);
    if (i >= total) return;
    int h4 = (int)(i % (H_ / 4));
    size_t bo = i / (H_ / 4);
    int o = (int)(bo & 127);
    int b = (int)(bo >> 7);
    float4 v;
    if (o < OPC_) {
        size_t si = (size_t)o * (H_ / 4) + h4;
        v = ((const float4*)opc)[si];
        if (b == 0) {
            ((__half2*)opcH)[2 * si]     = __floats2half2_rn(v.x, v.y);
            ((__half2*)opcH)[2 * si + 1] = __floats2half2_rn(v.z, v.w);
        }
    } else {
        size_t si = ((size_t)b * S2_ + (o - OPC_)) * (H_ / 4) + h4;
        v = ((const float4*)var)[si];
        ((__half2*)varH)[2 * si]     = __floats2half2_rn(v.x, v.y);
        ((__half2*)varH)[2 * si + 1] = __floats2half2_rn(v.z, v.w);
    }
    ((float4*)out_emb)[i] = v;
}

// batched 768x768 transposes -> fp16
__global__ void transpose5h_k(const float* s0, __half* d0, const float* s1, __half* d1,
                              const float* s2, __half* d2, const float* s3, __half* d3,
                              const float* s4, __half* d4)
{
    __shared__ float t[32][33];
    const float* src; __half* dst;
    switch (blockIdx.z) {
        case 0: src = s0; dst = d0; break;
        case 1: src = s1; dst = d1; break;
        case 2: src = s2; dst = d2; break;
        case 3: src = s3; dst = d3; break;
        default: src = s4; dst = d4; break;
    }
    int bx = blockIdx.x * 32, by = blockIdx.y * 32;
    int x = threadIdx.x, y = threadIdx.y;
#pragma unroll
    for (int i = 0; i < 32; i += 8)
        t[y + i][x] = src[(size_t)(by + y + i) * H_ + bx + x];
    __syncthreads();
#pragma unroll
    for (int i = 0; i < 32; i += 8)
        dst[(size_t)(bx + y + i) * H_ + by + x] = __float2half_rn(t[x][y + i]);
}

// batched [1536][768] transposes -> fp16 [768 n][1536 k]
__global__ void transpose3h_k(const float* s0, __half* d0, const float* s1, __half* d1,
                              const float* s2, __half* d2)
{
    __shared__ float t[32][33];
    const float* src; __half* dst;
    switch (blockIdx.z) {
        case 0: src = s0; dst = d0; break;
        case 1: src = s1; dst = d1; break;
        default: src = s2; dst = d2; break;
    }
    int bx = blockIdx.x * 32, by = blockIdx.y * 32;   // grid (24, 48)
    int x = threadIdx.x, y = threadIdx.y;
#pragma unroll
    for (int i = 0; i < 32; i += 8)
        t[y + i][x] = src[(size_t)(by + y + i) * H_ + bx + x];
    __syncthreads();
#pragma unroll
    for (int i = 0; i < 32; i += 8)
        dst[(size_t)(bx + y + i) * (2 * H_) + by + x] = __float2half_rn(t[x][y + i]);
}

// gates -> node (fp32 + fp16 + output copy + lower half of leafH)
__global__ void combine_node_k(const int* __restrict__ has_left,
                               float* __restrict__ out_node)
{
    int i = blockIdx.x * blockDim.x + threadIdx.x;
    if (i >= B_ * H_) return;
    int b = i / H_, h = i % H_;
    size_t base = (size_t)b * 2 * H_ + h;
    float v = has_left[b] ? ftanh(g_gCD[base]) * fsig(g_gCD[base + H_])
                          : ftanh(g_gAB[base]) * fsig(g_gAB[base + H_]);
    g_node[i] = v;
    __half hv = __float2half_rn(v);
    g_nodeH[i] = hv;
    g_leafH[base] = hv;
    out_node[i] = v;
}

// fused softmax (over S1) + context (attn @ enc fp32); writes ctx copies and
// the upper half of leafH. block = 768 threads, grid = B_.
__global__ __launch_bounds__(768) void softmax_context_k(
    const int* __restrict__ smask, const float* __restrict__ enc,
    float* __restrict__ out_ctx)
{
    __shared__ float attn[S1_];
    __shared__ float wred[16];
    const int b = blockIdx.x, t = threadIdx.x;
    const int lane = t & 31, w = t >> 5;

    float x = 0.f;
    if (t < S1_)
        x = smask[(size_t)b * S1_ + t] ? NEGV : g_eng[(size_t)b * S1_ + t];

    if (t < S1_) {
        float m = x;
#pragma unroll
        for (int o = 16; o; o >>= 1) m = fmaxf(m, __shfl_xor_sync(0xFFFFFFFFu, m, o));
        if (lane == 0) wred[w] = m;
    }
    __syncthreads();
    if (t == 0) {
        float m = wred[0];
#pragma unroll
        for (int k = 1; k < 16; k++) m = fmaxf(m, wred[k]);
        wred[0] = m;
    }
    __syncthreads();
    const float mx = wred[0];
    __syncthreads();

    float e = 0.f;
    if (t < S1_) {
        e = __expf(x - mx);
        float s = e;
#pragma unroll
        for (int o = 16; o; o >>= 1) s += __shfl_xor_sync(0xFFFFFFFFu, s, o);
        if (lane == 0) wred[w] = s;
    }
    __syncthreads();
    if (t == 0) {
        float s = wred[0];
#pragma unroll
        for (int k = 1; k < 16; k++) s += wred[k];
        wred[0] = s;
    }
    __syncthreads();
    if (t < S1_) attn[t] = e * __fdividef(1.f, wred[0]);
    __syncthreads();

    const float* ep = enc + (size_t)b * S1_ * H_ + t;
    float acc = 0.f;
#pragma unroll 8
    for (int s = 0; s < S1_; s++)
        acc = fmaf(attn[s], __ldg(ep + (size_t)s * H_), acc);
    size_t oi = (size_t)b * H_ + t;
    g_ctx[oi] = acc;
    out_ctx[oi] = acc;
    g_leafH[(size_t)b * 2 * H_ + H_ + t] = __float2half_rn(acc);
}

__global__ void finalize_score_k(const float* __restrict__ vsc,
                                 const int* __restrict__ cmask,
                                 float* __restrict__ score)
{
    int idx = (blockIdx.x * blockDim.x + threadIdx.x) >> 5;
    if (idx >= B_ * OT_) return;
    int lane = threadIdx.x & 31;
    int b = idx >> 7, o = idx & 127;
    if (cmask[idx]) {
        if (lane == 0) score[idx] = NEGV;
        return;
    }
    if (o >= OPC_) return;
    const float* q1 = g_Q1 + (size_t)b * H_;
    const float* q2 = g_Q2c + (size_t)o * H_;
    float acc = 0.f;
    for (int h = lane; h < H_; h += 32)
        acc += vsc[h] * ftanh(q1[h] + q2[h]);
#pragma unroll
    for (int off = 16; off; off >>= 1) acc += __shfl_xor_sync(0xFFFFFFFFu, acc, off);
    if (lane == 0) score[idx] = acc;
}

// ---------------- launch -------------------------------------------------------
extern "C" void kernel_launch(void* const* d_in, const int* in_sizes, int n_in,
                              void* d_out, int out_size)
{
    (void)in_sizes; (void)n_in; (void)out_size;
    const float* current = (const float*)d_in[0];
    const float* left    = (const float*)d_in[1];
    const float* enc     = (const float*)d_in[2];
    const float* var     = (const float*)d_in[3];
    const float* opc     = (const float*)d_in[4];
    const float* W_l     = (const float*)d_in[5];
    const float* b_l     = (const float*)d_in[6];
    const float* W_lg    = (const float*)d_in[7];
    const float* b_lg    = (const float*)d_in[8];
    const float* W_r     = (const float*)d_in[9];
    const float* b_r     = (const float*)d_in[10];
    const float* W_rg    = (const float*)d_in[11];
    const float* b_rg    = (const float*)d_in[12];
    const float* W_attn  = (const float*)d_in[13];
    const float* b_attn  = (const float*)d_in[14];
    const float* v_attn  = (const float*)d_in[15];
    const float* W_score = (const float*)d_in[16];
    const float* b_score = (const float*)d_in[17];
    const float* v_score = (const float*)d_in[18];
    const int*   has_left = (const int*)d_in[19];
    const int*   smask    = (const int*)d_in[20];
    const int*   cmask    = (const int*)d_in[21];

    float *gAB, *gCD, *node, *P1, *eng, *ctx, *Q1, *Q2c;
    __half *varH, *opcH, *lcH, *nodeH, *leafH;
    __half *WtLLG, *WtRRG, *WtA1, *WtA2, *WtS3, *WtS12;
    cudaGetSymbolAddress((void**)&gAB,  g_gAB);
    cudaGetSymbolAddress((void**)&gCD,  g_gCD);
    cudaGetSymbolAddress((void**)&node, g_node);
    cudaGetSymbolAddress((void**)&P1,   g_P1);
    cudaGetSymbolAddress((void**)&eng,  g_eng);
    cudaGetSymbolAddress((void**)&ctx,  g_ctx);
    cudaGetSymbolAddress((void**)&Q1,   g_Q1);
    cudaGetSymbolAddress((void**)&Q2c,  g_Q2c);
    cudaGetSymbolAddress((void**)&varH, g_varH);
    cudaGetSymbolAddress((void**)&opcH, g_opcH);
    cudaGetSymbolAddress((void**)&lcH,  g_lcH);
    cudaGetSymbolAddress((void**)&nodeH, g_nodeH);
    cudaGetSymbolAddress((void**)&leafH, g_leafH);
    cudaGetSymbolAddress((void**)&WtLLG, g_WtLLG);
    cudaGetSymbolAddress((void**)&WtRRG, g_WtRRG);
    cudaGetSymbolAddress((void**)&WtA1, g_WtA1);
    cudaGetSymbolAddress((void**)&WtA2, g_WtA2);
    cudaGetSymbolAddress((void**)&WtS3, g_WtS3);
    cudaGetSymbolAddress((void**)&WtS12, g_WtS12);

    float* out       = (float*)d_out;
    float* out_score = out;
    float* out_node  = out_score + B_ * OT_;
    float* out_ctx   = out_node + B_ * H_;
    float* out_emb   = out_ctx + B_ * H_;

    const int BH = B_ * H_;
    const int TPB = 256;

    cudaFuncSetAttribute(mma_k<0,0>, cudaFuncAttributeMaxDynamicSharedMemorySize, SMEM_MMA_H);
    cudaFuncSetAttribute(mma_k<1,1>, cudaFuncAttributeMaxDynamicSharedMemorySize, SMEM_MMA_F);
    cudaFuncSetAttribute(mma_k<2,0>, cudaFuncAttributeMaxDynamicSharedMemorySize, SMEM_MMA_H);

    // --- fills + conversions + transposes (independent) ---
    {
        int total = 2 * (B_ * 2 * H_) + 2 * BH + B_ * S1_ + B_ * OT_ + OPC_ * H_;
        fill_mega_k<<<(total + TPB - 1) / TPB, TPB>>>(
            gAB, b_l, b_lg, gCD, b_r, b_rg, P1, b_attn, Q1, b_score,
            eng, B_ * S1_, out_score, B_ * OT_, Q2c, OPC_ * H_);
    }
    prep_cur_k<<<(BH + TPB - 1) / TPB, TPB>>>(current, left, lcH);
    {
        size_t total4 = (size_t)B_ * OT_ * (H_ / 4);
        prep_emb_k<<<(unsigned)((total4 + TPB - 1) / TPB), TPB>>>(opc, var, out_emb, opcH, varH);
    }
    transpose5h_k<<<dim3(24, 24, 5), dim3(32, 8)>>>(
        W_l, WtLLG, W_lg, WtLLG + (size_t)H_ * H_,
        W_attn, WtA1, W_attn + (size_t)H_ * H_, WtA2,
        W_score + (size_t)2 * H_ * H_, WtS3);
    transpose3h_k<<<dim3(24, 48, 3), dim3(32, 8)>>>(
        W_r, WtRRG, W_rg, WtRRG + (size_t)H_ * 2 * H_, W_score, WtS12);

    // --- node: two merged gate GEMMs ---
    mma_k<0,0><<<dim3(6, 2, 6),  512, SMEM_MMA_H>>>(lcH + H_, WtLLG, gAB, nullptr, nullptr,
                                                    B_, H_, 2 * H_, 4, 2 * H_);
    mma_k<0,0><<<dim3(6, 2, 12), 512, SMEM_MMA_H>>>(lcH, WtRRG, gCD, nullptr, nullptr,
                                                    B_, 2 * H_, 2 * H_, 4, 2 * H_);
    combine_node_k<<<(BH + TPB - 1) / TPB, TPB>>>(has_left, out_node);

    // --- attention ---
    mma_k<0,0><<<dim3(3, 2, 6), 512, SMEM_MMA_H>>>(nodeH, WtA1, P1, nullptr, nullptr,
                                                   B_, H_, H_, 4, H_);
    mma_k<1,1><<<dim3(3, (B_ * S1_) / 128, 1), 512, SMEM_MMA_F>>>(enc, WtA2, eng, P1, v_attn,
                                                                  B_ * S1_, H_, H_, 24, 0);
    softmax_context_k<<<B_, 768>>>(smask, enc, out_ctx);

    // --- leaf score ---
    mma_k<0,0><<<dim3(3, 2, 12), 512, SMEM_MMA_H>>>(leafH, WtS12, Q1, nullptr, nullptr,
                                                    B_, 2 * H_, 2 * H_, 4, H_);
    mma_k<0,0><<<dim3(3, 1, 6),  512, SMEM_MMA_H>>>(opcH, WtS3, Q2c, nullptr, nullptr,
                                                    OPC_, H_, H_, 4, H_);
    mma_k<2,0><<<dim3(3, (B_ * S2_) / 128, 1), 512, SMEM_MMA_H>>>(varH, WtS3, out_score, Q1, v_score,
                                                                  B_ * S2_, H_, H_, 24, 0);
    finalize_score_k<<<(B_ * OT_ * 32 + TPB - 1) / TPB, TPB>>>(v_score, cmask, out_score);
}

// round 11
// speedup vs baseline: 1.1617x; 1.0243x over previous
#include <cuda_runtime.h>
#include <cuda_fp16.h>
#include <math.h>
#include <stdint.h>

#define B_   256
#define S1_  512
#define S2_  64
#define H_   768
#define OPC_ 64
#define OT_  128
#define NEGV (-1e12f)

// ---------------- scratch (device globals) ----------------------------------
__device__ float g_gAB [B_ * 2 * H_];     // [B][1536]: gA | gB
__device__ float g_gCD [B_ * 2 * H_];     // [B][1536]: gC | gD
__device__ float g_node[B_ * H_];
__device__ float g_P1  [B_ * H_];
__device__ float g_eng3[3 * B_ * S1_];    // per-x-CTA energy partials
__device__ float g_sc3 [3 * B_ * S2_];    // per-x-CTA score partials
__device__ float g_ctx [B_ * H_];
__device__ float g_Q1  [B_ * H_];
__device__ float g_Q2c [OPC_ * H_];
// fp16 activations
__device__ __half g_encH [(size_t)B_ * S1_ * H_];
__device__ __half g_varH [(size_t)B_ * S2_ * H_];
__device__ __half g_opcH [OPC_ * H_];
__device__ __half g_lcH  [B_ * 2 * H_];   // [left | current]
__device__ __half g_nodeH[B_ * H_];
__device__ __half g_leafH[B_ * 2 * H_];
// fp16 transposed weights: Wt[n][k] = W[k][n]
__device__ __half g_WtLLG [2 * H_ * H_];
__device__ __half g_WtRRG [2 * H_ * 2 * H_];
__device__ __half g_WtA1  [H_ * H_];
__device__ __half g_WtA2  [H_ * H_];
__device__ __half g_WtS3  [H_ * H_];
__device__ __half g_WtS12 [H_ * 2 * H_];

// ---------------- helpers ------------------------------------------------------
__device__ __forceinline__ float tanh_fast(float x) {
    float y; asm("tanh.approx.f32 %0, %1;" : "=f"(y) : "f"(x)); return y;
}
__device__ __forceinline__ float ftanh(float x) {
    float ax = fabsf(x);
    float e  = __expf(2.0f * ax);
    float r  = 1.0f - __fdividef(2.0f, e + 1.0f);
    return copysignf(r, x);
}
__device__ __forceinline__ float fsig(float x) {
    return __fdividef(1.0f, 1.0f + __expf(-x));
}
__device__ __forceinline__ uint32_t smem_u32(const void* p) {
    uint32_t a;
    asm("{ .reg .u64 t; cvta.to.shared.u64 t, %1; cvt.u32.u64 %0, t; }" : "=r"(a) : "l"(p));
    return a;
}
__device__ __forceinline__ void cp16(uint32_t saddr, const void* g, uint32_t sz) {
    asm volatile("cp.async.cg.shared.global [%0], [%1], 16, %2;"
                 :: "r"(saddr), "l"(g), "r"(sz) : "memory");
}
__device__ __forceinline__ void cp_commit() {
    asm volatile("cp.async.commit_group;" ::: "memory");
}
__device__ __forceinline__ void cp_wait2() {
    asm volatile("cp.async.wait_group 2;" ::: "memory");
}
__device__ __forceinline__ void cp_wait0() {
    asm volatile("cp.async.wait_group 0;" ::: "memory");
}
__device__ __forceinline__ void ldm4(uint32_t r[4], uint32_t addr) {
    asm volatile("ldmatrix.sync.aligned.m8n8.x4.shared.b16 {%0,%1,%2,%3}, [%4];"
                 : "=r"(r[0]), "=r"(r[1]), "=r"(r[2]), "=r"(r[3]) : "r"(addr));
}
__device__ __forceinline__ void mma_f16(float c[4], const uint32_t a[4],
                                        uint32_t b0, uint32_t b1) {
    asm volatile(
        "mma.sync.aligned.m16n8k16.row.col.f32.f16.f16.f32 "
        "{%0,%1,%2,%3}, {%4,%5,%6,%7}, {%8,%9}, {%0,%1,%2,%3};"
        : "+f"(c[0]), "+f"(c[1]), "+f"(c[2]), "+f"(c[3])
        : "r"(a[0]), "r"(a[1]), "r"(a[2]), "r"(a[3]), "r"(b0), "r"(b1));
}

// ---------------- pipelined fp16 MMA kernel (cp.async 4-stage, BK=32) ----------
// C-tile 128m x 256n, 512 thr = 16 warps (4 m-bands x 4 n-groups), warp 32x64.
// A row-major [M,lda] fp16; Wt row-major [N][K] fp16.
// MODE 0: split-K over blockIdx.z, atomicAdd into C[M,ldc] (bias preloaded).
// MODE 1: energy partial: out[blockIdx.x*(B*S1) + r] = sum_n v[n]*tanh(P1[bm>>9,n]+acc)
// MODE 2: score partial:  out[blockIdx.x*(B*S2) + r] = ... with Q1[r>>6]
#define KPAD 40
#define A_STAGE (128 * KPAD * 2)            // 10240 B
#define B_STAGE (256 * KPAD * 2)            // 20480 B
#define SMEM_MMA (4 * (A_STAGE + B_STAGE))  // 122880 B

template <int MODE>
__global__ __launch_bounds__(512, 1) void mma_k(
    const __half* __restrict__ A, const __half* __restrict__ Wt,
    float* __restrict__ outv,
    const float* __restrict__ aux1, const float* __restrict__ aux2,
    int M, int K, int lda, int niter, int ldc)
{
    extern __shared__ __align__(16) __half smh[];
    const uint32_t sA = smem_u32(smh);
    const uint32_t sB = sA + 4 * A_STAGE;

    const int tid  = threadIdx.x;
    const int lane = tid & 31;
    const int wid  = tid >> 5;
    const int wm   = wid & 3;
    const int wn   = wid >> 2;
    const int bm   = blockIdx.y * 128;
    const int bn   = blockIdx.x * 256;
    const int kst  = blockIdx.z * niter * 32;

    float acc[2][8][4];
#pragma unroll
    for (int i = 0; i < 2; i++)
#pragma unroll
        for (int j = 0; j < 8; j++)
#pragma unroll
            for (int q = 0; q < 4; q++) acc[i][j][q] = 0.f;

    // loaders: A 128 rows x 64B (1 cp16/thread); B 256 rows x 64B (2 cp16/thread)
    const int l_row = tid >> 2;
    const int lq    = tid & 3;
    const uint32_t a_sz = ((bm + l_row) < M) ? 16u : 0u;
    const __half* Ap  = A  + (size_t)(bm + l_row) * lda + kst + lq * 8;
    const __half* Bp0 = Wt + (size_t)(bn + l_row) * K + kst + lq * 8;
    const __half* Bp1 = Wt + (size_t)(bn + 128 + l_row) * K + kst + lq * 8;
    const uint32_t dA  = sA + (uint32_t)(l_row * KPAD + lq * 8) * 2u;
    const uint32_t dB0 = sB + (uint32_t)(l_row * KPAD + lq * 8) * 2u;
    const uint32_t dB1 = sB + (uint32_t)((128 + l_row) * KPAD + lq * 8) * 2u;

    auto issue = [&](int stage, int kt) {
        cp16(dA  + (uint32_t)stage * A_STAGE, Ap  + (size_t)kt * 32, a_sz);
        cp16(dB0 + (uint32_t)stage * B_STAGE, Bp0 + (size_t)kt * 32, 16u);
        cp16(dB1 + (uint32_t)stage * B_STAGE, Bp1 + (size_t)kt * 32, 16u);
    };

#pragma unroll
    for (int s = 0; s < 3; s++) {
        if (s < niter) issue(s, s);
        cp_commit();
    }

    const int lk = lane & 3;
    const int lg = lane >> 2;
    const int l15 = lane & 15;
    const int lhi = lane >> 4;
    const int l8k = (lane >> 3) & 1;
    const int l7  = lane & 7;

    const uint32_t aoff = (uint32_t)((wm * 32 + l15) * KPAD) * 2u + (uint32_t)lhi * 16u;
    const uint32_t boff = (uint32_t)((wn * 64 + l7 + lhi * 8) * KPAD) * 2u + (uint32_t)l8k * 16u;

    for (int c = 0; c < niter; c++) {
        cp_wait2();
        __syncthreads();
        const uint32_t soa = (uint32_t)(c & 3) * A_STAGE;
        const uint32_t sob = (uint32_t)(c & 3) * B_STAGE;

#pragma unroll
        for (int ks = 0; ks < 2; ks++) {
            const uint32_t kso = (uint32_t)ks * 32u;
            uint32_t a0[4], a1[4];
            ldm4(a0, sA + soa + aoff + kso);
            ldm4(a1, sA + soa + aoff + kso + 16u * KPAD * 2u);
#pragma unroll
            for (int p = 0; p < 4; p++) {
                uint32_t bb[4];
                ldm4(bb, sB + sob + boff + kso + (uint32_t)(p * 16 * KPAD) * 2u);
                mma_f16(acc[0][2 * p],     a0, bb[0], bb[1]);
                mma_f16(acc[0][2 * p + 1], a0, bb[2], bb[3]);
                mma_f16(acc[1][2 * p],     a1, bb[0], bb[1]);
                mma_f16(acc[1][2 * p + 1], a1, bb[2], bb[3]);
            }
        }

        if (c + 3 < niter) issue((c + 3) & 3, c + 3);
        cp_commit();
    }

    // ---------------- epilogues ----------------
    if (MODE == 0) {
#pragma unroll
        for (int ti = 0; ti < 2; ti++)
#pragma unroll
            for (int nj = 0; nj < 8; nj++) {
                int r0 = bm + wm * 32 + ti * 16 + lg;
                int cc = bn + wn * 64 + nj * 8 + 2 * lk;
                if (r0 < M) {
                    atomicAdd(&outv[(size_t)r0 * ldc + cc],     acc[ti][nj][0]);
                    atomicAdd(&outv[(size_t)r0 * ldc + cc + 1], acc[ti][nj][1]);
                }
                if (r0 + 8 < M) {
                    atomicAdd(&outv[(size_t)(r0 + 8) * ldc + cc],     acc[ti][nj][2]);
                    atomicAdd(&outv[(size_t)(r0 + 8) * ldc + cc + 1], acc[ti][nj][3]);
                }
            }
        return;
    }

    // MODE 1/2: tanh-dot partials, wn-reduce in SMEM, plain store per x-CTA
    float vv[16];
#pragma unroll
    for (int nj = 0; nj < 8; nj++)
#pragma unroll
        for (int u = 0; u < 2; u++)
            vv[nj * 2 + u] = __ldg(&aux2[bn + wn * 64 + nj * 8 + 2 * lk + u]);

    float part_rh[2][2];
#pragma unroll
    for (int ti = 0; ti < 2; ti++)
#pragma unroll
        for (int half = 0; half < 2; half++) {
            int r = bm + wm * 32 + ti * 16 + lg + half * 8;
            const int brow = (MODE == 1) ? (bm >> 9) : (r >> 6);
            const float* p1 = aux1 + (size_t)brow * H_;
            float part = 0.f;
#pragma unroll
            for (int nj = 0; nj < 8; nj++) {
                int n = bn + wn * 64 + nj * 8 + 2 * lk;
                part += vv[nj * 2]     * tanh_fast(acc[ti][nj][half * 2]     + __ldg(&p1[n]));
                part += vv[nj * 2 + 1] * tanh_fast(acc[ti][nj][half * 2 + 1] + __ldg(&p1[n + 1]));
            }
            part += __shfl_xor_sync(0xFFFFFFFFu, part, 1);
            part += __shfl_xor_sync(0xFFFFFFFFu, part, 2);
            part_rh[ti][half] = part;
        }

    cp_wait0();
    __syncthreads();
    float* red = (float*)smh;      // 128 rows x 4 wn
#pragma unroll
    for (int ti = 0; ti < 2; ti++)
#pragma unroll
        for (int half = 0; half < 2; half++)
            if (lk == 0)
                red[(wm * 32 + ti * 16 + lg + half * 8) * 4 + wn] = part_rh[ti][half];
    __syncthreads();
    if (tid < 128) {
        float s = red[tid * 4] + red[tid * 4 + 1] + red[tid * 4 + 2] + red[tid * 4 + 3];
        const int stride = (MODE == 1) ? (B_ * S1_) : (B_ * S2_);
        outv[(size_t)blockIdx.x * stride + bm + tid] = s;
    }
}

// ---------------- fused prep / epilogue helpers --------------------------------
__global__ void fill_mega_k(
    float* gAB, const float* bA, const float* bB,
    float* gCD, const float* bC, const float* bD,
    float* P1, const float* bE, float* Q1, const float* bF,
    float* z1, int n1)
{
    const int BH = B_ * H_;
    const int BH2 = B_ * 2 * H_;
    int i = blockIdx.x * blockDim.x + threadIdx.x;
    if (i < BH2) { int h = i % (2 * H_); gAB[i] = (h < H_) ? bA[h] : bB[h - H_]; return; }
    i -= BH2;
    if (i < BH2) { int h = i % (2 * H_); gCD[i] = (h < H_) ? bC[h] : bD[h - H_]; return; }
    i -= BH2;
    if (i < BH) { P1[i] = bE[i % H_]; return; }
    i -= BH;
    if (i < BH) { Q1[i] = bF[i % H_]; return; }
    i -= BH;
    if (i < n1) z1[i] = 0.f;
}

__global__ void cvt_h_k(const float* __restrict__ src, __half* __restrict__ dst, int n4)
{
    int i = blockIdx.x * blockDim.x + threadIdx.x;
    if (i >= n4) return;
    float4 v = ((const float4*)src)[i];
    ((__half2*)dst)[2 * i]     = __floats2half2_rn(v.x, v.y);
    ((__half2*)dst)[2 * i + 1] = __floats2half2_rn(v.z, v.w);
}

// left/current -> lcH
__global__ void prep_cur_k(const float* __restrict__ current, const float* __restrict__ left,
                           __half* __restrict__ lcH)
{
    int i = blockIdx.x * blockDim.x + threadIdx.x;
    if (i >= B_ * H_) return;
    int b = i / H_, h = i % H_;
    lcH[(size_t)b * 2 * H_ + h]      = __float2half_rn(left[i]);
    lcH[(size_t)b * 2 * H_ + H_ + h] = __float2half_rn(current[i]);
}

// opc/var -> out_emb (fp32) + opcH/varH (fp16), single pass
__global__ void prep_emb_k(const float* __restrict__ opc, const float* __restrict__ var,
                           float* __restrict__ out_emb,
                           __half* __restrict__ opcH, __half* __restrict__ varH)
{
    size_t i = (size_t)blockIdx.x * blockDim.x + threadIdx.x;   // float4 units
    const size_t total = (size_t)B_ * OT_ * (H_ / 4);
    if (i >= total) return;
    int h4 = (int)(i % (H_ / 4));
    size_t bo = i / (H_ / 4);
    int o = (int)(bo & 127);
    int b = (int)(bo >> 7);
    float4 v;
    if (o < OPC_) {
        size_t si = (size_t)o * (H_ / 4) + h4;
        v = ((const float4*)opc)[si];
        if (b == 0) {
            ((__half2*)opcH)[2 * si]     = __floats2half2_rn(v.x, v.y);
            ((__half2*)opcH)[2 * si + 1] = __floats2half2_rn(v.z, v.w);
        }
    } else {
        size_t si = ((size_t)b * S2_ + (o - OPC_)) * (H_ / 4) + h4;
        v = ((const float4*)var)[si];
        ((__half2*)varH)[2 * si]     = __floats2half2_rn(v.x, v.y);
        ((__half2*)varH)[2 * si + 1] = __floats2half2_rn(v.z, v.w);
    }
    ((float4*)out_emb)[i] = v;
}

// merged transposes -> fp16. z<5: 768x768 (dst stride 768); z>=5: 1536x768
// (dst [768 n][1536 k]). grid (24, 48, 8); square cases skip by >= 768.
__global__ void transpose8h_k(
    const float* s0, __half* d0, const float* s1, __half* d1,
    const float* s2, __half* d2, const float* s3, __half* d3,
    const float* s4, __half* d4,
    const float* t0, __half* e0, const float* t1, __half* e1,
    const float* t2, __half* e2)
{
    __shared__ float t[32][33];
    const float* src; __half* dst;
    int rows, dstride;
    switch (blockIdx.z) {
        case 0: src = s0; dst = d0; rows = H_; dstride = H_; break;
        case 1: src = s1; dst = d1; rows = H_; dstride = H_; break;
        case 2: src = s2; dst = d2; rows = H_; dstride = H_; break;
        case 3: src = s3; dst = d3; rows = H_; dstride = H_; break;
        case 4: src = s4; dst = d4; rows = H_; dstride = H_; break;
        case 5: src = t0; dst = e0; rows = 2 * H_; dstride = 2 * H_; break;
        case 6: src = t1; dst = e1; rows = 2 * H_; dstride = 2 * H_; break;
        default: src = t2; dst = e2; rows = 2 * H_; dstride = 2 * H_; break;
    }
    int bx = blockIdx.x * 32, by = blockIdx.y * 32;
    if (by >= rows) return;
    int x = threadIdx.x, y = threadIdx.y;
#pragma unroll
    for (int i = 0; i < 32; i += 8)
        t[y + i][x] = src[(size_t)(by + y + i) * H_ + bx + x];
    __syncthreads();
#pragma unroll
    for (int i = 0; i < 32; i += 8)
        dst[(size_t)(bx + y + i) * dstride + by + x] = __float2half_rn(t[x][y + i]);
}

// gates -> node (fp32 + fp16 + output copy + lower half of leafH)
__global__ void combine_node_k(const int* __restrict__ has_left,
                               float* __restrict__ out_node)
{
    int i = blockIdx.x * blockDim.x + threadIdx.x;
    if (i >= B_ * H_) return;
    int b = i / H_, h = i % H_;
    size_t base = (size_t)b * 2 * H_ + h;
    float v = has_left[b] ? ftanh(g_gCD[base]) * fsig(g_gCD[base + H_])
                          : ftanh(g_gAB[base]) * fsig(g_gAB[base + H_]);
    g_node[i] = v;
    __half hv = __float2half_rn(v);
    g_nodeH[i] = hv;
    g_leafH[base] = hv;
    out_node[i] = v;
}

// fused softmax (over S1, summing 3 energy partials) + context (attn @ encH);
// writes ctx copies and the upper half of leafH. block = 768, grid = B_.
__global__ __launch_bounds__(768) void softmax_context_k(
    const int* __restrict__ smask, const __half* __restrict__ encH,
    float* __restrict__ out_ctx)
{
    __shared__ float attn[S1_];
    __shared__ float wred[16];
    const int b = blockIdx.x, t = threadIdx.x;
    const int lane = t & 31, w = t >> 5;
    const int BS1 = B_ * S1_;

    float x = 0.f;
    if (t < S1_) {
        size_t i = (size_t)b * S1_ + t;
        x = smask[i] ? NEGV : (g_eng3[i] + g_eng3[i + BS1] + g_eng3[i + 2 * BS1]);
    }

    if (t < S1_) {
        float m = x;
#pragma unroll
        for (int o = 16; o; o >>= 1) m = fmaxf(m, __shfl_xor_sync(0xFFFFFFFFu, m, o));
        if (lane == 0) wred[w] = m;
    }
    __syncthreads();
    if (t == 0) {
        float m = wred[0];
#pragma unroll
        for (int k = 1; k < 16; k++) m = fmaxf(m, wred[k]);
        wred[0] = m;
    }
    __syncthreads();
    const float mx = wred[0];
    __syncthreads();

    float e = 0.f;
    if (t < S1_) {
        e = __expf(x - mx);
        float s = e;
#pragma unroll
        for (int o = 16; o; o >>= 1) s += __shfl_xor_sync(0xFFFFFFFFu, s, o);
        if (lane == 0) wred[w] = s;
    }
    __syncthreads();
    if (t == 0) {
        float s = wred[0];
#pragma unroll
        for (int k = 1; k < 16; k++) s += wred[k];
        wred[0] = s;
    }
    __syncthreads();
    if (t < S1_) attn[t] = e * __fdividef(1.f, wred[0]);
    __syncthreads();

    const __half* ep = encH + (size_t)b * S1_ * H_ + t;
    float acc = 0.f;
#pragma unroll 8
    for (int s = 0; s < S1_; s++)
        acc = fmaf(attn[s], __half2float(ep[(size_t)s * H_]), acc);
    size_t oi = (size_t)b * H_ + t;
    g_ctx[oi] = acc;
    out_ctx[oi] = acc;
    g_leafH[(size_t)b * 2 * H_ + H_ + t] = __float2half_rn(acc);
}

// full score assembly: mask; o<64 from Q1/Q2c; o>=64 = sum of 3 MMA partials
__global__ void finalize_score_k(const float* __restrict__ vsc,
                                 const int* __restrict__ cmask,
                                 float* __restrict__ score)
{
    int idx = (blockIdx.x * blockDim.x + threadIdx.x) >> 5;
    if (idx >= B_ * OT_) return;
    int lane = threadIdx.x & 31;
    int b = idx >> 7, o = idx & 127;
    if (cmask[idx]) {
        if (lane == 0) score[idx] = NEGV;
        return;
    }
    if (o >= OPC_) {
        if (lane == 0) {
            const int BS2 = B_ * S2_;
            int r = b * S2_ + (o - OPC_);
            score[idx] = g_sc3[r] + g_sc3[r + BS2] + g_sc3[r + 2 * BS2];
        }
        return;
    }
    const float* q1 = g_Q1 + (size_t)b * H_;
    const float* q2 = g_Q2c + (size_t)o * H_;
    float acc = 0.f;
    for (int h = lane; h < H_; h += 32)
        acc += vsc[h] * ftanh(q1[h] + q2[h]);
#pragma unroll
    for (int off = 16; off; off >>= 1) acc += __shfl_xor_sync(0xFFFFFFFFu, acc, off);
    if (lane == 0) score[idx] = acc;
}

// ---------------- launch -------------------------------------------------------
extern "C" void kernel_launch(void* const* d_in, const int* in_sizes, int n_in,
                              void* d_out, int out_size)
{
    (void)in_sizes; (void)n_in; (void)out_size;
    const float* current = (const float*)d_in[0];
    const float* left    = (const float*)d_in[1];
    const float* enc     = (const float*)d_in[2];
    const float* var     = (const float*)d_in[3];
    const float* opc     = (const float*)d_in[4];
    const float* W_l     = (const float*)d_in[5];
    const float* b_l     = (const float*)d_in[6];
    const float* W_lg    = (const float*)d_in[7];
    const float* b_lg    = (const float*)d_in[8];
    const float* W_r     = (const float*)d_in[9];
    const float* b_r     = (const float*)d_in[10];
    const float* W_rg    = (const float*)d_in[11];
    const float* b_rg    = (const float*)d_in[12];
    const float* W_attn  = (const float*)d_in[13];
    const float* b_attn  = (const float*)d_in[14];
    const float* v_attn  = (const float*)d_in[15];
    const float* W_score = (const float*)d_in[16];
    const float* b_score = (const float*)d_in[17];
    const float* v_score = (const float*)d_in[18];
    const int*   has_left = (const int*)d_in[19];
    const int*   smask    = (const int*)d_in[20];
    const int*   cmask    = (const int*)d_in[21];

    float *gAB, *gCD, *node, *P1, *eng3, *sc3, *ctx, *Q1, *Q2c;
    __half *encH, *varH, *opcH, *lcH, *nodeH, *leafH;
    __half *WtLLG, *WtRRG, *WtA1, *WtA2, *WtS3, *WtS12;
    cudaGetSymbolAddress((void**)&gAB,  g_gAB);
    cudaGetSymbolAddress((void**)&gCD,  g_gCD);
    cudaGetSymbolAddress((void**)&node, g_node);
    cudaGetSymbolAddress((void**)&P1,   g_P1);
    cudaGetSymbolAddress((void**)&eng3, g_eng3);
    cudaGetSymbolAddress((void**)&sc3,  g_sc3);
    cudaGetSymbolAddress((void**)&ctx,  g_ctx);
    cudaGetSymbolAddress((void**)&Q1,   g_Q1);
    cudaGetSymbolAddress((void**)&Q2c,  g_Q2c);
    cudaGetSymbolAddress((void**)&encH, g_encH);
    cudaGetSymbolAddress((void**)&varH, g_varH);
    cudaGetSymbolAddress((void**)&opcH, g_opcH);
    cudaGetSymbolAddress((void**)&lcH,  g_lcH);
    cudaGetSymbolAddress((void**)&nodeH, g_nodeH);
    cudaGetSymbolAddress((void**)&leafH, g_leafH);
    cudaGetSymbolAddress((void**)&WtLLG, g_WtLLG);
    cudaGetSymbolAddress((void**)&WtRRG, g_WtRRG);
    cudaGetSymbolAddress((void**)&WtA1, g_WtA1);
    cudaGetSymbolAddress((void**)&WtA2, g_WtA2);
    cudaGetSymbolAddress((void**)&WtS3, g_WtS3);
    cudaGetSymbolAddress((void**)&WtS12, g_WtS12);

    float* out       = (float*)d_out;
    float* out_score = out;
    float* out_node  = out_score + B_ * OT_;
    float* out_ctx   = out_node + B_ * H_;
    float* out_emb   = out_ctx + B_ * H_;

    const int BH = B_ * H_;
    const int TPB = 256;

    cudaFuncSetAttribute(mma_k<0>, cudaFuncAttributeMaxDynamicSharedMemorySize, SMEM_MMA);
    cudaFuncSetAttribute(mma_k<1>, cudaFuncAttributeMaxDynamicSharedMemorySize, SMEM_MMA);
    cudaFuncSetAttribute(mma_k<2>, cudaFuncAttributeMaxDynamicSharedMemorySize, SMEM_MMA);

    // --- fills + conversions + transposes (independent) ---
    {
        int total = 2 * (B_ * 2 * H_) + 2 * BH + OPC_ * H_;
        fill_mega_k<<<(total + TPB - 1) / TPB, TPB>>>(
            gAB, b_l, b_lg, gCD, b_r, b_rg, P1, b_attn, Q1, b_score,
            Q2c, OPC_ * H_);
    }
    prep_cur_k<<<(BH + TPB - 1) / TPB, TPB>>>(current, left, lcH);
    {
        size_t total4 = (size_t)B_ * OT_ * (H_ / 4);
        prep_emb_k<<<(unsigned)((total4 + TPB - 1) / TPB), TPB>>>(opc, var, out_emb, opcH, varH);
    }
    {
        int n4 = B_ * S1_ * (H_ / 4);
        cvt_h_k<<<(n4 + TPB - 1) / TPB, TPB>>>(enc, encH, n4);
    }
    transpose8h_k<<<dim3(24, 48, 8), dim3(32, 8)>>>(
        W_l, WtLLG, W_lg, WtLLG + (size_t)H_ * H_,
        W_attn, WtA1, W_attn + (size_t)H_ * H_, WtA2,
        W_score + (size_t)2 * H_ * H_, WtS3,
        W_r, WtRRG, W_rg, WtRRG + (size_t)H_ * 2 * H_, W_score, WtS12);

    // --- node: two merged gate GEMMs ---
    mma_k<0><<<dim3(6, 2, 6),  512, SMEM_MMA>>>(lcH + H_, WtLLG, gAB, nullptr, nullptr,
                                                B_, H_, 2 * H_, 4, 2 * H_);
    mma_k<0><<<dim3(6, 2, 12), 512, SMEM_MMA>>>(lcH, WtRRG, gCD, nullptr, nullptr,
                                                B_, 2 * H_, 2 * H_, 4, 2 * H_);
    combine_node_k<<<(BH + TPB - 1) / TPB, TPB>>>(has_left, out_node);

    // --- attention ---
    mma_k<0><<<dim3(3, 2, 6), 512, SMEM_MMA>>>(nodeH, WtA1, P1, nullptr, nullptr,
                                               B_, H_, H_, 4, H_);
    mma_k<1><<<dim3(3, (B_ * S1_) / 128, 1), 512, SMEM_MMA>>>(encH, WtA2, eng3, P1, v_attn,
                                                              B_ * S1_, H_, H_, 24, 0);
    softmax_context_k<<<B_, 768>>>(smask, encH, out_ctx);

    // --- leaf score ---
    mma_k<0><<<dim3(3, 2, 12), 512, SMEM_MMA>>>(leafH, WtS12, Q1, nullptr, nullptr,
                                                B_, 2 * H_, 2 * H_, 4, H_);
    mma_k<0><<<dim3(3, 1, 6),  512, SMEM_MMA>>>(opcH, WtS3, Q2c, nullptr, nullptr,
                                                OPC_, H_, H_, 4, H_);
    mma_k<2><<<dim3(3, (B_ * S2_) / 128, 1), 512, SMEM_MMA>>>(varH, WtS3, sc3, Q1, v_score,
                                                              B_ * S2_, H_, H_, 24, 0);
    finalize_score_k<<<(B_ * OT_ * 32 + TPB - 1) / TPB, TPB>>>(v_score, cmask, out_score);
}

// round 12
// speedup vs baseline: 1.1883x; 1.0229x over previous
#include <cuda_runtime.h>
#include <cuda_fp16.h>
#include <math.h>
#include <stdint.h>

#define B_   256
#define S1_  512
#define S2_  64
#define H_   768
#define OPC_ 64
#define OT_  128
#define NEGV (-1e12f)

// ---------------- scratch (device globals) ----------------------------------
__device__ float g_gAB [B_ * 2 * H_];     // [B][1536]: gA | gB
__device__ float g_gCD [B_ * 2 * H_];     // [B][1536]: gC | gD
__device__ float g_node[B_ * H_];
__device__ float g_P1  [B_ * H_];
__device__ float g_eng [B_ * S1_];
__device__ float g_ctx [B_ * H_];
__device__ float g_Q1  [B_ * H_];
__device__ float g_Q2c [OPC_ * H_];
// fp16 activations
__device__ __half g_encH [(size_t)B_ * S1_ * H_];
__device__ __half g_varH [(size_t)B_ * S2_ * H_];
__device__ __half g_curH [B_ * H_];
__device__ __half g_opcH [OPC_ * H_];
__device__ __half g_lcH  [B_ * 2 * H_];
__device__ __half g_nodeH[B_ * H_];
__device__ __half g_leafH[B_ * 2 * H_];
// fp16 transposed weights: Wt[n][k] = W[k][n]
__device__ __half g_WtLLG [2 * H_ * H_];
__device__ __half g_WtRRG [2 * H_ * 2 * H_];
__device__ __half g_WtA1  [H_ * H_];
__device__ __half g_WtA2  [H_ * H_];
__device__ __half g_WtS3  [H_ * H_];
__device__ __half g_WtS12 [H_ * 2 * H_];

// ---------------- helpers ------------------------------------------------------
__device__ __forceinline__ float tanh_fast(float x) {
    float y; asm("tanh.approx.f32 %0, %1;" : "=f"(y) : "f"(x)); return y;
}
__device__ __forceinline__ float ftanh(float x) {
    float ax = fabsf(x);
    float e  = __expf(2.0f * ax);
    float r  = 1.0f - __fdividef(2.0f, e + 1.0f);
    return copysignf(r, x);
}
__device__ __forceinline__ float fsig(float x) {
    return __fdividef(1.0f, 1.0f + __expf(-x));
}
__device__ __forceinline__ uint32_t smem_u32(const void* p) {
    uint32_t a;
    asm("{ .reg .u64 t; cvta.to.shared.u64 t, %1; cvt.u32.u64 %0, t; }" : "=r"(a) : "l"(p));
    return a;
}
__device__ __forceinline__ void cp16(uint32_t saddr, const __half* g, uint32_t sz) {
    asm volatile("cp.async.cg.shared.global [%0], [%1], 16, %2;"
                 :: "r"(saddr), "l"(g), "r"(sz) : "memory");
}
__device__ __forceinline__ void cp_commit() {
    asm volatile("cp.async.commit_group;" ::: "memory");
}
__device__ __forceinline__ void cp_wait2() {
    asm volatile("cp.async.wait_group 2;" ::: "memory");
}
__device__ __forceinline__ void ldm4(uint32_t r[4], uint32_t addr) {
    asm volatile("ldmatrix.sync.aligned.m8n8.x4.shared.b16 {%0,%1,%2,%3}, [%4];"
                 : "=r"(r[0]), "=r"(r[1]), "=r"(r[2]), "=r"(r[3]) : "r"(addr));
}
__device__ __forceinline__ void mma_f16(float c[4], const uint32_t a[4],
                                        uint32_t b0, uint32_t b1) {
    asm volatile(
        "mma.sync.aligned.m16n8k16.row.col.f32.f16.f16.f32 "
        "{%0,%1,%2,%3}, {%4,%5,%6,%7}, {%8,%9}, {%0,%1,%2,%3};"
        : "+f"(c[0]), "+f"(c[1]), "+f"(c[2]), "+f"(c[3])
        : "r"(a[0]), "r"(a[1]), "r"(a[2]), "r"(a[3]), "r"(b0), "r"(b1));
}

// ---------------- pipelined fp16 MMA kernel (cp.async 4-stage, BK=32) ----------
// C-tile 128m x 256n, 512 thr = 16 warps (4 m-bands x 4 n-groups), warp 32x64.
// A row-major [M,K] fp16; Wt row-major [N][K] fp16. SMEM rows padded to 40 halfs.
// MODE 0: split-K (blockIdx.z), atomicAdd into C[M,ldc] (bias preloaded).
// MODE 1: energy out[r] += sum_n v[n]*tanh(aux1[bm>>9, n] + acc)
// MODE 2: score  out[(r>>6)*128+64+(r&63)] += sum_n v[n]*tanh(aux1[r>>6, n] + acc)
#define KPAD 40
#define A_STAGE (128 * KPAD * 2)            // 10240 B
#define B_STAGE (256 * KPAD * 2)            // 20480 B
#define SMEM_MMA (4 * (A_STAGE + B_STAGE))  // 122880 B

template <int MODE>
__global__ __launch_bounds__(512, 1) void mma_k(
    const __half* __restrict__ A, const __half* __restrict__ Wt,
    float* __restrict__ outv,
    const float* __restrict__ aux1, const float* __restrict__ aux2,
    int M, int K, int niter, int ldc)
{
    extern __shared__ __align__(16) __half smh[];
    const uint32_t sA = smem_u32(smh);
    const uint32_t sB = sA + 4 * A_STAGE;

    const int tid  = threadIdx.x;
    const int lane = tid & 31;
    const int wid  = tid >> 5;
    const int wm   = wid & 3;
    const int wn   = wid >> 2;
    const int bm   = blockIdx.y * 128;
    const int bn   = blockIdx.x * 256;
    const int kst  = blockIdx.z * niter * 32;

    float acc[2][8][4];
#pragma unroll
    for (int i = 0; i < 2; i++)
#pragma unroll
        for (int j = 0; j < 8; j++)
#pragma unroll
            for (int q = 0; q < 4; q++) acc[i][j][q] = 0.f;

    // loaders: A 128 rows x 64B (1 cp16/thread); B 256 rows x 64B (2 cp16/thread)
    const int l_row = tid >> 2;
    const int lq    = tid & 3;
    const uint32_t a_sz = ((bm + l_row) < M) ? 16u : 0u;
    const __half* Ap  = A  + (size_t)(bm + l_row) * K + kst + lq * 8;
    const __half* Bp0 = Wt + (size_t)(bn + l_row) * K + kst + lq * 8;
    const __half* Bp1 = Wt + (size_t)(bn + 128 + l_row) * K + kst + lq * 8;
    const uint32_t dA  = sA + (uint32_t)(l_row * KPAD + lq * 8) * 2u;
    const uint32_t dB0 = sB + (uint32_t)(l_row * KPAD + lq * 8) * 2u;
    const uint32_t dB1 = sB + (uint32_t)((128 + l_row) * KPAD + lq * 8) * 2u;

    auto issue = [&](int stage, int kt) {
        cp16(dA  + (uint32_t)stage * A_STAGE, Ap  + (size_t)kt * 32, a_sz);
        cp16(dB0 + (uint32_t)stage * B_STAGE, Bp0 + (size_t)kt * 32, 16u);
        cp16(dB1 + (uint32_t)stage * B_STAGE, Bp1 + (size_t)kt * 32, 16u);
    };

#pragma unroll
    for (int s = 0; s < 3; s++) {
        if (s < niter) issue(s, s);
        cp_commit();
    }

    const int lk = lane & 3;
    const int lg = lane >> 2;
    const int l15 = lane & 15;
    const int lhi = lane >> 4;
    const int l8k = (lane >> 3) & 1;
    const int l7  = lane & 7;

    const uint32_t aoff = (uint32_t)((wm * 32 + l15) * KPAD) * 2u + (uint32_t)lhi * 16u;
    const uint32_t boff = (uint32_t)((wn * 64 + l7 + lhi * 8) * KPAD) * 2u + (uint32_t)l8k * 16u;

    for (int c = 0; c < niter; c++) {
        cp_wait2();
        __syncthreads();
        const uint32_t soa = (uint32_t)(c & 3) * A_STAGE;
        const uint32_t sob = (uint32_t)(c & 3) * B_STAGE;

#pragma unroll
        for (int ks = 0; ks < 2; ks++) {
            const uint32_t kso = (uint32_t)ks * 32u;
            uint32_t a0[4], a1[4];
            ldm4(a0, sA + soa + aoff + kso);
            ldm4(a1, sA + soa + aoff + kso + 16u * KPAD * 2u);
#pragma unroll
            for (int p = 0; p < 4; p++) {
                uint32_t bb[4];
                ldm4(bb, sB + sob + boff + kso + (uint32_t)(p * 16 * KPAD) * 2u);
                mma_f16(acc[0][2 * p],     a0, bb[0], bb[1]);
                mma_f16(acc[0][2 * p + 1], a0, bb[2], bb[3]);
                mma_f16(acc[1][2 * p],     a1, bb[0], bb[1]);
                mma_f16(acc[1][2 * p + 1], a1, bb[2], bb[3]);
            }
        }

        if (c + 3 < niter) issue((c + 3) & 3, c + 3);
        cp_commit();
    }

    // ---------------- epilogues ----------------
    if (MODE == 0) {
#pragma unroll
        for (int ti = 0; ti < 2; ti++)
#pragma unroll
            for (int nj = 0; nj < 8; nj++) {
                int r0 = bm + wm * 32 + ti * 16 + lg;
                int cc = bn + wn * 64 + nj * 8 + 2 * lk;
                if (r0 < M) {
                    atomicAdd(&outv[(size_t)r0 * ldc + cc],     acc[ti][nj][0]);
                    atomicAdd(&outv[(size_t)r0 * ldc + cc + 1], acc[ti][nj][1]);
                }
                if (r0 + 8 < M) {
                    atomicAdd(&outv[(size_t)(r0 + 8) * ldc + cc],     acc[ti][nj][2]);
                    atomicAdd(&outv[(size_t)(r0 + 8) * ldc + cc + 1], acc[ti][nj][3]);
                }
            }
        return;
    }

    float vv[16];
#pragma unroll
    for (int nj = 0; nj < 8; nj++)
#pragma unroll
        for (int u = 0; u < 2; u++)
            vv[nj * 2 + u] = __ldg(&aux2[bn + wn * 64 + nj * 8 + 2 * lk + u]);

    if (MODE == 1) {
        const int b = bm >> 9;
        float p1v[16];
#pragma unroll
        for (int nj = 0; nj < 8; nj++)
#pragma unroll
            for (int u = 0; u < 2; u++)
                p1v[nj * 2 + u] = __ldg(&aux1[(size_t)b * H_ + bn + wn * 64 + nj * 8 + 2 * lk + u]);
#pragma unroll
        for (int ti = 0; ti < 2; ti++)
#pragma unroll
            for (int half = 0; half < 2; half++) {
                int r = bm + wm * 32 + ti * 16 + lg + half * 8;
                float part = 0.f;
#pragma unroll
                for (int nj = 0; nj < 8; nj++) {
                    part += vv[nj * 2]     * tanh_fast(acc[ti][nj][half * 2]     + p1v[nj * 2]);
                    part += vv[nj * 2 + 1] * tanh_fast(acc[ti][nj][half * 2 + 1] + p1v[nj * 2 + 1]);
                }
                part += __shfl_xor_sync(0xFFFFFFFFu, part, 1);
                part += __shfl_xor_sync(0xFFFFFFFFu, part, 2);
                if (lk == 0) atomicAdd(&outv[r], part);
            }
    } else {
#pragma unroll
        for (int ti = 0; ti < 2; ti++)
#pragma unroll
            for (int half = 0; half < 2; half++) {
                int r = bm + wm * 32 + ti * 16 + lg + half * 8;
                int b = r >> 6;
                const float* q1 = aux1 + (size_t)b * H_;
                float part = 0.f;
#pragma unroll
                for (int nj = 0; nj < 8; nj++) {
                    int n = bn + wn * 64 + nj * 8 + 2 * lk;
                    part += vv[nj * 2]     * tanh_fast(acc[ti][nj][half * 2]     + __ldg(&q1[n]));
                    part += vv[nj * 2 + 1] * tanh_fast(acc[ti][nj][half * 2 + 1] + __ldg(&q1[n + 1]));
                }
                part += __shfl_xor_sync(0xFFFFFFFFu, part, 1);
                part += __shfl_xor_sync(0xFFFFFFFFu, part, 2);
                if (lk == 0) atomicAdd(&outv[(size_t)b * OT_ + OPC_ + (r & 63)], part);
            }
    }
}

// ---------------- fused prep / epilogue helpers --------------------------------
__global__ void fill_mega_k(
    float* gAB, const float* bA, const float* bB,
    float* gCD, const float* bC, const float* bD,
    float* P1, const float* bE, float* Q1, const float* bF,
    float* z1, int n1, float* z2, int n2, float* z3, int n3)
{
    const int BH = B_ * H_;
    const int BH2 = B_ * 2 * H_;
    int i = blockIdx.x * blockDim.x + threadIdx.x;
    if (i < BH2) { int h = i % (2 * H_); gAB[i] = (h < H_) ? bA[h] : bB[h - H_]; return; }
    i -= BH2;
    if (i < BH2) { int h = i % (2 * H_); gCD[i] = (h < H_) ? bC[h] : bD[h - H_]; return; }
    i -= BH2;
    if (i < BH) { P1[i] = bE[i % H_]; return; }
    i -= BH;
    if (i < BH) { Q1[i] = bF[i % H_]; return; }
    i -= BH;
    if (i < n1) { z1[i] = 0.f; return; }
    i -= n1;
    if (i < n2) { z2[i] = 0.f; return; }
    i -= n2;
    if (i < n3) z3[i] = 0.f;
}

__global__ void cvt_h_k(const float* __restrict__ src, __half* __restrict__ dst, int n4)
{
    int i = blockIdx.x * blockDim.x + threadIdx.x;
    if (i >= n4) return;
    float4 v = ((const float4*)src)[i];
    ((__half2*)dst)[2 * i]     = __floats2half2_rn(v.x, v.y);
    ((__half2*)dst)[2 * i + 1] = __floats2half2_rn(v.z, v.w);
}

// current/left -> curH, lcH
__global__ void prep_cur_k(const float* __restrict__ current, const float* __restrict__ left,
                           __half* __restrict__ curH, __half* __restrict__ lcH)
{
    int i = blockIdx.x * blockDim.x + threadIdx.x;
    if (i >= B_ * H_) return;
    int b = i / H_, h = i % H_;
    float c = current[i], l = left[i];
    curH[i] = __float2half_rn(c);
    lcH[(size_t)b * 2 * H_ + h]      = __float2half_rn(l);
    lcH[(size_t)b * 2 * H_ + H_ + h] = __float2half_rn(c);
}

// opc/var -> out_emb (fp32) + opcH/varH (fp16), single pass
__global__ void prep_emb_k(const float* __restrict__ opc, const float* __restrict__ var,
                           float* __restrict__ out_emb,
                           __half* __restrict__ opcH, __half* __restrict__ varH)
{
    size_t i = (size_t)blockIdx.x * blockDim.x + threadIdx.x;   // float4 units
    const size_t total = (size_t)B_ * OT_ * (H_ / 4);
    if (i >= total) return;
    int h4 = (int)(i % (H_ / 4));
    size_t bo = i / (H_ / 4);
    int o = (int)(bo & 127);
    int b = (int)(bo >> 7);
    float4 v;
    if (o < OPC_) {
        size_t si = (size_t)o * (H_ / 4) + h4;
        v = ((const float4*)opc)[si];
        if (b == 0) {
            ((__half2*)opcH)[2 * si]     = __floats2half2_rn(v.x, v.y);
            ((__half2*)opcH)[2 * si + 1] = __floats2half2_rn(v.z, v.w);
        }
    } else {
        size_t si = ((size_t)b * S2_ + (o - OPC_)) * (H_ / 4) + h4;
        v = ((const float4*)var)[si];
        ((__half2*)varH)[2 * si]     = __floats2half2_rn(v.x, v.y);
        ((__half2*)varH)[2 * si + 1] = __floats2half2_rn(v.z, v.w);
    }
    ((float4*)out_emb)[i] = v;
}

// batched 768x768 transposes -> fp16
__global__ void transpose5h_k(const float* s0, __half* d0, const float* s1, __half* d1,
                              const float* s2, __half* d2, const float* s3, __half* d3,
                              const float* s4, __half* d4)
{
    __shared__ float t[32][33];
    const float* src; __half* dst;
    switch (blockIdx.z) {
        case 0: src = s0; dst = d0; break;
        case 1: src = s1; dst = d1; break;
        case 2: src = s2; dst = d2; break;
        case 3: src = s3; dst = d3; break;
        default: src = s4; dst = d4; break;
    }
    int bx = blockIdx.x * 32, by = blockIdx.y * 32;
    int x = threadIdx.x, y = threadIdx.y;
#pragma unroll
    for (int i = 0; i < 32; i += 8)
        t[y + i][x] = src[(size_t)(by + y + i) * H_ + bx + x];
    __syncthreads();
#pragma unroll
    for (int i = 0; i < 32; i += 8)
        dst[(size_t)(bx + y + i) * H_ + by + x] = __float2half_rn(t[x][y + i]);
}

// batched [1536][768] transposes -> fp16 [768 n][1536 k]
__global__ void transpose3h_k(const float* s0, __half* d0, const float* s1, __half* d1,
                              const float* s2, __half* d2)
{
    __shared__ float t[32][33];
    const float* src; __half* dst;
    switch (blockIdx.z) {
        case 0: src = s0; dst = d0; break;
        case 1: src = s1; dst = d1; break;
        default: src = s2; dst = d2; break;
    }
    int bx = blockIdx.x * 32, by = blockIdx.y * 32;   // grid (24, 48)
    int x = threadIdx.x, y = threadIdx.y;
#pragma unroll
    for (int i = 0; i < 32; i += 8)
        t[y + i][x] = src[(size_t)(by + y + i) * H_ + bx + x];
    __syncthreads();
#pragma unroll
    for (int i = 0; i < 32; i += 8)
        dst[(size_t)(bx + y + i) * (2 * H_) + by + x] = __float2half_rn(t[x][y + i]);
}

// gates -> node (fp32 + fp16 + output copy + lower half of leafH)
__global__ void combine_node_k(const int* __restrict__ has_left,
                               float* __restrict__ out_node)
{
    int i = blockIdx.x * blockDim.x + threadIdx.x;
    if (i >= B_ * H_) return;
    int b = i / H_, h = i % H_;
    size_t base = (size_t)b * 2 * H_ + h;
    float v = has_left[b] ? ftanh(g_gCD[base]) * fsig(g_gCD[base + H_])
                          : ftanh(g_gAB[base]) * fsig(g_gAB[base + H_]);
    g_node[i] = v;
    __half hv = __float2half_rn(v);
    g_nodeH[i] = hv;
    g_leafH[base] = hv;
    out_node[i] = v;
}

// fused softmax (over S1) + context (attn @ encH); writes ctx copies and
// the upper half of leafH. block = 768 threads, grid = B_.
__global__ __launch_bounds__(768) void softmax_context_k(
    const int* __restrict__ smask, const __half* __restrict__ encH,
    float* __restrict__ out_ctx)
{
    __shared__ float attn[S1_];
    __shared__ float wred[16];
    const int b = blockIdx.x, t = threadIdx.x;
    const int lane = t & 31, w = t >> 5;

    float x = 0.f;
    if (t < S1_)
        x = smask[(size_t)b * S1_ + t] ? NEGV : g_eng[(size_t)b * S1_ + t];

    if (t < S1_) {
        float m = x;
#pragma unroll
        for (int o = 16; o; o >>= 1) m = fmaxf(m, __shfl_xor_sync(0xFFFFFFFFu, m, o));
        if (lane == 0) wred[w] = m;
    }
    __syncthreads();
    if (t == 0) {
        float m = wred[0];
#pragma unroll
        for (int k = 1; k < 16; k++) m = fmaxf(m, wred[k]);
        wred[0] = m;
    }
    __syncthreads();
    const float mx = wred[0];
    __syncthreads();

    float e = 0.f;
    if (t < S1_) {
        e = __expf(x - mx);
        float s = e;
#pragma unroll
        for (int o = 16; o; o >>= 1) s += __shfl_xor_sync(0xFFFFFFFFu, s, o);
        if (lane == 0) wred[w] = s;
    }
    __syncthreads();
    if (t == 0) {
        float s = wred[0];
#pragma unroll
        for (int k = 1; k < 16; k++) s += wred[k];
        wred[0] = s;
    }
    __syncthreads();
    if (t < S1_) attn[t] = e * __fdividef(1.f, wred[0]);
    __syncthreads();

    const __half* ep = encH + (size_t)b * S1_ * H_ + t;
    float acc = 0.f;
#pragma unroll 8
    for (int s = 0; s < S1_; s++)
        acc = fmaf(attn[s], __half2float(ep[(size_t)s * H_]), acc);
    size_t oi = (size_t)b * H_ + t;
    g_ctx[oi] = acc;
    out_ctx[oi] = acc;
    g_leafH[(size_t)b * 2 * H_ + H_ + t] = __float2half_rn(acc);
}

__global__ void finalize_score_k(const float* __restrict__ vsc,
                                 const int* __restrict__ cmask,
                                 float* __restrict__ score)
{
    int idx = (blockIdx.x * blockDim.x + threadIdx.x) >> 5;
    if (idx >= B_ * OT_) return;
    int lane = threadIdx.x & 31;
    int b = idx >> 7, o = idx & 127;
    if (cmask[idx]) {
        if (lane == 0) score[idx] = NEGV;
        return;
    }
    if (o >= OPC_) return;
    const float* q1 = g_Q1 + (size_t)b * H_;
    const float* q2 = g_Q2c + (size_t)o * H_;
    float acc = 0.f;
    for (int h = lane; h < H_; h += 32)
        acc += vsc[h] * ftanh(q1[h] + q2[h]);
#pragma unroll
    for (int off = 16; off; off >>= 1) acc += __shfl_xor_sync(0xFFFFFFFFu, acc, off);
    if (lane == 0) score[idx] = acc;
}

// ---------------- launch -------------------------------------------------------
extern "C" void kernel_launch(void* const* d_in, const int* in_sizes, int n_in,
                              void* d_out, int out_size)
{
    (void)in_sizes; (void)n_in; (void)out_size;
    const float* current = (const float*)d_in[0];
    const float* left    = (const float*)d_in[1];
    const float* enc     = (const float*)d_in[2];
    const float* var     = (const float*)d_in[3];
    const float* opc     = (const float*)d_in[4];
    const float* W_l     = (const float*)d_in[5];
    const float* b_l     = (const float*)d_in[6];
    const float* W_lg    = (const float*)d_in[7];
    const float* b_lg    = (const float*)d_in[8];
    const float* W_r     = (const float*)d_in[9];
    const float* b_r     = (const float*)d_in[10];
    const float* W_rg    = (const float*)d_in[11];
    const float* b_rg    = (const float*)d_in[12];
    const float* W_attn  = (const float*)d_in[13];
    const float* b_attn  = (const float*)d_in[14];
    const float* v_attn  = (const float*)d_in[15];
    const float* W_score = (const float*)d_in[16];
    const float* b_score = (const float*)d_in[17];
    const float* v_score = (const float*)d_in[18];
    const int*   has_left = (const int*)d_in[19];
    const int*   smask    = (const int*)d_in[20];
    const int*   cmask    = (const int*)d_in[21];

    float *gAB, *gCD, *node, *P1, *eng, *ctx, *Q1, *Q2c;
    __half *encH, *varH, *curH, *opcH, *lcH, *nodeH, *leafH;
    __half *WtLLG, *WtRRG, *WtA1, *WtA2, *WtS3, *WtS12;
    cudaGetSymbolAddress((void**)&gAB,  g_gAB);
    cudaGetSymbolAddress((void**)&gCD,  g_gCD);
    cudaGetSymbolAddress((void**)&node, g_node);
    cudaGetSymbolAddress((void**)&P1,   g_P1);
    cudaGetSymbolAddress((void**)&eng,  g_eng);
    cudaGetSymbolAddress((void**)&ctx,  g_ctx);
    cudaGetSymbolAddress((void**)&Q1,   g_Q1);
    cudaGetSymbolAddress((void**)&Q2c,  g_Q2c);
    cudaGetSymbolAddress((void**)&encH, g_encH);
    cudaGetSymbolAddress((void**)&varH, g_varH);
    cudaGetSymbolAddress((void**)&curH, g_curH);
    cudaGetSymbolAddress((void**)&opcH, g_opcH);
    cudaGetSymbolAddress((void**)&lcH,  g_lcH);
    cudaGetSymbolAddress((void**)&nodeH, g_nodeH);
    cudaGetSymbolAddress((void**)&leafH, g_leafH);
    cudaGetSymbolAddress((void**)&WtLLG, g_WtLLG);
    cudaGetSymbolAddress((void**)&WtRRG, g_WtRRG);
    cudaGetSymbolAddress((void**)&WtA1, g_WtA1);
    cudaGetSymbolAddress((void**)&WtA2, g_WtA2);
    cudaGetSymbolAddress((void**)&WtS3, g_WtS3);
    cudaGetSymbolAddress((void**)&WtS12, g_WtS12);

    float* out       = (float*)d_out;
    float* out_score = out;
    float* out_node  = out_score + B_ * OT_;
    float* out_ctx   = out_node + B_ * H_;
    float* out_emb   = out_ctx + B_ * H_;

    const int BH = B_ * H_;
    const int TPB = 256;

    cudaFuncSetAttribute(mma_k<0>, cudaFuncAttributeMaxDynamicSharedMemorySize, SMEM_MMA);
    cudaFuncSetAttribute(mma_k<1>, cudaFuncAttributeMaxDynamicSharedMemorySize, SMEM_MMA);
    cudaFuncSetAttribute(mma_k<2>, cudaFuncAttributeMaxDynamicSharedMemorySize, SMEM_MMA);

    // --- fills + conversions + transposes (independent) ---
    {
        int total = 2 * (B_ * 2 * H_) + 2 * BH + B_ * S1_ + B_ * OT_ + OPC_ * H_;
        fill_mega_k<<<(total + TPB - 1) / TPB, TPB>>>(
            gAB, b_l, b_lg, gCD, b_r, b_rg, P1, b_attn, Q1, b_score,
            eng, B_ * S1_, out_score, B_ * OT_, Q2c, OPC_ * H_);
    }
    prep_cur_k<<<(BH + TPB - 1) / TPB, TPB>>>(current, left, curH, lcH);
    {
        size_t total4 = (size_t)B_ * OT_ * (H_ / 4);
        prep_emb_k<<<(unsigned)((total4 + TPB - 1) / TPB), TPB>>>(opc, var, out_emb, opcH, varH);
    }
    {
        int n4 = B_ * S1_ * (H_ / 4);
        cvt_h_k<<<(n4 + TPB - 1) / TPB, TPB>>>(enc, encH, n4);
    }
    transpose5h_k<<<dim3(24, 24, 5), dim3(32, 8)>>>(
        W_l, WtLLG, W_lg, WtLLG + (size_t)H_ * H_,
        W_attn, WtA1, W_attn + (size_t)H_ * H_, WtA2,
        W_score + (size_t)2 * H_ * H_, WtS3);
    transpose3h_k<<<dim3(24, 48, 3), dim3(32, 8)>>>(
        W_r, WtRRG, W_rg, WtRRG + (size_t)H_ * 2 * H_, W_score, WtS12);

    // --- node: two merged gate GEMMs ---
    mma_k<0><<<dim3(6, 2, 6),  512, SMEM_MMA>>>(curH, WtLLG, gAB, nullptr, nullptr,
                                                B_, H_, 4, 2 * H_);
    mma_k<0><<<dim3(6, 2, 12), 512, SMEM_MMA>>>(lcH, WtRRG, gCD, nullptr, nullptr,
                                                B_, 2 * H_, 4, 2 * H_);
    combine_node_k<<<(BH + TPB - 1) / TPB, TPB>>>(has_left, out_node);

    // --- attention ---
    mma_k<0><<<dim3(3, 2, 6), 512, SMEM_MMA>>>(nodeH, WtA1, P1, nullptr, nullptr,
                                               B_, H_, 4, H_);
    mma_k<1><<<dim3(3, (B_ * S1_) / 128, 1), 512, SMEM_MMA>>>(encH, WtA2, eng, P1, v_attn,
                                                              B_ * S1_, H_, 24, 0);
    softmax_context_k<<<B_, 768>>>(smask, encH, out_ctx);

    // --- leaf score ---
    mma_k<0><<<dim3(3, 2, 12), 512, SMEM_MMA>>>(leafH, WtS12, Q1, nullptr, nullptr,
                                                B_, 2 * H_, 4, H_);
    mma_k<0><<<dim3(3, 1, 6),  512, SMEM_MMA>>>(opcH, WtS3, Q2c, nullptr, nullptr,
                                                OPC_, H_, 4, H_);
    mma_k<2><<<dim3(3, (B_ * S2_) / 128, 1), 512, SMEM_MMA>>>(varH, WtS3, out_score, Q1, v_score,
                                                              B_ * S2_, H_, 24, 0);
    finalize_score_k<<<(B_ * OT_ * 32 + TPB - 1) / TPB, TPB>>>(v_score, cmask, out_score);
}

// round 13
// speedup vs baseline: 1.1948x; 1.0055x over previous
#include <cuda_runtime.h>
#include <cuda_fp16.h>
#include <math.h>
#include <stdint.h>

#define B_   256
#define S1_  512
#define S2_  64
#define H_   768
#define OPC_ 64
#define OT_  128
#define NEGV (-1e12f)

// ---------------- scratch (device globals) ----------------------------------
__device__ float g_gAB [B_ * 2 * H_];     // [B][1536]: gA | gB
__device__ float g_gCD [B_ * 2 * H_];     // [B][1536]: gC | gD
__device__ float g_node[B_ * H_];
__device__ float g_P1  [B_ * H_];
__device__ float g_eng [B_ * S1_];
__device__ float g_ctx [B_ * H_];
__device__ float g_Q1  [B_ * H_];
__device__ float g_Q2c [OPC_ * H_];
// fp16 activations
__device__ __half g_encH [(size_t)B_ * S1_ * H_];
__device__ __half g_varH [(size_t)B_ * S2_ * H_];
__device__ __half g_opcH [OPC_ * H_];
__device__ __half g_lcH  [B_ * 2 * H_];   // [left | current]
__device__ __half g_nodeH[B_ * H_];
__device__ __half g_leafH[B_ * 2 * H_];
// fp16 transposed weights: Wt[n][k] = W[k][n]
__device__ __half g_WtLLG [2 * H_ * H_];
__device__ __half g_WtRRG [2 * H_ * 2 * H_];
__device__ __half g_WtA1  [H_ * H_];
__device__ __half g_WtA2  [H_ * H_];
__device__ __half g_WtS3  [H_ * H_];
__device__ __half g_WtS12 [H_ * 2 * H_];

// ---------------- helpers ------------------------------------------------------
__device__ __forceinline__ float tanh_fast(float x) {
    float y; asm("tanh.approx.f32 %0, %1;" : "=f"(y) : "f"(x)); return y;
}
__device__ __forceinline__ float ftanh(float x) {
    float ax = fabsf(x);
    float e  = __expf(2.0f * ax);
    float r  = 1.0f - __fdividef(2.0f, e + 1.0f);
    return copysignf(r, x);
}
__device__ __forceinline__ float fsig(float x) {
    return __fdividef(1.0f, 1.0f + __expf(-x));
}
__device__ __forceinline__ uint32_t smem_u32(const void* p) {
    uint32_t a;
    asm("{ .reg .u64 t; cvta.to.shared.u64 t, %1; cvt.u32.u64 %0, t; }" : "=r"(a) : "l"(p));
    return a;
}
__device__ __forceinline__ void cp16(uint32_t saddr, const __half* g, uint32_t sz) {
    asm volatile("cp.async.cg.shared.global [%0], [%1], 16, %2;"
                 :: "r"(saddr), "l"(g), "r"(sz) : "memory");
}
__device__ __forceinline__ void cp_commit() {
    asm volatile("cp.async.commit_group;" ::: "memory");
}
__device__ __forceinline__ void cp_wait2() {
    asm volatile("cp.async.wait_group 2;" ::: "memory");
}
__device__ __forceinline__ void ldm4(uint32_t r[4], uint32_t addr) {
    asm volatile("ldmatrix.sync.aligned.m8n8.x4.shared.b16 {%0,%1,%2,%3}, [%4];"
                 : "=r"(r[0]), "=r"(r[1]), "=r"(r[2]), "=r"(r[3]) : "r"(addr));
}
__device__ __forceinline__ void mma_f16(float c[4], const uint32_t a[4],
                                        uint32_t b0, uint32_t b1) {
    asm volatile(
        "mma.sync.aligned.m16n8k16.row.col.f32.f16.f16.f32 "
        "{%0,%1,%2,%3}, {%4,%5,%6,%7}, {%8,%9}, {%0,%1,%2,%3};"
        : "+f"(c[0]), "+f"(c[1]), "+f"(c[2]), "+f"(c[3])
        : "r"(a[0]), "r"(a[1]), "r"(a[2]), "r"(a[3]), "r"(b0), "r"(b1));
}

// ---------------- pipelined fp16 MMA kernel (cp.async 4-stage, BK=32) ----------
// C-tile 128m x 256n, 512 thr = 16 warps (4 m-bands x 4 n-groups), warp 32x64.
// A row-major [M,lda] fp16; Wt row-major [N][K] fp16. SMEM rows padded to 40 halfs.
// MODE 0: split-K (blockIdx.z), atomicAdd into C[M,ldc] (bias preloaded).
// MODE 1: energy out[r] += sum_n v[n]*tanh(aux1[bm>>9, n] + acc)
// MODE 2: score  out[(r>>6)*128+64+(r&63)] += sum_n v[n]*tanh(aux1[r>>6, n] + acc)
#define KPAD 40
#define A_STAGE (128 * KPAD * 2)            // 10240 B
#define B_STAGE (256 * KPAD * 2)            // 20480 B
#define SMEM_MMA (4 * (A_STAGE + B_STAGE))  // 122880 B

template <int MODE>
__global__ __launch_bounds__(512, 1) void mma_k(
    const __half* __restrict__ A, const __half* __restrict__ Wt,
    float* __restrict__ outv,
    const float* __restrict__ aux1, const float* __restrict__ aux2,
    int M, int K, int lda, int niter, int ldc)
{
    extern __shared__ __align__(16) __half smh[];
    const uint32_t sA = smem_u32(smh);
    const uint32_t sB = sA + 4 * A_STAGE;

    const int tid  = threadIdx.x;
    const int lane = tid & 31;
    const int wid  = tid >> 5;
    const int wm   = wid & 3;
    const int wn   = wid >> 2;
    const int bm   = blockIdx.y * 128;
    const int bn   = blockIdx.x * 256;
    const int kst  = blockIdx.z * niter * 32;

    float acc[2][8][4];
#pragma unroll
    for (int i = 0; i < 2; i++)
#pragma unroll
        for (int j = 0; j < 8; j++)
#pragma unroll
            for (int q = 0; q < 4; q++) acc[i][j][q] = 0.f;

    // loaders: A 128 rows x 64B (1 cp16/thread); B 256 rows x 64B (2 cp16/thread)
    const int l_row = tid >> 2;
    const int lq    = tid & 3;
    const uint32_t a_sz = ((bm + l_row) < M) ? 16u : 0u;
    const __half* Ap  = A  + (size_t)(bm + l_row) * lda + kst + lq * 8;
    const __half* Bp0 = Wt + (size_t)(bn + l_row) * K + kst + lq * 8;
    const __half* Bp1 = Wt + (size_t)(bn + 128 + l_row) * K + kst + lq * 8;
    const uint32_t dA  = sA + (uint32_t)(l_row * KPAD + lq * 8) * 2u;
    const uint32_t dB0 = sB + (uint32_t)(l_row * KPAD + lq * 8) * 2u;
    const uint32_t dB1 = sB + (uint32_t)((128 + l_row) * KPAD + lq * 8) * 2u;

    auto issue = [&](int stage, int kt) {
        cp16(dA  + (uint32_t)stage * A_STAGE, Ap  + (size_t)kt * 32, a_sz);
        cp16(dB0 + (uint32_t)stage * B_STAGE, Bp0 + (size_t)kt * 32, 16u);
        cp16(dB1 + (uint32_t)stage * B_STAGE, Bp1 + (size_t)kt * 32, 16u);
    };

#pragma unroll
    for (int s = 0; s < 3; s++) {
        if (s < niter) issue(s, s);
        cp_commit();
    }

    const int lk = lane & 3;
    const int lg = lane >> 2;
    const int l15 = lane & 15;
    const int lhi = lane >> 4;
    const int l8k = (lane >> 3) & 1;
    const int l7  = lane & 7;

    const uint32_t aoff = (uint32_t)((wm * 32 + l15) * KPAD) * 2u + (uint32_t)lhi * 16u;
    const uint32_t boff = (uint32_t)((wn * 64 + l7 + lhi * 8) * KPAD) * 2u + (uint32_t)l8k * 16u;

    for (int c = 0; c < niter; c++) {
        cp_wait2();
        __syncthreads();
        const uint32_t soa = (uint32_t)(c & 3) * A_STAGE;
        const uint32_t sob = (uint32_t)(c & 3) * B_STAGE;

#pragma unroll
        for (int ks = 0; ks < 2; ks++) {
            const uint32_t kso = (uint32_t)ks * 32u;
            uint32_t a0[4], a1[4];
            ldm4(a0, sA + soa + aoff + kso);
            ldm4(a1, sA + soa + aoff + kso + 16u * KPAD * 2u);
#pragma unroll
            for (int p = 0; p < 4; p++) {
                uint32_t bb[4];
                ldm4(bb, sB + sob + boff + kso + (uint32_t)(p * 16 * KPAD) * 2u);
                mma_f16(acc[0][2 * p],     a0, bb[0], bb[1]);
                mma_f16(acc[0][2 * p + 1], a0, bb[2], bb[3]);
                mma_f16(acc[1][2 * p],     a1, bb[0], bb[1]);
                mma_f16(acc[1][2 * p + 1], a1, bb[2], bb[3]);
            }
        }

        if (c + 3 < niter) issue((c + 3) & 3, c + 3);
        cp_commit();
    }

    // ---------------- epilogues ----------------
    if (MODE == 0) {
#pragma unroll
        for (int ti = 0; ti < 2; ti++)
#pragma unroll
            for (int nj = 0; nj < 8; nj++) {
                int r0 = bm + wm * 32 + ti * 16 + lg;
                int cc = bn + wn * 64 + nj * 8 + 2 * lk;
                if (r0 < M) {
                    atomicAdd(&outv[(size_t)r0 * ldc + cc],     acc[ti][nj][0]);
                    atomicAdd(&outv[(size_t)r0 * ldc + cc + 1], acc[ti][nj][1]);
                }
                if (r0 + 8 < M) {
                    atomicAdd(&outv[(size_t)(r0 + 8) * ldc + cc],     acc[ti][nj][2]);
                    atomicAdd(&outv[(size_t)(r0 + 8) * ldc + cc + 1], acc[ti][nj][3]);
                }
            }
        return;
    }

    float vv[16];
#pragma unroll
    for (int nj = 0; nj < 8; nj++)
#pragma unroll
        for (int u = 0; u < 2; u++)
            vv[nj * 2 + u] = __ldg(&aux2[bn + wn * 64 + nj * 8 + 2 * lk + u]);

    if (MODE == 1) {
        const int b = bm >> 9;
        float p1v[16];
#pragma unroll
        for (int nj = 0; nj < 8; nj++)
#pragma unroll
            for (int u = 0; u < 2; u++)
                p1v[nj * 2 + u] = __ldg(&aux1[(size_t)b * H_ + bn + wn * 64 + nj * 8 + 2 * lk + u]);
#pragma unroll
        for (int ti = 0; ti < 2; ti++)
#pragma unroll
            for (int half = 0; half < 2; half++) {
                int r = bm + wm * 32 + ti * 16 + lg + half * 8;
                float part = 0.f;
#pragma unroll
                for (int nj = 0; nj < 8; nj++) {
                    part += vv[nj * 2]     * tanh_fast(acc[ti][nj][half * 2]     + p1v[nj * 2]);
                    part += vv[nj * 2 + 1] * tanh_fast(acc[ti][nj][half * 2 + 1] + p1v[nj * 2 + 1]);
                }
                part += __shfl_xor_sync(0xFFFFFFFFu, part, 1);
                part += __shfl_xor_sync(0xFFFFFFFFu, part, 2);
                if (lk == 0) atomicAdd(&outv[r], part);
            }
    } else {
#pragma unroll
        for (int ti = 0; ti < 2; ti++)
#pragma unroll
            for (int half = 0; half < 2; half++) {
                int r = bm + wm * 32 + ti * 16 + lg + half * 8;
                int b = r >> 6;
                const float* q1 = aux1 + (size_t)b * H_;
                float part = 0.f;
#pragma unroll
                for (int nj = 0; nj < 8; nj++) {
                    int n = bn + wn * 64 + nj * 8 + 2 * lk;
                    part += vv[nj * 2]     * tanh_fast(acc[ti][nj][half * 2]     + __ldg(&q1[n]));
                    part += vv[nj * 2 + 1] * tanh_fast(acc[ti][nj][half * 2 + 1] + __ldg(&q1[n + 1]));
                }
                part += __shfl_xor_sync(0xFFFFFFFFu, part, 1);
                part += __shfl_xor_sync(0xFFFFFFFFu, part, 2);
                if (lk == 0) atomicAdd(&outv[(size_t)b * OT_ + OPC_ + (r & 63)], part);
            }
    }
}

// ---------------- fused prep / epilogue helpers --------------------------------
// bias fills + zero fills + left/current -> lcH (all independent elementwise)
__global__ void fill_mega_k(
    float* gAB, const float* bA, const float* bB,
    float* gCD, const float* bC, const float* bD,
    float* P1, const float* bE, float* Q1, const float* bF,
    float* z1, int n1, float* z2, int n2, float* z3, int n3,
    const float* current, const float* left, __half* lcH)
{
    const int BH = B_ * H_;
    const int BH2 = B_ * 2 * H_;
    int i = blockIdx.x * blockDim.x + threadIdx.x;
    if (i < BH2) { int h = i % (2 * H_); gAB[i] = (h < H_) ? bA[h] : bB[h - H_]; return; }
    i -= BH2;
    if (i < BH2) { int h = i % (2 * H_); gCD[i] = (h < H_) ? bC[h] : bD[h - H_]; return; }
    i -= BH2;
    if (i < BH) { P1[i] = bE[i % H_]; return; }
    i -= BH;
    if (i < BH) { Q1[i] = bF[i % H_]; return; }
    i -= BH;
    if (i < n1) { z1[i] = 0.f; return; }
    i -= n1;
    if (i < n2) { z2[i] = 0.f; return; }
    i -= n2;
    if (i < n3) { z3[i] = 0.f; return; }
    i -= n3;
    if (i < BH) {
        int b = i / H_, h = i % H_;
        lcH[(size_t)b * 2 * H_ + h]      = __float2half_rn(left[i]);
        lcH[(size_t)b * 2 * H_ + H_ + h] = __float2half_rn(current[i]);
    }
}

__global__ void cvt_h_k(const float* __restrict__ src, __half* __restrict__ dst, int n4)
{
    int i = blockIdx.x * blockDim.x + threadIdx.x;
    if (i >= n4) return;
    float4 v = ((const float4*)src)[i];
    ((__half2*)dst)[2 * i]     = __floats2half2_rn(v.x, v.y);
    ((__half2*)dst)[2 * i + 1] = __floats2half2_rn(v.z, v.w);
}

// opc/var -> out_emb (fp32) + opcH/varH (fp16), single pass
__global__ void prep_emb_k(const float* __restrict__ opc, const float* __restrict__ var,
                           float* __restrict__ out_emb,
                           __half* __restrict__ opcH, __half* __restrict__ varH)
{
    size_t i = (size_t)blockIdx.x * blockDim.x + threadIdx.x;   // float4 units
    const size_t total = (size_t)B_ * OT_ * (H_ / 4);
    if (i >= total) return;
    int h4 = (int)(i % (H_ / 4));
    size_t bo = i / (H_ / 4);
    int o = (int)(bo & 127);
    int b = (int)(bo >> 7);
    float4 v;
    if (o < OPC_) {
        size_t si = (size_t)o * (H_ / 4) + h4;
        v = ((const float4*)opc)[si];
        if (b == 0) {
            ((__half2*)opcH)[2 * si]     = __floats2half2_rn(v.x, v.y);
            ((__half2*)opcH)[2 * si + 1] = __floats2half2_rn(v.z, v.w);
        }
    } else {
        size_t si = ((size_t)b * S2_ + (o - OPC_)) * (H_ / 4) + h4;
        v = ((const float4*)var)[si];
        ((__half2*)varH)[2 * si]     = __floats2half2_rn(v.x, v.y);
        ((__half2*)varH)[2 * si + 1] = __floats2half2_rn(v.z, v.w);
    }
    ((float4*)out_emb)[i] = v;
}

// batched 768x768 transposes -> fp16
__global__ void transpose5h_k(const float* s0, __half* d0, const float* s1, __half* d1,
                              const float* s2, __half* d2, const float* s3, __half* d3,
                              const float* s4, __half* d4)
{
    __shared__ float t[32][33];
    const float* src; __half* dst;
    switch (blockIdx.z) {
        case 0: src = s0; dst = d0; break;
        case 1: src = s1; dst = d1; break;
        case 2: src = s2; dst = d2; break;
        case 3: src = s3; dst = d3; break;
        default: src = s4; dst = d4; break;
    }
    int bx = blockIdx.x * 32, by = blockIdx.y * 32;
    int x = threadIdx.x, y = threadIdx.y;
#pragma unroll
    for (int i = 0; i < 32; i += 8)
        t[y + i][x] = src[(size_t)(by + y + i) * H_ + bx + x];
    __syncthreads();
#pragma unroll
    for (int i = 0; i < 32; i += 8)
        dst[(size_t)(bx + y + i) * H_ + by + x] = __float2half_rn(t[x][y + i]);
}

// batched [1536][768] transposes -> fp16 [768 n][1536 k]
__global__ void transpose3h_k(const float* s0, __half* d0, const float* s1, __half* d1,
                              const float* s2, __half* d2)
{
    __shared__ float t[32][33];
    const float* src; __half* dst;
    switch (blockIdx.z) {
        case 0: src = s0; dst = d0; break;
        case 1: src = s1; dst = d1; break;
        default: src = s2; dst = d2; break;
    }
    int bx = blockIdx.x * 32, by = blockIdx.y * 32;   // grid (24, 48)
    int x = threadIdx.x, y = threadIdx.y;
#pragma unroll
    for (int i = 0; i < 32; i += 8)
        t[y + i][x] = src[(size_t)(by + y + i) * H_ + bx + x];
    __syncthreads();
#pragma unroll
    for (int i = 0; i < 32; i += 8)
        dst[(size_t)(bx + y + i) * (2 * H_) + by + x] = __float2half_rn(t[x][y + i]);
}

// gates -> node (fp32 + fp16 + output copy + lower half of leafH)
__global__ void combine_node_k(const int* __restrict__ has_left,
                               float* __restrict__ out_node)
{
    int i = blockIdx.x * blockDim.x + threadIdx.x;
    if (i >= B_ * H_) return;
    int b = i / H_, h = i % H_;
    size_t base = (size_t)b * 2 * H_ + h;
    float v = has_left[b] ? ftanh(g_gCD[base]) * fsig(g_gCD[base + H_])
                          : ftanh(g_gAB[base]) * fsig(g_gAB[base + H_]);
    g_node[i] = v;
    __half hv = __float2half_rn(v);
    g_nodeH[i] = hv;
    g_leafH[base] = hv;
    out_node[i] = v;
}

// fused softmax (over S1) + context (attn @ encH); writes ctx copies and
// the upper half of leafH. block = 768 threads, grid = B_.
__global__ __launch_bounds__(768) void softmax_context_k(
    const int* __restrict__ smask, const __half* __restrict__ encH,
    float* __restrict__ out_ctx)
{
    __shared__ float attn[S1_];
    __shared__ float wred[16];
    const int b = blockIdx.x, t = threadIdx.x;
    const int lane = t & 31, w = t >> 5;

    float x = 0.f;
    if (t < S1_)
        x = smask[(size_t)b * S1_ + t] ? NEGV : g_eng[(size_t)b * S1_ + t];

    if (t < S1_) {
        float m = x;
#pragma unroll
        for (int o = 16; o; o >>= 1) m = fmaxf(m, __shfl_xor_sync(0xFFFFFFFFu, m, o));
        if (lane == 0) wred[w] = m;
    }
    __syncthreads();
    if (t == 0) {
        float m = wred[0];
#pragma unroll
        for (int k = 1; k < 16; k++) m = fmaxf(m, wred[k]);
        wred[0] = m;
    }
    __syncthreads();
    const float mx = wred[0];
    __syncthreads();

    float e = 0.f;
    if (t < S1_) {
        e = __expf(x - mx);
        float s = e;
#pragma unroll
        for (int o = 16; o; o >>= 1) s += __shfl_xor_sync(0xFFFFFFFFu, s, o);
        if (lane == 0) wred[w] = s;
    }
    __syncthreads();
    if (t == 0) {
        float s = wred[0];
#pragma unroll
        for (int k = 1; k < 16; k++) s += wred[k];
        wred[0] = s;
    }
    __syncthreads();
    if (t < S1_) attn[t] = e * __fdividef(1.f, wred[0]);
    __syncthreads();

    const __half* ep = encH + (size_t)b * S1_ * H_ + t;
    float acc = 0.f;
#pragma unroll 8
    for (int s = 0; s < S1_; s++)
        acc = fmaf(attn[s], __half2float(ep[(size_t)s * H_]), acc);
    size_t oi = (size_t)b * H_ + t;
    g_ctx[oi] = acc;
    out_ctx[oi] = acc;
    g_leafH[(size_t)b * 2 * H_ + H_ + t] = __float2half_rn(acc);
}

__global__ void finalize_score_k(const float* __restrict__ vsc,
                                 const int* __restrict__ cmask,
                                 float* __restrict__ score)
{
    int idx = (blockIdx.x * blockDim.x + threadIdx.x) >> 5;
    if (idx >= B_ * OT_) return;
    int lane = threadIdx.x & 31;
    int b = idx >> 7, o = idx & 127;
    if (cmask[idx]) {
        if (lane == 0) score[idx] = NEGV;
        return;
    }
    if (o >= OPC_) return;
    const float* q1 = g_Q1 + (size_t)b * H_;
    const float* q2 = g_Q2c + (size_t)o * H_;
    float acc = 0.f;
    for (int h = lane; h < H_; h += 32)
        acc += vsc[h] * ftanh(q1[h] + q2[h]);
#pragma unroll
    for (int off = 16; off; off >>= 1) acc += __shfl_xor_sync(0xFFFFFFFFu, acc, off);
    if (lane == 0) score[idx] = acc;
}

// ---------------- launch -------------------------------------------------------
extern "C" void kernel_launch(void* const* d_in, const int* in_sizes, int n_in,
                              void* d_out, int out_size)
{
    (void)in_sizes; (void)n_in; (void)out_size;
    const float* current = (const float*)d_in[0];
    const float* left    = (const float*)d_in[1];
    const float* enc     = (const float*)d_in[2];
    const float* var     = (const float*)d_in[3];
    const float* opc     = (const float*)d_in[4];
    const float* W_l     = (const float*)d_in[5];
    const float* b_l     = (const float*)d_in[6];
    const float* W_lg    = (const float*)d_in[7];
    const float* b_lg    = (const float*)d_in[8];
    const float* W_r     = (const float*)d_in[9];
    const float* b_r     = (const float*)d_in[10];
    const float* W_rg    = (const float*)d_in[11];
    const float* b_rg    = (const float*)d_in[12];
    const float* W_attn  = (const float*)d_in[13];
    const float* b_attn  = (const float*)d_in[14];
    const float* v_attn  = (const float*)d_in[15];
    const float* W_score = (const float*)d_in[16];
    const float* b_score = (const float*)d_in[17];
    const float* v_score = (const float*)d_in[18];
    const int*   has_left = (const int*)d_in[19];
    const int*   smask    = (const int*)d_in[20];
    const int*   cmask    = (const int*)d_in[21];

    float *gAB, *gCD, *node, *P1, *eng, *ctx, *Q1, *Q2c;
    __half *encH, *varH, *opcH, *lcH, *nodeH, *leafH;
    __half *WtLLG, *WtRRG, *WtA1, *WtA2, *WtS3, *WtS12;
    cudaGetSymbolAddress((void**)&gAB,  g_gAB);
    cudaGetSymbolAddress((void**)&gCD,  g_gCD);
    cudaGetSymbolAddress((void**)&node, g_node);
    cudaGetSymbolAddress((void**)&P1,   g_P1);
    cudaGetSymbolAddress((void**)&eng,  g_eng);
    cudaGetSymbolAddress((void**)&ctx,  g_ctx);
    cudaGetSymbolAddress((void**)&Q1,   g_Q1);
    cudaGetSymbolAddress((void**)&Q2c,  g_Q2c);
    cudaGetSymbolAddress((void**)&encH, g_encH);
    cudaGetSymbolAddress((void**)&varH, g_varH);
    cudaGetSymbolAddress((void**)&opcH, g_opcH);
    cudaGetSymbolAddress((void**)&lcH,  g_lcH);
    cudaGetSymbolAddress((void**)&nodeH, g_nodeH);
    cudaGetSymbolAddress((void**)&leafH, g_leafH);
    cudaGetSymbolAddress((void**)&WtLLG, g_WtLLG);
    cudaGetSymbolAddress((void**)&WtRRG, g_WtRRG);
    cudaGetSymbolAddress((void**)&WtA1, g_WtA1);
    cudaGetSymbolAddress((void**)&WtA2, g_WtA2);
    cudaGetSymbolAddress((void**)&WtS3, g_WtS3);
    cudaGetSymbolAddress((void**)&WtS12, g_WtS12);

    float* out       = (float*)d_out;
    float* out_score = out;
    float* out_node  = out_score + B_ * OT_;
    float* out_ctx   = out_node + B_ * H_;
    float* out_emb   = out_ctx + B_ * H_;

    const int BH = B_ * H_;
    const int TPB = 256;

    cudaFuncSetAttribute(mma_k<0>, cudaFuncAttributeMaxDynamicSharedMemorySize, SMEM_MMA);
    cudaFuncSetAttribute(mma_k<1>, cudaFuncAttributeMaxDynamicSharedMemorySize, SMEM_MMA);
    cudaFuncSetAttribute(mma_k<2>, cudaFuncAttributeMaxDynamicSharedMemorySize, SMEM_MMA);

    // --- fills + lc conversion + emb/var/opc conversion + enc conversion + transposes
    {
        int total = 2 * (B_ * 2 * H_) + 2 * BH + B_ * S1_ + B_ * OT_ + OPC_ * H_ + BH;
        fill_mega_k<<<(total + TPB - 1) / TPB, TPB>>>(
            gAB, b_l, b_lg, gCD, b_r, b_rg, P1, b_attn, Q1, b_score,
            eng, B_ * S1_, out_score, B_ * OT_, Q2c, OPC_ * H_,
            current, left, lcH);
    }
    {
        size_t total4 = (size_t)B_ * OT_ * (H_ / 4);
        prep_emb_k<<<(unsigned)((total4 + TPB - 1) / TPB), TPB>>>(opc, var, out_emb, opcH, varH);
    }
    {
        int n4 = B_ * S1_ * (H_ / 4);
        cvt_h_k<<<(n4 + TPB - 1) / TPB, TPB>>>(enc, encH, n4);
    }
    transpose5h_k<<<dim3(24, 24, 5), dim3(32, 8)>>>(
        W_l, WtLLG, W_lg, WtLLG + (size_t)H_ * H_,
        W_attn, WtA1, W_attn + (size_t)H_ * H_, WtA2,
        W_score + (size_t)2 * H_ * H_, WtS3);
    transpose3h_k<<<dim3(24, 48, 3), dim3(32, 8)>>>(
        W_r, WtRRG, W_rg, WtRRG + (size_t)H_ * 2 * H_, W_score, WtS12);

    // --- node: two merged gate GEMMs (A = current half / full lc of lcH) ---
    mma_k<0><<<dim3(6, 2, 6),  512, SMEM_MMA>>>(lcH + H_, WtLLG, gAB, nullptr, nullptr,
                                                B_, H_, 2 * H_, 4, 2 * H_);
    mma_k<0><<<dim3(6, 2, 12), 512, SMEM_MMA>>>(lcH, WtRRG, gCD, nullptr, nullptr,
                                                B_, 2 * H_, 2 * H_, 4, 2 * H_);
    combine_node_k<<<(BH + TPB - 1) / TPB, TPB>>>(has_left, out_node);

    // --- attention ---
    mma_k<0><<<dim3(3, 2, 6), 512, SMEM_MMA>>>(nodeH, WtA1, P1, nullptr, nullptr,
                                               B_, H_, H_, 4, H_);
    mma_k<1><<<dim3(3, (B_ * S1_) / 128, 1), 512, SMEM_MMA>>>(encH, WtA2, eng, P1, v_attn,
                                                              B_ * S1_, H_, H_, 24, 0);
    softmax_context_k<<<B_, 768>>>(smask, encH, out_ctx);

    // --- leaf score ---
    mma_k<0><<<dim3(3, 2, 12), 512, SMEM_MMA>>>(leafH, WtS12, Q1, nullptr, nullptr,
                                                B_, 2 * H_, 2 * H_, 4, H_);
    mma_k<0><<<dim3(3, 1, 6),  512, SMEM_MMA>>>(opcH, WtS3, Q2c, nullptr, nullptr,
                                                OPC_, H_, H_, 4, H_);
    mma_k<2><<<dim3(3, (B_ * S2_) / 128, 1), 512, SMEM_MMA>>>(varH, WtS3, out_score, Q1, v_score,
                                                              B_ * S2_, H_, H_, 24, 0);
    finalize_score_k<<<(B_ * OT_ * 32 + TPB - 1) / TPB, TPB>>>(v_score, cmask, out_score);
}

// round 14
// speedup vs baseline: 1.2024x; 1.0064x over previous
#include <cuda_runtime.h>
#include <cuda_fp16.h>
#include <math.h>
#include <stdint.h>

#define B_   256
#define S1_  512
#define S2_  64
#define H_   768
#define OPC_ 64
#define OT_  128
#define NEGV (-1e12f)

// ---------------- scratch (device globals) ----------------------------------
__device__ float g_gAB [B_ * 2 * H_];     // [B][1536]: gA | gB
__device__ float g_gCD [B_ * 2 * H_];     // [B][1536]: gC | gD
__device__ float g_node[B_ * H_];
__device__ float g_P1  [B_ * H_];
__device__ float g_eng [B_ * S1_];
__device__ float g_ctx [B_ * H_];
__device__ float g_Q1  [B_ * H_];
__device__ float g_Q2c [OPC_ * H_];
// fp16 activations
__device__ __half g_encH [(size_t)B_ * S1_ * H_];
__device__ __half g_varH [(size_t)B_ * S2_ * H_];
__device__ __half g_opcH [OPC_ * H_];
__device__ __half g_lcH  [B_ * 2 * H_];   // [left | current]
__device__ __half g_nodeH[B_ * H_];
__device__ __half g_leafH[B_ * 2 * H_];
// fp16 transposed weights: Wt[n][k] = W[k][n]
__device__ __half g_WtLLG [2 * H_ * H_];
__device__ __half g_WtRRG [2 * H_ * 2 * H_];
__device__ __half g_WtA1  [H_ * H_];
__device__ __half g_WtA2  [H_ * H_];
__device__ __half g_WtS3  [H_ * H_];
__device__ __half g_WtS12 [H_ * 2 * H_];

// ---------------- helpers ------------------------------------------------------
__device__ __forceinline__ float tanh_fast(float x) {
    float y; asm("tanh.approx.f32 %0, %1;" : "=f"(y) : "f"(x)); return y;
}
__device__ __forceinline__ float ftanh(float x) {
    float ax = fabsf(x);
    float e  = __expf(2.0f * ax);
    float r  = 1.0f - __fdividef(2.0f, e + 1.0f);
    return copysignf(r, x);
}
__device__ __forceinline__ float fsig(float x) {
    return __fdividef(1.0f, 1.0f + __expf(-x));
}
__device__ __forceinline__ uint32_t smem_u32(const void* p) {
    uint32_t a;
    asm("{ .reg .u64 t; cvta.to.shared.u64 t, %1; cvt.u32.u64 %0, t; }" : "=r"(a) : "l"(p));
    return a;
}
__device__ __forceinline__ void cp16(uint32_t saddr, const __half* g, uint32_t sz) {
    asm volatile("cp.async.cg.shared.global [%0], [%1], 16, %2;"
                 :: "r"(saddr), "l"(g), "r"(sz) : "memory");
}
__device__ __forceinline__ void cp_commit() {
    asm volatile("cp.async.commit_group;" ::: "memory");
}
__device__ __forceinline__ void cp_wait2() {
    asm volatile("cp.async.wait_group 2;" ::: "memory");
}
__device__ __forceinline__ void ldm4(uint32_t r[4], uint32_t addr) {
    asm volatile("ldmatrix.sync.aligned.m8n8.x4.shared.b16 {%0,%1,%2,%3}, [%4];"
                 : "=r"(r[0]), "=r"(r[1]), "=r"(r[2]), "=r"(r[3]) : "r"(addr));
}
__device__ __forceinline__ void mma_f16(float c[4], const uint32_t a[4],
                                        uint32_t b0, uint32_t b1) {
    asm volatile(
        "mma.sync.aligned.m16n8k16.row.col.f32.f16.f16.f32 "
        "{%0,%1,%2,%3}, {%4,%5,%6,%7}, {%8,%9}, {%0,%1,%2,%3};"
        : "+f"(c[0]), "+f"(c[1]), "+f"(c[2]), "+f"(c[3])
        : "r"(a[0]), "r"(a[1]), "r"(a[2]), "r"(a[3]), "r"(b0), "r"(b1));
}

// ---------------- pipelined fp16 MMA kernel (cp.async 4-stage, BK=32) ----------
// C-tile 128m x 256n, 512 thr = 16 warps (4 m-bands x 4 n-groups), warp 32x64.
// A row-major [M,lda] fp16; Wt row-major [N][K] fp16. SMEM rows padded to 40 halfs.
// MODE 0: split-K (blockIdx.z), atomicAdd into C[M,ldc] (bias preloaded).
// MODE 1: energy out[r] += sum_n v[n]*tanh(aux1[bm>>9, n] + acc)
// MODE 2: score  out[(r>>6)*128+64+(r&63)] += sum_n v[n]*tanh(aux1[r>>6, n] + acc)
#define KPAD 40
#define A_STAGE (128 * KPAD * 2)            // 10240 B
#define B_STAGE (256 * KPAD * 2)            // 20480 B
#define SMEM_MMA (4 * (A_STAGE + B_STAGE))  // 122880 B

template <int MODE>
__global__ __launch_bounds__(512, 1) void mma_k(
    const __half* __restrict__ A, const __half* __restrict__ Wt,
    float* __restrict__ outv,
    const float* __restrict__ aux1, const float* __restrict__ aux2,
    int M, int K, int lda, int niter, int ldc)
{
    extern __shared__ __align__(16) __half smh[];
    const uint32_t sA = smem_u32(smh);
    const uint32_t sB = sA + 4 * A_STAGE;

    const int tid  = threadIdx.x;
    const int lane = tid & 31;
    const int wid  = tid >> 5;
    const int wm   = wid & 3;
    const int wn   = wid >> 2;
    const int bm   = blockIdx.y * 128;
    const int bn   = blockIdx.x * 256;
    const int kst  = blockIdx.z * niter * 32;

    float acc[2][8][4];
#pragma unroll
    for (int i = 0; i < 2; i++)
#pragma unroll
        for (int j = 0; j < 8; j++)
#pragma unroll
            for (int q = 0; q < 4; q++) acc[i][j][q] = 0.f;

    // loaders: A 128 rows x 64B (1 cp16/thread); B 256 rows x 64B (2 cp16/thread)
    const int l_row = tid >> 2;
    const int lq    = tid & 3;
    const uint32_t a_sz = ((bm + l_row) < M) ? 16u : 0u;
    const __half* Ap  = A  + (size_t)(bm + l_row) * lda + kst + lq * 8;
    const __half* Bp0 = Wt + (size_t)(bn + l_row) * K + kst + lq * 8;
    const __half* Bp1 = Wt + (size_t)(bn + 128 + l_row) * K + kst + lq * 8;
    const uint32_t dA  = sA + (uint32_t)(l_row * KPAD + lq * 8) * 2u;
    const uint32_t dB0 = sB + (uint32_t)(l_row * KPAD + lq * 8) * 2u;
    const uint32_t dB1 = sB + (uint32_t)((128 + l_row) * KPAD + lq * 8) * 2u;

    auto issue = [&](int stage, int kt) {
        cp16(dA  + (uint32_t)stage * A_STAGE, Ap  + (size_t)kt * 32, a_sz);
        cp16(dB0 + (uint32_t)stage * B_STAGE, Bp0 + (size_t)kt * 32, 16u);
        cp16(dB1 + (uint32_t)stage * B_STAGE, Bp1 + (size_t)kt * 32, 16u);
    };

#pragma unroll
    for (int s = 0; s < 3; s++) {
        if (s < niter) issue(s, s);
        cp_commit();
    }

    const int lk = lane & 3;
    const int lg = lane >> 2;
    const int l15 = lane & 15;
    const int lhi = lane >> 4;
    const int l8k = (lane >> 3) & 1;
    const int l7  = lane & 7;

    const uint32_t aoff = (uint32_t)((wm * 32 + l15) * KPAD) * 2u + (uint32_t)lhi * 16u;
    const uint32_t boff = (uint32_t)((wn * 64 + l7 + lhi * 8) * KPAD) * 2u + (uint32_t)l8k * 16u;

    for (int c = 0; c < niter; c++) {
        cp_wait2();
        __syncthreads();
        const uint32_t soa = (uint32_t)(c & 3) * A_STAGE;
        const uint32_t sob = (uint32_t)(c & 3) * B_STAGE;

#pragma unroll
        for (int ks = 0; ks < 2; ks++) {
            const uint32_t kso = (uint32_t)ks * 32u;
            uint32_t a0[4], a1[4];
            ldm4(a0, sA + soa + aoff + kso);
            ldm4(a1, sA + soa + aoff + kso + 16u * KPAD * 2u);
#pragma unroll
            for (int p = 0; p < 4; p++) {
                uint32_t bb[4];
                ldm4(bb, sB + sob + boff + kso + (uint32_t)(p * 16 * KPAD) * 2u);
                mma_f16(acc[0][2 * p],     a0, bb[0], bb[1]);
                mma_f16(acc[0][2 * p + 1], a0, bb[2], bb[3]);
                mma_f16(acc[1][2 * p],     a1, bb[0], bb[1]);
                mma_f16(acc[1][2 * p + 1], a1, bb[2], bb[3]);
            }
        }

        if (c + 3 < niter) issue((c + 3) & 3, c + 3);
        cp_commit();
    }

    // ---------------- epilogues ----------------
    if (MODE == 0) {
#pragma unroll
        for (int ti = 0; ti < 2; ti++)
#pragma unroll
            for (int nj = 0; nj < 8; nj++) {
                int r0 = bm + wm * 32 + ti * 16 + lg;
                int cc = bn + wn * 64 + nj * 8 + 2 * lk;
                if (r0 < M) {
                    atomicAdd(&outv[(size_t)r0 * ldc + cc],     acc[ti][nj][0]);
                    atomicAdd(&outv[(size_t)r0 * ldc + cc + 1], acc[ti][nj][1]);
                }
                if (r0 + 8 < M) {
                    atomicAdd(&outv[(size_t)(r0 + 8) * ldc + cc],     acc[ti][nj][2]);
                    atomicAdd(&outv[(size_t)(r0 + 8) * ldc + cc + 1], acc[ti][nj][3]);
                }
            }
        return;
    }

    float vv[16];
#pragma unroll
    for (int nj = 0; nj < 8; nj++)
#pragma unroll
        for (int u = 0; u < 2; u++)
            vv[nj * 2 + u] = __ldg(&aux2[bn + wn * 64 + nj * 8 + 2 * lk + u]);

    if (MODE == 1) {
        const int b = bm >> 9;
        float p1v[16];
#pragma unroll
        for (int nj = 0; nj < 8; nj++)
#pragma unroll
            for (int u = 0; u < 2; u++)
                p1v[nj * 2 + u] = __ldg(&aux1[(size_t)b * H_ + bn + wn * 64 + nj * 8 + 2 * lk + u]);
#pragma unroll
        for (int ti = 0; ti < 2; ti++)
#pragma unroll
            for (int half = 0; half < 2; half++) {
                int r = bm + wm * 32 + ti * 16 + lg + half * 8;
                float part = 0.f;
#pragma unroll
                for (int nj = 0; nj < 8; nj++) {
                    part += vv[nj * 2]     * tanh_fast(acc[ti][nj][half * 2]     + p1v[nj * 2]);
                    part += vv[nj * 2 + 1] * tanh_fast(acc[ti][nj][half * 2 + 1] + p1v[nj * 2 + 1]);
                }
                part += __shfl_xor_sync(0xFFFFFFFFu, part, 1);
                part += __shfl_xor_sync(0xFFFFFFFFu, part, 2);
                if (lk == 0) atomicAdd(&outv[r], part);
            }
    } else {
#pragma unroll
        for (int ti = 0; ti < 2; ti++)
#pragma unroll
            for (int half = 0; half < 2; half++) {
                int r = bm + wm * 32 + ti * 16 + lg + half * 8;
                int b = r >> 6;
                const float* q1 = aux1 + (size_t)b * H_;
                float part = 0.f;
#pragma unroll
                for (int nj = 0; nj < 8; nj++) {
                    int n = bn + wn * 64 + nj * 8 + 2 * lk;
                    part += vv[nj * 2]     * tanh_fast(acc[ti][nj][half * 2]     + __ldg(&q1[n]));
                    part += vv[nj * 2 + 1] * tanh_fast(acc[ti][nj][half * 2 + 1] + __ldg(&q1[n + 1]));
                }
                part += __shfl_xor_sync(0xFFFFFFFFu, part, 1);
                part += __shfl_xor_sync(0xFFFFFFFFu, part, 2);
                if (lk == 0) atomicAdd(&outv[(size_t)b * OT_ + OPC_ + (r & 63)], part);
            }
    }
}

// ---------------- fused prep / epilogue helpers --------------------------------
// bias fills + zero fills + left/current -> lcH (all independent elementwise)
__global__ void fill_mega_k(
    float* gAB, const float* bA, const float* bB,
    float* gCD, const float* bC, const float* bD,
    float* P1, const float* bE, float* Q1, const float* bF,
    float* z1, int n1, float* z2, int n2, float* z3, int n3,
    const float* current, const float* left, __half* lcH)
{
    const int BH = B_ * H_;
    const int BH2 = B_ * 2 * H_;
    int i = blockIdx.x * blockDim.x + threadIdx.x;
    if (i < BH2) { int h = i % (2 * H_); gAB[i] = (h < H_) ? bA[h] : bB[h - H_]; return; }
    i -= BH2;
    if (i < BH2) { int h = i % (2 * H_); gCD[i] = (h < H_) ? bC[h] : bD[h - H_]; return; }
    i -= BH2;
    if (i < BH) { P1[i] = bE[i % H_]; return; }
    i -= BH;
    if (i < BH) { Q1[i] = bF[i % H_]; return; }
    i -= BH;
    if (i < n1) { z1[i] = 0.f; return; }
    i -= n1;
    if (i < n2) { z2[i] = 0.f; return; }
    i -= n2;
    if (i < n3) { z3[i] = 0.f; return; }
    i -= n3;
    if (i < BH) {
        int b = i / H_, h = i % H_;
        lcH[(size_t)b * 2 * H_ + h]      = __float2half_rn(left[i]);
        lcH[(size_t)b * 2 * H_ + H_ + h] = __float2half_rn(current[i]);
    }
}

__global__ void cvt_h_k(const float* __restrict__ src, __half* __restrict__ dst, int n4)
{
    int i = blockIdx.x * blockDim.x + threadIdx.x;
    if (i >= n4) return;
    float4 v = ((const float4*)src)[i];
    ((__half2*)dst)[2 * i]     = __floats2half2_rn(v.x, v.y);
    ((__half2*)dst)[2 * i + 1] = __floats2half2_rn(v.z, v.w);
}

// opc/var -> out_emb (fp32) + opcH/varH (fp16), single pass
__global__ void prep_emb_k(const float* __restrict__ opc, const float* __restrict__ var,
                           float* __restrict__ out_emb,
                           __half* __restrict__ opcH, __half* __restrict__ varH)
{
    size_t i = (size_t)blockIdx.x * blockDim.x + threadIdx.x;   // float4 units
    const size_t total = (size_t)B_ * OT_ * (H_ / 4);
    if (i >= total) return;
    int h4 = (int)(i % (H_ / 4));
    size_t bo = i / (H_ / 4);
    int o = (int)(bo & 127);
    int b = (int)(bo >> 7);
    float4 v;
    if (o < OPC_) {
        size_t si = (size_t)o * (H_ / 4) + h4;
        v = ((const float4*)opc)[si];
        if (b == 0) {
            ((__half2*)opcH)[2 * si]     = __floats2half2_rn(v.x, v.y);
            ((__half2*)opcH)[2 * si + 1] = __floats2half2_rn(v.z, v.w);
        }
    } else {
        size_t si = ((size_t)b * S2_ + (o - OPC_)) * (H_ / 4) + h4;
        v = ((const float4*)var)[si];
        ((__half2*)varH)[2 * si]     = __floats2half2_rn(v.x, v.y);
        ((__half2*)varH)[2 * si + 1] = __floats2half2_rn(v.z, v.w);
    }
    ((float4*)out_emb)[i] = v;
}

// batched 768x768 transposes -> fp16
__global__ void transpose5h_k(const float* s0, __half* d0, const float* s1, __half* d1,
                              const float* s2, __half* d2, const float* s3, __half* d3,
                              const float* s4, __half* d4)
{
    __shared__ float t[32][33];
    const float* src; __half* dst;
    switch (blockIdx.z) {
        case 0: src = s0; dst = d0; break;
        case 1: src = s1; dst = d1; break;
        case 2: src = s2; dst = d2; break;
        case 3: src = s3; dst = d3; break;
        default: src = s4; dst = d4; break;
    }
    int bx = blockIdx.x * 32, by = blockIdx.y * 32;
    int x = threadIdx.x, y = threadIdx.y;
#pragma unroll
    for (int i = 0; i < 32; i += 8)
        t[y + i][x] = src[(size_t)(by + y + i) * H_ + bx + x];
    __syncthreads();
#pragma unroll
    for (int i = 0; i < 32; i += 8)
        dst[(size_t)(bx + y + i) * H_ + by + x] = __float2half_rn(t[x][y + i]);
}

// batched [1536][768] transposes -> fp16 [768 n][1536 k]
__global__ void transpose3h_k(const float* s0, __half* d0, const float* s1, __half* d1,
                              const float* s2, __half* d2)
{
    __shared__ float t[32][33];
    const float* src; __half* dst;
    switch (blockIdx.z) {
        case 0: src = s0; dst = d0; break;
        case 1: src = s1; dst = d1; break;
        default: src = s2; dst = d2; break;
    }
    int bx = blockIdx.x * 32, by = blockIdx.y * 32;   // grid (24, 48)
    int x = threadIdx.x, y = threadIdx.y;
#pragma unroll
    for (int i = 0; i < 32; i += 8)
        t[y + i][x] = src[(size_t)(by + y + i) * H_ + bx + x];
    __syncthreads();
#pragma unroll
    for (int i = 0; i < 32; i += 8)
        dst[(size_t)(bx + y + i) * (2 * H_) + by + x] = __float2half_rn(t[x][y + i]);
}

// gates -> node (fp32 + fp16 + output copy + lower half of leafH)
__global__ void combine_node_k(const int* __restrict__ has_left,
                               float* __restrict__ out_node)
{
    int i = blockIdx.x * blockDim.x + threadIdx.x;
    if (i >= B_ * H_) return;
    int b = i / H_, h = i % H_;
    size_t base = (size_t)b * 2 * H_ + h;
    float v = has_left[b] ? ftanh(g_gCD[base]) * fsig(g_gCD[base + H_])
                          : ftanh(g_gAB[base]) * fsig(g_gAB[base + H_]);
    g_node[i] = v;
    __half hv = __float2half_rn(v);
    g_nodeH[i] = hv;
    g_leafH[base] = hv;
    out_node[i] = v;
}

// fused softmax (over S1) + context (attn @ encH); writes ctx copies and
// the upper half of leafH. block = 768 threads, grid = B_.
__global__ __launch_bounds__(768) void softmax_context_k(
    const int* __restrict__ smask, const __half* __restrict__ encH,
    float* __restrict__ out_ctx)
{
    __shared__ float attn[S1_];
    __shared__ float wred[16];
    const int b = blockIdx.x, t = threadIdx.x;
    const int lane = t & 31, w = t >> 5;

    float x = 0.f;
    if (t < S1_)
        x = smask[(size_t)b * S1_ + t] ? NEGV : g_eng[(size_t)b * S1_ + t];

    if (t < S1_) {
        float m = x;
#pragma unroll
        for (int o = 16; o; o >>= 1) m = fmaxf(m, __shfl_xor_sync(0xFFFFFFFFu, m, o));
        if (lane == 0) wred[w] = m;
    }
    __syncthreads();
    if (t == 0) {
        float m = wred[0];
#pragma unroll
        for (int k = 1; k < 16; k++) m = fmaxf(m, wred[k]);
        wred[0] = m;
    }
    __syncthreads();
    const float mx = wred[0];
    __syncthreads();

    float e = 0.f;
    if (t < S1_) {
        e = __expf(x - mx);
        float s = e;
#pragma unroll
        for (int o = 16; o; o >>= 1) s += __shfl_xor_sync(0xFFFFFFFFu, s, o);
        if (lane == 0) wred[w] = s;
    }
    __syncthreads();
    if (t == 0) {
        float s = wred[0];
#pragma unroll
        for (int k = 1; k < 16; k++) s += wred[k];
        wred[0] = s;
    }
    __syncthreads();
    if (t < S1_) attn[t] = e * __fdividef(1.f, wred[0]);
    __syncthreads();

    const __half* ep = encH + (size_t)b * S1_ * H_ + t;
    float acc = 0.f;
#pragma unroll 8
    for (int s = 0; s < S1_; s++)
        acc = fmaf(attn[s], __half2float(ep[(size_t)s * H_]), acc);
    size_t oi = (size_t)b * H_ + t;
    g_ctx[oi] = acc;
    out_ctx[oi] = acc;
    g_leafH[(size_t)b * 2 * H_ + H_ + t] = __float2half_rn(acc);
}

__global__ void finalize_score_k(const float* __restrict__ vsc,
                                 const int* __restrict__ cmask,
                                 float* __restrict__ score)
{
    int idx = (blockIdx.x * blockDim.x + threadIdx.x) >> 5;
    if (idx >= B_ * OT_) return;
    int lane = threadIdx.x & 31;
    int b = idx >> 7, o = idx & 127;
    if (cmask[idx]) {
        if (lane == 0) score[idx] = NEGV;
        return;
    }
    if (o >= OPC_) return;
    const float* q1 = g_Q1 + (size_t)b * H_;
    const float* q2 = g_Q2c + (size_t)o * H_;
    float acc = 0.f;
    for (int h = lane; h < H_; h += 32)
        acc += vsc[h] * ftanh(q1[h] + q2[h]);
#pragma unroll
    for (int off = 16; off; off >>= 1) acc += __shfl_xor_sync(0xFFFFFFFFu, acc, off);
    if (lane == 0) score[idx] = acc;
}

// ---------------- launch -------------------------------------------------------
extern "C" void kernel_launch(void* const* d_in, const int* in_sizes, int n_in,
                              void* d_out, int out_size)
{
    (void)in_sizes; (void)n_in; (void)out_size;
    const float* current = (const float*)d_in[0];
    const float* left    = (const float*)d_in[1];
    const float* enc     = (const float*)d_in[2];
    const float* var     = (const float*)d_in[3];
    const float* opc     = (const float*)d_in[4];
    const float* W_l     = (const float*)d_in[5];
    const float* b_l     = (const float*)d_in[6];
    const float* W_lg    = (const float*)d_in[7];
    const float* b_lg    = (const float*)d_in[8];
    const float* W_r     = (const float*)d_in[9];
    const float* b_r     = (const float*)d_in[10];
    const float* W_rg    = (const float*)d_in[11];
    const float* b_rg    = (const float*)d_in[12];
    const float* W_attn  = (const float*)d_in[13];
    const float* b_attn  = (const float*)d_in[14];
    const float* v_attn  = (const float*)d_in[15];
    const float* W_score = (const float*)d_in[16];
    const float* b_score = (const float*)d_in[17];
    const float* v_score = (const float*)d_in[18];
    const int*   has_left = (const int*)d_in[19];
    const int*   smask    = (const int*)d_in[20];
    const int*   cmask    = (const int*)d_in[21];

    float *gAB, *gCD, *node, *P1, *eng, *ctx, *Q1, *Q2c;
    __half *encH, *varH, *opcH, *lcH, *nodeH, *leafH;
    __half *WtLLG, *WtRRG, *WtA1, *WtA2, *WtS3, *WtS12;
    cudaGetSymbolAddress((void**)&gAB,  g_gAB);
    cudaGetSymbolAddress((void**)&gCD,  g_gCD);
    cudaGetSymbolAddress((void**)&node, g_node);
    cudaGetSymbolAddress((void**)&P1,   g_P1);
    cudaGetSymbolAddress((void**)&eng,  g_eng);
    cudaGetSymbolAddress((void**)&ctx,  g_ctx);
    cudaGetSymbolAddress((void**)&Q1,   g_Q1);
    cudaGetSymbolAddress((void**)&Q2c,  g_Q2c);
    cudaGetSymbolAddress((void**)&encH, g_encH);
    cudaGetSymbolAddress((void**)&varH, g_varH);
    cudaGetSymbolAddress((void**)&opcH, g_opcH);
    cudaGetSymbolAddress((void**)&lcH,  g_lcH);
    cudaGetSymbolAddress((void**)&nodeH, g_nodeH);
    cudaGetSymbolAddress((void**)&leafH, g_leafH);
    cudaGetSymbolAddress((void**)&WtLLG, g_WtLLG);
    cudaGetSymbolAddress((void**)&WtRRG, g_WtRRG);
    cudaGetSymbolAddress((void**)&WtA1, g_WtA1);
    cudaGetSymbolAddress((void**)&WtA2, g_WtA2);
    cudaGetSymbolAddress((void**)&WtS3, g_WtS3);
    cudaGetSymbolAddress((void**)&WtS12, g_WtS12);

    float* out       = (float*)d_out;
    float* out_score = out;
    float* out_node  = out_score + B_ * OT_;
    float* out_ctx   = out_node + B_ * H_;
    float* out_emb   = out_ctx + B_ * H_;

    const int BH = B_ * H_;
    const int TPB = 256;

    cudaFuncSetAttribute(mma_k<0>, cudaFuncAttributeMaxDynamicSharedMemorySize, SMEM_MMA);
    cudaFuncSetAttribute(mma_k<1>, cudaFuncAttributeMaxDynamicSharedMemorySize, SMEM_MMA);
    cudaFuncSetAttribute(mma_k<2>, cudaFuncAttributeMaxDynamicSharedMemorySize, SMEM_MMA);

    // ---- fork a side stream for independent DRAM-bound prep (graph-capture-safe
    // fork/join via events). Handles are intentionally not destroyed: destroying a
    // forked stream mid-capture invalidates the capture; kernel_launch is only
    // invoked a handful of times (correctness + capture), so the leak is bounded.
    cudaStream_t s1;
    cudaStreamCreateWithFlags(&s1, cudaStreamNonBlocking);
    cudaEvent_t evFork, evJoin;
    cudaEventCreateWithFlags(&evFork, cudaEventDisableTiming);
    cudaEventCreateWithFlags(&evJoin, cudaEventDisableTiming);

    cudaEventRecord(evFork, 0);
    cudaStreamWaitEvent(s1, evFork, 0);

    // ---- side chain (stream s1): enc fp16 conversion + emb outputs/conversions
    {
        int n4 = B_ * S1_ * (H_ / 4);
        cvt_h_k<<<(n4 + TPB - 1) / TPB, TPB, 0, s1>>>(enc, encH, n4);
    }
    {
        size_t total4 = (size_t)B_ * OT_ * (H_ / 4);
        prep_emb_k<<<(unsigned)((total4 + TPB - 1) / TPB), TPB, 0, s1>>>(
            opc, var, out_emb, opcH, varH);
    }
    cudaEventRecord(evJoin, s1);

    // ---- main chain (default stream): fills + lcH + transposes
    {
        int total = 2 * (B_ * 2 * H_) + 2 * BH + B_ * S1_ + B_ * OT_ + OPC_ * H_ + BH;
        fill_mega_k<<<(total + TPB - 1) / TPB, TPB>>>(
            gAB, b_l, b_lg, gCD, b_r, b_rg, P1, b_attn, Q1, b_score,
            eng, B_ * S1_, out_score, B_ * OT_, Q2c, OPC_ * H_,
            current, left, lcH);
    }
    transpose5h_k<<<dim3(24, 24, 5), dim3(32, 8)>>>(
        W_l, WtLLG, W_lg, WtLLG + (size_t)H_ * H_,
        W_attn, WtA1, W_attn + (size_t)H_ * H_, WtA2,
        W_score + (size_t)2 * H_ * H_, WtS3);
    transpose3h_k<<<dim3(24, 48, 3), dim3(32, 8)>>>(
        W_r, WtRRG, W_rg, WtRRG + (size_t)H_ * 2 * H_, W_score, WtS12);

    // --- node: two merged gate GEMMs (A = current half / full lc of lcH) ---
    mma_k<0><<<dim3(6, 2, 6),  512, SMEM_MMA>>>(lcH + H_, WtLLG, gAB, nullptr, nullptr,
                                                B_, H_, 2 * H_, 4, 2 * H_);
    mma_k<0><<<dim3(6, 2, 12), 512, SMEM_MMA>>>(lcH, WtRRG, gCD, nullptr, nullptr,
                                                B_, 2 * H_, 2 * H_, 4, 2 * H_);
    combine_node_k<<<(BH + TPB - 1) / TPB, TPB>>>(has_left, out_node);

    // --- attention: P1 GEMM, then join side chain before encH consumers ---
    mma_k<0><<<dim3(3, 2, 6), 512, SMEM_MMA>>>(nodeH, WtA1, P1, nullptr, nullptr,
                                               B_, H_, H_, 4, H_);
    cudaStreamWaitEvent(0, evJoin, 0);
    mma_k<1><<<dim3(3, (B_ * S1_) / 128, 1), 512, SMEM_MMA>>>(encH, WtA2, eng, P1, v_attn,
                                                              B_ * S1_, H_, H_, 24, 0);
    softmax_context_k<<<B_, 768>>>(smask, encH, out_ctx);

    // --- leaf score ---
    mma_k<0><<<dim3(3, 2, 12), 512, SMEM_MMA>>>(leafH, WtS12, Q1, nullptr, nullptr,
                                                B_, 2 * H_, 2 * H_, 4, H_);
    mma_k<0><<<dim3(3, 1, 6),  512, SMEM_MMA>>>(opcH, WtS3, Q2c, nullptr, nullptr,
                                                OPC_, H_, H_, 4, H_);
    mma_k<2><<<dim3(3, (B_ * S2_) / 128, 1), 512, SMEM_MMA>>>(varH, WtS3, out_score, Q1, v_score,
                                                              B_ * S2_, H_, H_, 24, 0);
    finalize_score_k<<<(B_ * OT_ * 32 + TPB - 1) / TPB, TPB>>>(v_score, cmask, out_score);
}

// round 15
// speedup vs baseline: 1.2231x; 1.0172x over previous
#include <cuda_runtime.h>
#include <cuda_fp16.h>
#include <math.h>
#include <stdint.h>

#define B_   256
#define S1_  512
#define S2_  64
#define H_   768
#define OPC_ 64
#define OT_  128
#define NEGV (-1e12f)

// ---------------- scratch (device globals) ----------------------------------
__device__ float g_gAB [B_ * 2 * H_];     // [B][1536]: gA | gB
__device__ float g_gCD [B_ * 2 * H_];     // [B][1536]: gC | gD
__device__ float g_node[B_ * H_];
__device__ float g_P1  [B_ * H_];
__device__ float g_eng [B_ * S1_];
__device__ float g_ctx [B_ * H_];
__device__ float g_Q1  [B_ * H_];
__device__ float g_Q2c [OPC_ * H_];
// fp16 activations
__device__ __half g_encH [(size_t)B_ * S1_ * H_];
__device__ __half g_varH [(size_t)B_ * S2_ * H_];
__device__ __half g_opcH [OPC_ * H_];
__device__ __half g_lcH  [B_ * 2 * H_];   // [left | current]
__device__ __half g_nodeH[B_ * H_];
__device__ __half g_leafH[B_ * 2 * H_];
// fp16 transposed weights: Wt[n][k] = W[k][n]
__device__ __half g_WtLLG [2 * H_ * H_];
__device__ __half g_WtRRG [2 * H_ * 2 * H_];
__device__ __half g_WtA1  [H_ * H_];
__device__ __half g_WtA2  [H_ * H_];
__device__ __half g_WtS3  [H_ * H_];
__device__ __half g_WtS12 [H_ * 2 * H_];

// ---------------- helpers ------------------------------------------------------
__device__ __forceinline__ float tanh_fast(float x) {
    float y; asm("tanh.approx.f32 %0, %1;" : "=f"(y) : "f"(x)); return y;
}
__device__ __forceinline__ float ftanh(float x) {
    float ax = fabsf(x);
    float e  = __expf(2.0f * ax);
    float r  = 1.0f - __fdividef(2.0f, e + 1.0f);
    return copysignf(r, x);
}
__device__ __forceinline__ float fsig(float x) {
    return __fdividef(1.0f, 1.0f + __expf(-x));
}
__device__ __forceinline__ uint32_t smem_u32(const void* p) {
    uint32_t a;
    asm("{ .reg .u64 t; cvta.to.shared.u64 t, %1; cvt.u32.u64 %0, t; }" : "=r"(a) : "l"(p));
    return a;
}
__device__ __forceinline__ void cp16(uint32_t saddr, const __half* g, uint32_t sz) {
    asm volatile("cp.async.cg.shared.global [%0], [%1], 16, %2;"
                 :: "r"(saddr), "l"(g), "r"(sz) : "memory");
}
__device__ __forceinline__ void cp_commit() {
    asm volatile("cp.async.commit_group;" ::: "memory");
}
__device__ __forceinline__ void cp_wait2() {
    asm volatile("cp.async.wait_group 2;" ::: "memory");
}
__device__ __forceinline__ void ldm4(uint32_t r[4], uint32_t addr) {
    asm volatile("ldmatrix.sync.aligned.m8n8.x4.shared.b16 {%0,%1,%2,%3}, [%4];"
                 : "=r"(r[0]), "=r"(r[1]), "=r"(r[2]), "=r"(r[3]) : "r"(addr));
}
__device__ __forceinline__ void mma_f16(float c[4], const uint32_t a[4],
                                        uint32_t b0, uint32_t b1) {
    asm volatile(
        "mma.sync.aligned.m16n8k16.row.col.f32.f16.f16.f32 "
        "{%0,%1,%2,%3}, {%4,%5,%6,%7}, {%8,%9}, {%0,%1,%2,%3};"
        : "+f"(c[0]), "+f"(c[1]), "+f"(c[2]), "+f"(c[3])
        : "r"(a[0]), "r"(a[1]), "r"(a[2]), "r"(a[3]), "r"(b0), "r"(b1));
}

// ---------------- pipelined fp16 MMA kernel (cp.async 4-stage, BK=32) ----------
// C-tile 128m x 256n, 512 thr = 16 warps (4 m-bands x 4 n-groups), warp 32x64.
// A row-major [M,lda] fp16; Wt row-major [N][K] fp16. SMEM rows padded to 40 halfs.
// MODE 0: split-K (blockIdx.z), atomicAdd into C[M,ldc] (bias preloaded).
// MODE 1: energy out[r] += sum_n v[n]*tanh(aux1[bm>>9, n] + acc)
// MODE 2: score  out[(r>>6)*128+64+(r&63)] += sum_n v[n]*tanh(aux1[r>>6, n] + acc)
#define KPAD 40
#define A_STAGE (128 * KPAD * 2)            // 10240 B
#define B_STAGE (256 * KPAD * 2)            // 20480 B
#define SMEM_MMA (4 * (A_STAGE + B_STAGE))  // 122880 B

template <int MODE>
__global__ __launch_bounds__(512, 1) void mma_k(
    const __half* __restrict__ A, const __half* __restrict__ Wt,
    float* __restrict__ outv,
    const float* __restrict__ aux1, const float* __restrict__ aux2,
    int M, int K, int lda, int niter, int ldc)
{
    extern __shared__ __align__(16) __half smh[];
    const uint32_t sA = smem_u32(smh);
    const uint32_t sB = sA + 4 * A_STAGE;

    const int tid  = threadIdx.x;
    const int lane = tid & 31;
    const int wid  = tid >> 5;
    const int wm   = wid & 3;
    const int wn   = wid >> 2;
    const int bm   = blockIdx.y * 128;
    const int bn   = blockIdx.x * 256;
    const int kst  = blockIdx.z * niter * 32;

    float acc[2][8][4];
#pragma unroll
    for (int i = 0; i < 2; i++)
#pragma unroll
        for (int j = 0; j < 8; j++)
#pragma unroll
            for (int q = 0; q < 4; q++) acc[i][j][q] = 0.f;

    // loaders: A 128 rows x 64B (1 cp16/thread); B 256 rows x 64B (2 cp16/thread)
    const int l_row = tid >> 2;
    const int lq    = tid & 3;
    const uint32_t a_sz = ((bm + l_row) < M) ? 16u : 0u;
    const __half* Ap  = A  + (size_t)(bm + l_row) * lda + kst + lq * 8;
    const __half* Bp0 = Wt + (size_t)(bn + l_row) * K + kst + lq * 8;
    const __half* Bp1 = Wt + (size_t)(bn + 128 + l_row) * K + kst + lq * 8;
    const uint32_t dA  = sA + (uint32_t)(l_row * KPAD + lq * 8) * 2u;
    const uint32_t dB0 = sB + (uint32_t)(l_row * KPAD + lq * 8) * 2u;
    const uint32_t dB1 = sB + (uint32_t)((128 + l_row) * KPAD + lq * 8) * 2u;

    auto issue = [&](int stage, int kt) {
        cp16(dA  + (uint32_t)stage * A_STAGE, Ap  + (size_t)kt * 32, a_sz);
        cp16(dB0 + (uint32_t)stage * B_STAGE, Bp0 + (size_t)kt * 32, 16u);
        cp16(dB1 + (uint32_t)stage * B_STAGE, Bp1 + (size_t)kt * 32, 16u);
    };

#pragma unroll
    for (int s = 0; s < 3; s++) {
        if (s < niter) issue(s, s);
        cp_commit();
    }

    const int lk = lane & 3;
    const int lg = lane >> 2;
    const int l15 = lane & 15;
    const int lhi = lane >> 4;
    const int l8k = (lane >> 3) & 1;
    const int l7  = lane & 7;

    const uint32_t aoff = (uint32_t)((wm * 32 + l15) * KPAD) * 2u + (uint32_t)lhi * 16u;
    const uint32_t boff = (uint32_t)((wn * 64 + l7 + lhi * 8) * KPAD) * 2u + (uint32_t)l8k * 16u;

    for (int c = 0; c < niter; c++) {
        cp_wait2();
        __syncthreads();
        const uint32_t soa = (uint32_t)(c & 3) * A_STAGE;
        const uint32_t sob = (uint32_t)(c & 3) * B_STAGE;

#pragma unroll
        for (int ks = 0; ks < 2; ks++) {
            const uint32_t kso = (uint32_t)ks * 32u;
            uint32_t a0[4], a1[4];
            ldm4(a0, sA + soa + aoff + kso);
            ldm4(a1, sA + soa + aoff + kso + 16u * KPAD * 2u);
#pragma unroll
            for (int p = 0; p < 4; p++) {
                uint32_t bb[4];
                ldm4(bb, sB + sob + boff + kso + (uint32_t)(p * 16 * KPAD) * 2u);
                mma_f16(acc[0][2 * p],     a0, bb[0], bb[1]);
                mma_f16(acc[0][2 * p + 1], a0, bb[2], bb[3]);
                mma_f16(acc[1][2 * p],     a1, bb[0], bb[1]);
                mma_f16(acc[1][2 * p + 1], a1, bb[2], bb[3]);
            }
        }

        if (c + 3 < niter) issue((c + 3) & 3, c + 3);
        cp_commit();
    }

    // ---------------- epilogues ----------------
    if (MODE == 0) {
#pragma unroll
        for (int ti = 0; ti < 2; ti++)
#pragma unroll
            for (int nj = 0; nj < 8; nj++) {
                int r0 = bm + wm * 32 + ti * 16 + lg;
                int cc = bn + wn * 64 + nj * 8 + 2 * lk;
                if (r0 < M) {
                    atomicAdd(&outv[(size_t)r0 * ldc + cc],     acc[ti][nj][0]);
                    atomicAdd(&outv[(size_t)r0 * ldc + cc + 1], acc[ti][nj][1]);
                }
                if (r0 + 8 < M) {
                    atomicAdd(&outv[(size_t)(r0 + 8) * ldc + cc],     acc[ti][nj][2]);
                    atomicAdd(&outv[(size_t)(r0 + 8) * ldc + cc + 1], acc[ti][nj][3]);
                }
            }
        return;
    }

    float vv[16];
#pragma unroll
    for (int nj = 0; nj < 8; nj++)
#pragma unroll
        for (int u = 0; u < 2; u++)
            vv[nj * 2 + u] = __ldg(&aux2[bn + wn * 64 + nj * 8 + 2 * lk + u]);

    if (MODE == 1) {
        const int b = bm >> 9;
        float p1v[16];
#pragma unroll
        for (int nj = 0; nj < 8; nj++)
#pragma unroll
            for (int u = 0; u < 2; u++)
                p1v[nj * 2 + u] = __ldg(&aux1[(size_t)b * H_ + bn + wn * 64 + nj * 8 + 2 * lk + u]);
#pragma unroll
        for (int ti = 0; ti < 2; ti++)
#pragma unroll
            for (int half = 0; half < 2; half++) {
                int r = bm + wm * 32 + ti * 16 + lg + half * 8;
                float part = 0.f;
#pragma unroll
                for (int nj = 0; nj < 8; nj++) {
                    part += vv[nj * 2]     * tanh_fast(acc[ti][nj][half * 2]     + p1v[nj * 2]);
                    part += vv[nj * 2 + 1] * tanh_fast(acc[ti][nj][half * 2 + 1] + p1v[nj * 2 + 1]);
                }
                part += __shfl_xor_sync(0xFFFFFFFFu, part, 1);
                part += __shfl_xor_sync(0xFFFFFFFFu, part, 2);
                if (lk == 0) atomicAdd(&outv[r], part);
            }
    } else {
#pragma unroll
        for (int ti = 0; ti < 2; ti++)
#pragma unroll
            for (int half = 0; half < 2; half++) {
                int r = bm + wm * 32 + ti * 16 + lg + half * 8;
                int b = r >> 6;
                const float* q1 = aux1 + (size_t)b * H_;
                float part = 0.f;
#pragma unroll
                for (int nj = 0; nj < 8; nj++) {
                    int n = bn + wn * 64 + nj * 8 + 2 * lk;
                    part += vv[nj * 2]     * tanh_fast(acc[ti][nj][half * 2]     + __ldg(&q1[n]));
                    part += vv[nj * 2 + 1] * tanh_fast(acc[ti][nj][half * 2 + 1] + __ldg(&q1[n + 1]));
                }
                part += __shfl_xor_sync(0xFFFFFFFFu, part, 1);
                part += __shfl_xor_sync(0xFFFFFFFFu, part, 2);
                if (lk == 0) atomicAdd(&outv[(size_t)b * OT_ + OPC_ + (r & 63)], part);
            }
    }
}

// ---------------- fused prep / epilogue helpers --------------------------------
// bias fills + zero fills + left/current -> lcH (all independent elementwise)
__global__ void fill_mega_k(
    float* gAB, const float* bA, const float* bB,
    float* gCD, const float* bC, const float* bD,
    float* P1, const float* bE, float* Q1, const float* bF,
    float* z1, int n1, float* z2, int n2, float* z3, int n3,
    const float* current, const float* left, __half* lcH)
{
    const int BH = B_ * H_;
    const int BH2 = B_ * 2 * H_;
    int i = blockIdx.x * blockDim.x + threadIdx.x;
    if (i < BH2) { int h = i % (2 * H_); gAB[i] = (h < H_) ? bA[h] : bB[h - H_]; return; }
    i -= BH2;
    if (i < BH2) { int h = i % (2 * H_); gCD[i] = (h < H_) ? bC[h] : bD[h - H_]; return; }
    i -= BH2;
    if (i < BH) { P1[i] = bE[i % H_]; return; }
    i -= BH;
    if (i < BH) { Q1[i] = bF[i % H_]; return; }
    i -= BH;
    if (i < n1) { z1[i] = 0.f; return; }
    i -= n1;
    if (i < n2) { z2[i] = 0.f; return; }
    i -= n2;
    if (i < n3) { z3[i] = 0.f; return; }
    i -= n3;
    if (i < BH) {
        int b = i / H_, h = i % H_;
        lcH[(size_t)b * 2 * H_ + h]      = __float2half_rn(left[i]);
        lcH[(size_t)b * 2 * H_ + H_ + h] = __float2half_rn(current[i]);
    }
}

// grid-stride fp32->fp16 conversion (capped grid => SM co-residency with MMA)
__global__ void cvt_h_k(const float* __restrict__ src, __half* __restrict__ dst, int n4)
{
    int stride = gridDim.x * blockDim.x;
    for (int i = blockIdx.x * blockDim.x + threadIdx.x; i < n4; i += stride) {
        float4 v = ((const float4*)src)[i];
        ((__half2*)dst)[2 * i]     = __floats2half2_rn(v.x, v.y);
        ((__half2*)dst)[2 * i + 1] = __floats2half2_rn(v.z, v.w);
    }
}

// opc/var -> out_emb (fp32) + opcH/varH (fp16); grid-stride (capped grid)
__global__ void prep_emb_k(const float* __restrict__ opc, const float* __restrict__ var,
                           float* __restrict__ out_emb,
                           __half* __restrict__ opcH, __half* __restrict__ varH)
{
    const size_t total = (size_t)B_ * OT_ * (H_ / 4);
    size_t stride = (size_t)gridDim.x * blockDim.x;
    for (size_t i = (size_t)blockIdx.x * blockDim.x + threadIdx.x; i < total; i += stride) {
        int h4 = (int)(i % (H_ / 4));
        size_t bo = i / (H_ / 4);
        int o = (int)(bo & 127);
        int b = (int)(bo >> 7);
        float4 v;
        if (o < OPC_) {
            size_t si = (size_t)o * (H_ / 4) + h4;
            v = ((const float4*)opc)[si];
            if (b == 0) {
                ((__half2*)opcH)[2 * si]     = __floats2half2_rn(v.x, v.y);
                ((__half2*)opcH)[2 * si + 1] = __floats2half2_rn(v.z, v.w);
            }
        } else {
            size_t si = ((size_t)b * S2_ + (o - OPC_)) * (H_ / 4) + h4;
            v = ((const float4*)var)[si];
            ((__half2*)varH)[2 * si]     = __floats2half2_rn(v.x, v.y);
            ((__half2*)varH)[2 * si + 1] = __floats2half2_rn(v.z, v.w);
        }
        ((float4*)out_emb)[i] = v;
    }
}

// batched 768x768 transposes -> fp16
__global__ void transpose5h_k(const float* s0, __half* d0, const float* s1, __half* d1,
                              const float* s2, __half* d2, const float* s3, __half* d3,
                              const float* s4, __half* d4)
{
    __shared__ float t[32][33];
    const float* src; __half* dst;
    switch (blockIdx.z) {
        case 0: src = s0; dst = d0; break;
        case 1: src = s1; dst = d1; break;
        case 2: src = s2; dst = d2; break;
        case 3: src = s3; dst = d3; break;
        default: src = s4; dst = d4; break;
    }
    int bx = blockIdx.x * 32, by = blockIdx.y * 32;
    int x = threadIdx.x, y = threadIdx.y;
#pragma unroll
    for (int i = 0; i < 32; i += 8)
        t[y + i][x] = src[(size_t)(by + y + i) * H_ + bx + x];
    __syncthreads();
#pragma unroll
    for (int i = 0; i < 32; i += 8)
        dst[(size_t)(bx + y + i) * H_ + by + x] = __float2half_rn(t[x][y + i]);
}

// batched [1536][768] transposes -> fp16 [768 n][1536 k]
__global__ void transpose3h_k(const float* s0, __half* d0, const float* s1, __half* d1,
                              const float* s2, __half* d2)
{
    __shared__ float t[32][33];
    const float* src; __half* dst;
    switch (blockIdx.z) {
        case 0: src = s0; dst = d0; break;
        case 1: src = s1; dst = d1; break;
        default: src = s2; dst = d2; break;
    }
    int bx = blockIdx.x * 32, by = blockIdx.y * 32;   // grid (24, 48)
    int x = threadIdx.x, y = threadIdx.y;
#pragma unroll
    for (int i = 0; i < 32; i += 8)
        t[y + i][x] = src[(size_t)(by + y + i) * H_ + bx + x];
    __syncthreads();
#pragma unroll
    for (int i = 0; i < 32; i += 8)
        dst[(size_t)(bx + y + i) * (2 * H_) + by + x] = __float2half_rn(t[x][y + i]);
}

// gates -> node (fp32 + fp16 + output copy + lower half of leafH)
__global__ void combine_node_k(const int* __restrict__ has_left,
                               float* __restrict__ out_node)
{
    int i = blockIdx.x * blockDim.x + threadIdx.x;
    if (i >= B_ * H_) return;
    int b = i / H_, h = i % H_;
    size_t base = (size_t)b * 2 * H_ + h;
    float v = has_left[b] ? ftanh(g_gCD[base]) * fsig(g_gCD[base + H_])
                          : ftanh(g_gAB[base]) * fsig(g_gAB[base + H_]);
    g_node[i] = v;
    __half hv = __float2half_rn(v);
    g_nodeH[i] = hv;
    g_leafH[base] = hv;
    out_node[i] = v;
}

// fused softmax (over S1) + context (attn @ encH); writes ctx copies and
// the upper half of leafH. block = 768 threads, grid = B_.
__global__ __launch_bounds__(768) void softmax_context_k(
    const int* __restrict__ smask, const __half* __restrict__ encH,
    float* __restrict__ out_ctx)
{
    __shared__ float attn[S1_];
    __shared__ float wred[16];
    const int b = blockIdx.x, t = threadIdx.x;
    const int lane = t & 31, w = t >> 5;

    float x = 0.f;
    if (t < S1_)
        x = smask[(size_t)b * S1_ + t] ? NEGV : g_eng[(size_t)b * S1_ + t];

    if (t < S1_) {
        float m = x;
#pragma unroll
        for (int o = 16; o; o >>= 1) m = fmaxf(m, __shfl_xor_sync(0xFFFFFFFFu, m, o));
        if (lane == 0) wred[w] = m;
    }
    __syncthreads();
    if (t == 0) {
        float m = wred[0];
#pragma unroll
        for (int k = 1; k < 16; k++) m = fmaxf(m, wred[k]);
        wred[0] = m;
    }
    __syncthreads();
    const float mx = wred[0];
    __syncthreads();

    float e = 0.f;
    if (t < S1_) {
        e = __expf(x - mx);
        float s = e;
#pragma unroll
        for (int o = 16; o; o >>= 1) s += __shfl_xor_sync(0xFFFFFFFFu, s, o);
        if (lane == 0) wred[w] = s;
    }
    __syncthreads();
    if (t == 0) {
        float s = wred[0];
#pragma unroll
        for (int k = 1; k < 16; k++) s += wred[k];
        wred[0] = s;
    }
    __syncthreads();
    if (t < S1_) attn[t] = e * __fdividef(1.f, wred[0]);
    __syncthreads();

    const __half* ep = encH + (size_t)b * S1_ * H_ + t;
    float acc = 0.f;
#pragma unroll 8
    for (int s = 0; s < S1_; s++)
        acc = fmaf(attn[s], __half2float(ep[(size_t)s * H_]), acc);
    size_t oi = (size_t)b * H_ + t;
    g_ctx[oi] = acc;
    out_ctx[oi] = acc;
    g_leafH[(size_t)b * 2 * H_ + H_ + t] = __float2half_rn(acc);
}

__global__ void finalize_score_k(const float* __restrict__ vsc,
                                 const int* __restrict__ cmask,
                                 float* __restrict__ score)
{
    int idx = (blockIdx.x * blockDim.x + threadIdx.x) >> 5;
    if (idx >= B_ * OT_) return;
    int lane = threadIdx.x & 31;
    int b = idx >> 7, o = idx & 127;
    if (cmask[idx]) {
        if (lane == 0) score[idx] = NEGV;
        return;
    }
    if (o >= OPC_) return;
    const float* q1 = g_Q1 + (size_t)b * H_;
    const float* q2 = g_Q2c + (size_t)o * H_;
    float acc = 0.f;
    for (int h = lane; h < H_; h += 32)
        acc += vsc[h] * ftanh(q1[h] + q2[h]);
#pragma unroll
    for (int off = 16; off; off >>= 1) acc += __shfl_xor_sync(0xFFFFFFFFu, acc, off);
    if (lane == 0) score[idx] = acc;
}

// ---------------- launch -------------------------------------------------------
extern "C" void kernel_launch(void* const* d_in, const int* in_sizes, int n_in,
                              void* d_out, int out_size)
{
    (void)in_sizes; (void)n_in; (void)out_size;
    const float* current = (const float*)d_in[0];
    const float* left    = (const float*)d_in[1];
    const float* enc     = (const float*)d_in[2];
    const float* var     = (const float*)d_in[3];
    const float* opc     = (const float*)d_in[4];
    const float* W_l     = (const float*)d_in[5];
    const float* b_l     = (const float*)d_in[6];
    const float* W_lg    = (const float*)d_in[7];
    const float* b_lg    = (const float*)d_in[8];
    const float* W_r     = (const float*)d_in[9];
    const float* b_r     = (const float*)d_in[10];
    const float* W_rg    = (const float*)d_in[11];
    const float* b_rg    = (const float*)d_in[12];
    const float* W_attn  = (const float*)d_in[13];
    const float* b_attn  = (const float*)d_in[14];
    const float* v_attn  = (const float*)d_in[15];
    const float* W_score = (const float*)d_in[16];
    const float* b_score = (const float*)d_in[17];
    const float* v_score = (const float*)d_in[18];
    const int*   has_left = (const int*)d_in[19];
    const int*   smask    = (const int*)d_in[20];
    const int*   cmask    = (const int*)d_in[21];

    float *gAB, *gCD, *node, *P1, *eng, *ctx, *Q1, *Q2c;
    __half *encH, *varH, *opcH, *lcH, *nodeH, *leafH;
    __half *WtLLG, *WtRRG, *WtA1, *WtA2, *WtS3, *WtS12;
    cudaGetSymbolAddress((void**)&gAB,  g_gAB);
    cudaGetSymbolAddress((void**)&gCD,  g_gCD);
    cudaGetSymbolAddress((void**)&node, g_node);
    cudaGetSymbolAddress((void**)&P1,   g_P1);
    cudaGetSymbolAddress((void**)&eng,  g_eng);
    cudaGetSymbolAddress((void**)&ctx,  g_ctx);
    cudaGetSymbolAddress((void**)&Q1,   g_Q1);
    cudaGetSymbolAddress((void**)&Q2c,  g_Q2c);
    cudaGetSymbolAddress((void**)&encH, g_encH);
    cudaGetSymbolAddress((void**)&varH, g_varH);
    cudaGetSymbolAddress((void**)&opcH, g_opcH);
    cudaGetSymbolAddress((void**)&lcH,  g_lcH);
    cudaGetSymbolAddress((void**)&nodeH, g_nodeH);
    cudaGetSymbolAddress((void**)&leafH, g_leafH);
    cudaGetSymbolAddress((void**)&WtLLG, g_WtLLG);
    cudaGetSymbolAddress((void**)&WtRRG, g_WtRRG);
    cudaGetSymbolAddress((void**)&WtA1, g_WtA1);
    cudaGetSymbolAddress((void**)&WtA2, g_WtA2);
    cudaGetSymbolAddress((void**)&WtS3, g_WtS3);
    cudaGetSymbolAddress((void**)&WtS12, g_WtS12);

    float* out       = (float*)d_out;
    float* out_score = out;
    float* out_node  = out_score + B_ * OT_;
    float* out_ctx   = out_node + B_ * H_;
    float* out_emb   = out_ctx + B_ * H_;

    const int BH = B_ * H_;
    const int TPB = 256;

    cudaFuncSetAttribute(mma_k<0>, cudaFuncAttributeMaxDynamicSharedMemorySize, SMEM_MMA);
    cudaFuncSetAttribute(mma_k<1>, cudaFuncAttributeMaxDynamicSharedMemorySize, SMEM_MMA);
    cudaFuncSetAttribute(mma_k<2>, cudaFuncAttributeMaxDynamicSharedMemorySize, SMEM_MMA);

    // ---- fork a side stream for independent DRAM-bound prep (graph-capture-safe
    // fork/join via events). Handles intentionally not destroyed during capture.
    cudaStream_t s1;
    cudaStreamCreateWithFlags(&s1, cudaStreamNonBlocking);
    cudaEvent_t evFork, evJoin;
    cudaEventCreateWithFlags(&evFork, cudaEventDisableTiming);
    cudaEventCreateWithFlags(&evJoin, cudaEventDisableTiming);

    cudaEventRecord(evFork, 0);
    cudaStreamWaitEvent(s1, evFork, 0);

    // ---- side chain (stream s1): capped-grid grid-stride conversions so MMA /
    // prep CTAs on the main stream can co-reside on the SMs.
    {
        int n4 = B_ * S1_ * (H_ / 4);
        cvt_h_k<<<592, TPB, 0, s1>>>(enc, encH, n4);
    }
    prep_emb_k<<<592, TPB, 0, s1>>>(opc, var, out_emb, opcH, varH);
    cudaEventRecord(evJoin, s1);

    // ---- main chain (default stream): fills + lcH + transposes
    {
        int total = 2 * (B_ * 2 * H_) + 2 * BH + B_ * S1_ + B_ * OT_ + OPC_ * H_ + BH;
        fill_mega_k<<<(total + TPB - 1) / TPB, TPB>>>(
            gAB, b_l, b_lg, gCD, b_r, b_rg, P1, b_attn, Q1, b_score,
            eng, B_ * S1_, out_score, B_ * OT_, Q2c, OPC_ * H_,
            current, left, lcH);
    }
    transpose5h_k<<<dim3(24, 24, 5), dim3(32, 8)>>>(
        W_l, WtLLG, W_lg, WtLLG + (size_t)H_ * H_,
        W_attn, WtA1, W_attn + (size_t)H_ * H_, WtA2,
        W_score + (size_t)2 * H_ * H_, WtS3);
    transpose3h_k<<<dim3(24, 48, 3), dim3(32, 8)>>>(
        W_r, WtRRG, W_rg, WtRRG + (size_t)H_ * 2 * H_, W_score, WtS12);

    // --- node: two merged gate GEMMs (A = current half / full lc of lcH) ---
    mma_k<0><<<dim3(6, 2, 6),  512, SMEM_MMA>>>(lcH + H_, WtLLG, gAB, nullptr, nullptr,
                                                B_, H_, 2 * H_, 4, 2 * H_);
    mma_k<0><<<dim3(6, 2, 12), 512, SMEM_MMA>>>(lcH, WtRRG, gCD, nullptr, nullptr,
                                                B_, 2 * H_, 2 * H_, 4, 2 * H_);
    combine_node_k<<<(BH + TPB - 1) / TPB, TPB>>>(has_left, out_node);

    // --- attention: P1 GEMM, then join side chain before encH consumers ---
    mma_k<0><<<dim3(3, 2, 6), 512, SMEM_MMA>>>(nodeH, WtA1, P1, nullptr, nullptr,
                                               B_, H_, H_, 4, H_);
    cudaStreamWaitEvent(0, evJoin, 0);
    mma_k<1><<<dim3(3, (B_ * S1_) / 128, 1), 512, SMEM_MMA>>>(encH, WtA2, eng, P1, v_attn,
                                                              B_ * S1_, H_, H_, 24, 0);
    softmax_context_k<<<B_, 768>>>(smask, encH, out_ctx);

    // --- leaf score ---
    mma_k<0><<<dim3(3, 2, 12), 512, SMEM_MMA>>>(leafH, WtS12, Q1, nullptr, nullptr,
                                                B_, 2 * H_, 2 * H_, 4, H_);
    mma_k<0><<<dim3(3, 1, 6),  512, SMEM_MMA>>>(opcH, WtS3, Q2c, nullptr, nullptr,
                                                OPC_, H_, H_, 4, H_);
    mma_k<2><<<dim3(3, (B_ * S2_) / 128, 1), 512, SMEM_MMA>>>(varH, WtS3, out_score, Q1, v_score,
                                                              B_ * S2_, H_, H_, 24, 0);
    finalize_score_k<<<(B_ * OT_ * 32 + TPB - 1) / TPB, TPB>>>(v_score, cmask, out_score);
}